// round 3
// baseline (speedup 1.0000x reference)
#include <cuda_runtime.h>
#include <math.h>

#define B_  2
#define S_  1024
#define D_  1024
#define H_  16
#define F_  4096
#define L_  6
#define V_  32000
#define DK_ 64
#define M_  (B_*S_)   // 2048 token rows

// ---------------- scratch (no allocation allowed -> __device__ globals) ----------------
__device__ __align__(16) float g_x [M_*D_];   // residual stream
__device__ __align__(16) float g_h [M_*D_];   // layernorm output
__device__ __align__(16) float g_q [M_*D_];
__device__ __align__(16) float g_k [M_*D_];
__device__ __align__(16) float g_v [M_*D_];
__device__ __align__(16) float g_ao[M_*D_];   // attention output
__device__ __align__(16) float g_ff[M_*F_];   // FFN intermediate

// ---------------- embedding + sinusoidal PE ----------------
__global__ void k_embed(const int* __restrict__ ids, const float* __restrict__ emb,
                        float* __restrict__ x)
{
    int idx = blockIdx.x * 256 + threadIdx.x;
    if (idx >= M_*D_) return;
    int d  = idx & (D_-1);
    int ms = idx >> 10;           // D_ = 1024
    int s  = ms & (S_-1);
    int tok = ids[ms];
    int i2 = d & ~1;
    float freq = expf((float)i2 * (-9.210340371976184f / (float)D_));
    float ang  = (float)s * freq;
    float pe   = (d & 1) ? cosf(ang) : sinf(ang);
    x[idx] = emb[tok*D_ + d] * 32.0f + pe;   // sqrt(1024) = 32
}

// ---------------- layernorm: one block per row ----------------
__global__ void __launch_bounds__(256) k_ln(const float* __restrict__ x,
                                            const float* __restrict__ g,
                                            const float* __restrict__ b,
                                            float* __restrict__ out)
{
    int row = blockIdx.x;
    int t = threadIdx.x;
    float4 v = ((const float4*)(x + row*D_))[t];   // D_/4 = 256 -> one float4/thread
    float s  = v.x+v.y+v.z+v.w;
    float ss = v.x*v.x+v.y*v.y+v.z*v.z+v.w*v.w;
    #pragma unroll
    for (int o=16;o>0;o>>=1){
        s  += __shfl_xor_sync(0xffffffffu, s,  o);
        ss += __shfl_xor_sync(0xffffffffu, ss, o);
    }
    __shared__ float rs[8], rss[8];
    if ((t&31)==0){ rs[t>>5]=s; rss[t>>5]=ss; }
    __syncthreads();
    float tot=0.f, tot2=0.f;
    #pragma unroll
    for (int i=0;i<8;i++){ tot += rs[i]; tot2 += rss[i]; }
    float mean = tot * (1.0f/D_);
    float var  = tot2 * (1.0f/D_) - mean*mean;
    float rstd = rsqrtf(var + 1e-5f);
    float4 gv = ((const float4*)g)[t];
    float4 bv = ((const float4*)b)[t];
    float4 o;
    o.x=(v.x-mean)*rstd*gv.x+bv.x; o.y=(v.y-mean)*rstd*gv.y+bv.y;
    o.z=(v.z-mean)*rstd*gv.z+bv.z; o.w=(v.w-mean)*rstd*gv.w+bv.w;
    ((float4*)(out + row*D_))[t] = o;
}

// ---------------- SGEMM 128x128x8, double-buffered, 8x8 per thread ----------------
// EPI: 0 = +bias, 1 = gelu(+bias), 2 = +bias+residual, 3 = plain (no bias)
// gridDim.z selects among 3 weight/bias/output sets (fused QKV); pass duplicates for z=1.
#define BM 128
#define BN 128
#define BK 8

__device__ __forceinline__ float geluf(float x){
    return 0.5f*x*(1.0f + erff(x*0.7071067811865476f));
}

template<bool TRANSB, int EPI>
__global__ void __launch_bounds__(256) k_gemm(
    int N, int K,
    const float* __restrict__ A,
    const float* __restrict__ Bm0, const float* __restrict__ Bm1, const float* __restrict__ Bm2,
    const float* __restrict__ bias0, const float* __restrict__ bias1, const float* __restrict__ bias2,
    const float* res,
    float* C0, float* C1, float* C2)
{
    int z = blockIdx.z;
    const float* Bm   = (z==0)?Bm0  :((z==1)?Bm1  :Bm2);
    const float* bias = (z==0)?bias0:((z==1)?bias1:bias2);
    float*       C    = (z==0)?C0   :((z==1)?C1   :C2);

    __shared__ float As[2][BK][BM];
    __shared__ float Bs[2][BK][BN];

    int tid = threadIdx.x;
    int bn = blockIdx.x*BN, bm = blockIdx.y*BM;

    int arow = tid>>1, acol = (tid&1)*4;
    const float* Ap = A + (bm+arow)*K + acol;

    const float* Bp;
    int brow, bcol;
    if (!TRANSB){
        brow = tid>>5; bcol = (tid&31)*4;          // brow: k, bcol: n
        Bp = Bm + brow*N + bn + bcol;
    } else {
        brow = tid>>1; bcol = (tid&1)*4;           // brow: n, bcol: k
        Bp = Bm + (size_t)(bn+brow)*K + bcol;
    }

    {   // prologue: tile 0 -> smem[0]
        float4 a0 = *(const float4*)Ap;
        As[0][acol+0][arow]=a0.x; As[0][acol+1][arow]=a0.y;
        As[0][acol+2][arow]=a0.z; As[0][acol+3][arow]=a0.w;
        float4 b0 = *(const float4*)Bp;
        if (!TRANSB){
            *(float4*)&Bs[0][brow][bcol] = b0;
        } else {
            Bs[0][bcol+0][brow]=b0.x; Bs[0][bcol+1][brow]=b0.y;
            Bs[0][bcol+2][brow]=b0.z; Bs[0][bcol+3][brow]=b0.w;
        }
    }
    __syncthreads();

    float acc[8][8];
    #pragma unroll
    for (int i=0;i<8;i++)
        #pragma unroll
        for (int j=0;j<8;j++) acc[i][j]=0.f;

    int tm = (tid>>4)*8, tn = (tid&15)*8;
    int nk = K/BK;
    int buf = 0;
    for (int kt=0; kt<nk; kt++){
        float4 aN, bN;
        if (kt+1 < nk){
            aN = *(const float4*)(Ap + (kt+1)*BK);
            if (!TRANSB) bN = *(const float4*)(Bp + (size_t)(kt+1)*BK*N);
            else         bN = *(const float4*)(Bp + (kt+1)*BK);
        }
        #pragma unroll
        for (int kk=0;kk<BK;kk++){
            float a[8], bb[8];
            *(float4*)&a[0]  = *(const float4*)&As[buf][kk][tm];
            *(float4*)&a[4]  = *(const float4*)&As[buf][kk][tm+4];
            *(float4*)&bb[0] = *(const float4*)&Bs[buf][kk][tn];
            *(float4*)&bb[4] = *(const float4*)&Bs[buf][kk][tn+4];
            #pragma unroll
            for (int i=0;i<8;i++)
                #pragma unroll
                for (int j=0;j<8;j++)
                    acc[i][j] += a[i]*bb[j];
        }
        if (kt+1 < nk){
            int nb = buf^1;
            As[nb][acol+0][arow]=aN.x; As[nb][acol+1][arow]=aN.y;
            As[nb][acol+2][arow]=aN.z; As[nb][acol+3][arow]=aN.w;
            if (!TRANSB){
                *(float4*)&Bs[nb][brow][bcol] = bN;
            } else {
                Bs[nb][bcol+0][brow]=bN.x; Bs[nb][bcol+1][brow]=bN.y;
                Bs[nb][bcol+2][brow]=bN.z; Bs[nb][bcol+3][brow]=bN.w;
            }
            __syncthreads();
            buf = nb;
        }
    }

    float bias_r[8];
    #pragma unroll
    for (int j=0;j<8;j++) bias_r[j] = (EPI==3) ? 0.f : bias[bn+tn+j];

    #pragma unroll
    for (int i=0;i<8;i++){
        int row  = bm + tm + i;
        int base = row*N + bn + tn;
        float o[8];
        #pragma unroll
        for (int j=0;j<8;j++){
            float vv = acc[i][j] + bias_r[j];
            if (EPI==1) vv = geluf(vv);
            o[j] = vv;
        }
        if (EPI==2){
            float4 r0 = *(const float4*)(res + base);
            float4 r1 = *(const float4*)(res + base + 4);
            o[0]+=r0.x; o[1]+=r0.y; o[2]+=r0.z; o[3]+=r0.w;
            o[4]+=r1.x; o[5]+=r1.y; o[6]+=r1.z; o[7]+=r1.w;
        }
        *(float4*)(C+base)   = make_float4(o[0],o[1],o[2],o[3]);
        *(float4*)(C+base+4) = make_float4(o[4],o[5],o[6],o[7]);
    }
}

// ---------------- flash attention: grid (S/64, B*H), 256 threads ----------------
// thread = (row r = tid>>2, quarter qc = tid&3). Scores: 8 keys/thread.
// AV: 16 output dims/thread at dims {qc + 4j} (conflict-free Vs reads).
__global__ void __launch_bounds__(256) k_attn(const float* __restrict__ Q,
                                              const float* __restrict__ K,
                                              const float* __restrict__ V,
                                              float* __restrict__ O)
{
    __shared__ float Qs[64][65];
    __shared__ float Ks[32][65];
    __shared__ float Vs[32][65];
    __shared__ float Ps[64][33];

    int tid = threadIdx.x;
    int qt = blockIdx.x;
    int bh = blockIdx.y;
    int bb = bh >> 4;
    int hh = bh & 15;
    int r  = tid >> 2;
    int qc = tid & 3;

    {   // load Q tile (64x64)
        const float* qp = Q + ((bb*S_ + qt*64 + r)*D_) + hh*DK_ + qc*16;
        #pragma unroll
        for (int u=0; u<4; u++){
            float4 t = *(const float4*)(qp + 4*u);
            int c = qc*16 + 4*u;
            Qs[r][c]=t.x; Qs[r][c+1]=t.y; Qs[r][c+2]=t.z; Qs[r][c+3]=t.w;
        }
    }

    float m = -1e30f, l = 0.f;
    float acc[16];
    #pragma unroll
    for (int j=0;j<16;j++) acc[j]=0.f;

    int krow = tid >> 3, cg = tid & 7;
    int qg = qt*64 + r;
    int nkt = 2*qt + 2;

    for (int kt=0; kt<nkt; kt++){
        __syncthreads();                 // guard previous AV reads vs K/V overwrite
        {
            int srow = (bb*S_ + kt*32 + krow)*D_ + hh*DK_ + cg*8;
            #pragma unroll
            for (int u=0;u<2;u++){
                float4 t  = *(const float4*)(K + srow + 4*u);
                float4 tv = *(const float4*)(V + srow + 4*u);
                int c = cg*8 + 4*u;
                Ks[krow][c]=t.x;  Ks[krow][c+1]=t.y;  Ks[krow][c+2]=t.z;  Ks[krow][c+3]=t.w;
                Vs[krow][c]=tv.x; Vs[krow][c+1]=tv.y; Vs[krow][c+2]=tv.z; Vs[krow][c+3]=tv.w;
            }
        }
        __syncthreads();

        float sc[8];
        #pragma unroll
        for (int j=0;j<8;j++) sc[j]=0.f;
        #pragma unroll 16
        for (int d=0; d<DK_; d++){
            float qv = Qs[r][d];
            #pragma unroll
            for (int j=0;j<8;j++) sc[j] += qv * Ks[qc*8+j][d];
        }
        float tmax = -1e30f;
        #pragma unroll
        for (int j=0;j<8;j++){
            int kg = kt*32 + qc*8 + j;
            sc[j] = (kg <= qg) ? sc[j]*0.125f : -1e30f;   // scale = 1/sqrt(64)
            tmax = fmaxf(tmax, sc[j]);
        }
        tmax = fmaxf(tmax, __shfl_xor_sync(0xffffffffu, tmax, 1));
        tmax = fmaxf(tmax, __shfl_xor_sync(0xffffffffu, tmax, 2));
        float mnew = fmaxf(m, tmax);
        float corr = __expf(m - mnew);
        float psum = 0.f;
        #pragma unroll
        for (int j=0;j<8;j++){
            float p = __expf(sc[j] - mnew);
            Ps[r][qc*8+j] = p;
            psum += p;
        }
        psum += __shfl_xor_sync(0xffffffffu, psum, 1);
        psum += __shfl_xor_sync(0xffffffffu, psum, 2);
        l = l*corr + psum;
        m = mnew;
        #pragma unroll
        for (int j=0;j<16;j++) acc[j] *= corr;
        __syncthreads();                 // Ps complete before AV
        #pragma unroll 8
        for (int k=0;k<32;k++){
            float p = Ps[r][k];
            #pragma unroll
            for (int j=0;j<16;j++) acc[j] += p * Vs[k][qc + 4*j];
        }
    }
    float inv = 1.0f/l;
    float* op = O + ((bb*S_ + qg)*D_) + hh*DK_;
    #pragma unroll
    for (int j=0;j<16;j++) op[qc + 4*j] = acc[j]*inv;
}

// ---------------- orchestration ----------------
extern "C" void kernel_launch(void* const* d_in, const int* in_sizes, int n_in,
                              void* d_out, int out_size)
{
    (void)in_sizes; (void)n_in; (void)out_size;
    const int*   ids  = (const int*)  d_in[0];
    const float* emb  = (const float*)d_in[1];
    const float* wq   = (const float*)d_in[2];
    const float* bq   = (const float*)d_in[3];
    const float* wk   = (const float*)d_in[4];
    const float* bk   = (const float*)d_in[5];
    const float* wv   = (const float*)d_in[6];
    const float* bv   = (const float*)d_in[7];
    const float* wo   = (const float*)d_in[8];
    const float* bo   = (const float*)d_in[9];
    const float* ln1g = (const float*)d_in[10];
    const float* ln1b = (const float*)d_in[11];
    const float* ln2g = (const float*)d_in[12];
    const float* ln2b = (const float*)d_in[13];
    const float* w1   = (const float*)d_in[14];
    const float* b1   = (const float*)d_in[15];
    const float* w2   = (const float*)d_in[16];
    const float* b2   = (const float*)d_in[17];
    const float* lnfg = (const float*)d_in[18];
    const float* lnfb = (const float*)d_in[19];
    float* out = (float*)d_out;

    float *px,*ph,*pq,*pk,*pv,*pa,*pf;
    cudaGetSymbolAddress((void**)&px, g_x);
    cudaGetSymbolAddress((void**)&ph, g_h);
    cudaGetSymbolAddress((void**)&pq, g_q);
    cudaGetSymbolAddress((void**)&pk, g_k);
    cudaGetSymbolAddress((void**)&pv, g_v);
    cudaGetSymbolAddress((void**)&pa, g_ao);
    cudaGetSymbolAddress((void**)&pf, g_ff);

    k_embed<<<(M_*D_+255)/256, 256>>>(ids, emb, px);

    for (int l=0; l<L_; l++){
        size_t odd = (size_t)l*D_*D_;
        k_ln<<<M_,256>>>(px, ln1g+l*D_, ln1b+l*D_, ph);
        // fused QKV via grid.z = 3
        k_gemm<false,0><<<dim3(D_/BN, M_/BM, 3),256>>>(D_, D_, ph,
            wq+odd, wk+odd, wv+odd,
            bq+l*D_, bk+l*D_, bv+l*D_,
            nullptr, pq, pk, pv);
        k_attn<<<dim3(S_/64, B_*H_),256>>>(pq, pk, pv, pa);
        // x = x + attn @ Wo + bo  (in-place residual: each element read once then written)
        k_gemm<false,2><<<dim3(D_/BN, M_/BM, 1),256>>>(D_, D_, pa,
            wo+odd, wo+odd, wo+odd,
            bo+l*D_, bo+l*D_, bo+l*D_,
            px, px, px, px);
        k_ln<<<M_,256>>>(px, ln2g+l*D_, ln2b+l*D_, ph);
        k_gemm<false,1><<<dim3(F_/BN, M_/BM, 1),256>>>(F_, D_, ph,
            w1+(size_t)l*D_*F_, w1+(size_t)l*D_*F_, w1+(size_t)l*D_*F_,
            b1+l*F_, b1+l*F_, b1+l*F_,
            nullptr, pf, pf, pf);
        k_gemm<false,2><<<dim3(D_/BN, M_/BM, 1),256>>>(D_, F_, pf,
            w2+(size_t)l*F_*D_, w2+(size_t)l*F_*D_, w2+(size_t)l*F_*D_,
            b2+l*D_, b2+l*D_, b2+l*D_,
            px, px, px, px);
    }
    k_ln<<<M_,256>>>(px, lnfg, lnfb, ph);
    // logits = h @ emb^T  (B stored [V, D] -> TRANSB, no bias)
    k_gemm<true,3><<<dim3(V_/BN, M_/BM, 1),256>>>(V_, D_, ph,
        emb, emb, emb,
        nullptr, nullptr, nullptr,
        nullptr, out, out, out);
}

// round 5
// speedup vs baseline: 1.6951x; 1.6951x over previous
#include <cuda_runtime.h>
#include <cuda_bf16.h>
#include <cstdint>
#include <math.h>

typedef unsigned int u32;

#define B_  2
#define S_  1024
#define D_  1024
#define H_  16
#define F_  4096
#define L_  6
#define V_  32000
#define DK_ 64
#define M_  (B_*S_)   // 2048 token rows

#define BM 128
#define BN 128
#define BKK 32        // k-tile (elements)

// ---------------- scratch ----------------
__device__ __align__(16) float g_x [M_*D_];
__device__ __align__(16) float g_h [M_*D_];
__device__ __align__(16) float g_q [M_*D_];
__device__ __align__(16) float g_k [M_*D_];
__device__ __align__(16) float g_v [M_*D_];
__device__ __align__(16) float g_ao[M_*D_];
__device__ __align__(16) float g_ff[M_*F_];

// ---------------- embedding + sinusoidal PE ----------------
__global__ void k_embed(const int* __restrict__ ids, const float* __restrict__ emb,
                        float* __restrict__ x)
{
    int idx = blockIdx.x * 256 + threadIdx.x;
    if (idx >= M_*D_) return;
    int d  = idx & (D_-1);
    int ms = idx >> 10;
    int s  = ms & (S_-1);
    int tok = ids[ms];
    int i2 = d & ~1;
    float freq = expf((float)i2 * (-9.210340371976184f / (float)D_));
    float ang  = (float)s * freq;
    float pe   = (d & 1) ? cosf(ang) : sinf(ang);
    x[idx] = emb[tok*D_ + d] * 32.0f + pe;
}

// ---------------- layernorm ----------------
__global__ void __launch_bounds__(256) k_ln(const float* __restrict__ x,
                                            const float* __restrict__ g,
                                            const float* __restrict__ b,
                                            float* __restrict__ out)
{
    int row = blockIdx.x;
    int t = threadIdx.x;
    float4 v = ((const float4*)(x + row*D_))[t];
    float s  = v.x+v.y+v.z+v.w;
    float ss = v.x*v.x+v.y*v.y+v.z*v.z+v.w*v.w;
    #pragma unroll
    for (int o=16;o>0;o>>=1){
        s  += __shfl_xor_sync(0xffffffffu, s,  o);
        ss += __shfl_xor_sync(0xffffffffu, ss, o);
    }
    __shared__ float rs[8], rss[8];
    if ((t&31)==0){ rs[t>>5]=s; rss[t>>5]=ss; }
    __syncthreads();
    float tot=0.f, tot2=0.f;
    #pragma unroll
    for (int i=0;i<8;i++){ tot += rs[i]; tot2 += rss[i]; }
    float mean = tot * (1.0f/D_);
    float var  = tot2 * (1.0f/D_) - mean*mean;
    float rstd = rsqrtf(var + 1e-5f);
    float4 gv = ((const float4*)g)[t];
    float4 bv = ((const float4*)b)[t];
    float4 o;
    o.x=(v.x-mean)*rstd*gv.x+bv.x; o.y=(v.y-mean)*rstd*gv.y+bv.y;
    o.z=(v.z-mean)*rstd*gv.z+bv.z; o.w=(v.w-mean)*rstd*gv.w+bv.w;
    ((float4*)(out + row*D_))[t] = o;
}

// ---------------- mma helpers ----------------
__device__ __forceinline__ u32 cvt_smem(const void* p){
    return (u32)__cvta_generic_to_shared(p);
}
__device__ __forceinline__ void ldsm4(u32 &r0,u32 &r1,u32 &r2,u32 &r3, u32 a){
    asm volatile("ldmatrix.sync.aligned.m8n8.x4.shared.b16 {%0,%1,%2,%3},[%4];\n"
        : "=r"(r0),"=r"(r1),"=r"(r2),"=r"(r3) : "r"(a));
}
__device__ __forceinline__ void ldsm4t(u32 &r0,u32 &r1,u32 &r2,u32 &r3, u32 a){
    asm volatile("ldmatrix.sync.aligned.m8n8.x4.trans.shared.b16 {%0,%1,%2,%3},[%4];\n"
        : "=r"(r0),"=r"(r1),"=r"(r2),"=r"(r3) : "r"(a));
}
__device__ __forceinline__ void mma16816(float* c, const u32* a, const u32* b){
    asm volatile("mma.sync.aligned.m16n8k16.row.col.f32.bf16.bf16.f32 "
        "{%0,%1,%2,%3},{%4,%5,%6,%7},{%8,%9},{%0,%1,%2,%3};\n"
        : "+f"(c[0]),"+f"(c[1]),"+f"(c[2]),"+f"(c[3])
        : "r"(a[0]),"r"(a[1]),"r"(a[2]),"r"(a[3]),"r"(b[0]),"r"(b[1]));
}
__device__ __forceinline__ u32 pack2(__nv_bfloat16 h0, __nv_bfloat16 h1){
    unsigned short u0 = *reinterpret_cast<unsigned short*>(&h0);
    unsigned short u1 = *reinterpret_cast<unsigned short*>(&h1);
    return (u32)u0 | ((u32)u1 << 16);
}
__device__ __forceinline__ void split2(float x0, float x1, u32 &hi, u32 &lo){
    __nv_bfloat16 h0 = __float2bfloat16_rn(x0);
    __nv_bfloat16 h1 = __float2bfloat16_rn(x1);
    float f0 = __bfloat162float(h0), f1 = __bfloat162float(h1);
    hi = pack2(h0, h1);
    lo = pack2(__float2bfloat16_rn(x0 - f0), __float2bfloat16_rn(x1 - f1));
}

__device__ __forceinline__ float geluf(float x){
    return 0.5f*x*(1.0f + erff(x*0.7071067811865476f));
}

// ---------------- bf16x3-split tensor-core GEMM ----------------
// C[M,N] = A[M,K] @ B  (B is [K,N] if !TRANSB, else [N,K])
// EPI: 0 = +bias, 1 = gelu(+bias), 2 = +bias+residual, 3 = plain
template<bool TRANSB, int EPI>
__global__ void __launch_bounds__(256) k_gemm(
    int N, int K,
    const float* __restrict__ A,
    const float* __restrict__ Bm0, const float* __restrict__ Bm1, const float* __restrict__ Bm2,
    const float* __restrict__ bias0, const float* __restrict__ bias1, const float* __restrict__ bias2,
    const float* res,
    float* C0, float* C1, float* C2)
{
    constexpr int AKP = BKK + 8;                   // 40: A smem row stride (elems)
    constexpr int BRR = TRANSB ? BN : BKK;         // B smem rows
    constexpr int BCC = TRANSB ? (BKK+8) : (BN+8); // B smem cols (40 or 136)

    int z = blockIdx.z;
    const float* Bm   = (z==0)?Bm0  :((z==1)?Bm1  :Bm2);
    const float* bias = (z==0)?bias0:((z==1)?bias1:bias2);
    float*       C    = (z==0)?C0   :((z==1)?C1   :C2);

    __shared__ __align__(16) __nv_bfloat16 As_h[BM][AKP];
    __shared__ __align__(16) __nv_bfloat16 As_l[BM][AKP];
    __shared__ __align__(16) __nv_bfloat16 Bs_h[BRR][BCC];
    __shared__ __align__(16) __nv_bfloat16 Bs_l[BRR][BCC];

    const int tid  = threadIdx.x;
    const int lane = tid & 31;
    const int wid  = tid >> 5;
    const int warp_m = wid & 1;       // 0..1
    const int warp_n = wid >> 1;      // 0..3
    const int m_base = warp_m * 64;
    const int n_base = warp_n * 32;
    const int bm = blockIdx.y * BM;
    const int bn = blockIdx.x * BN;

    // ldmatrix base addresses
    const u32 a_base_h = cvt_smem(&As_h[m_base + (lane & 15)][(lane >> 4) * 8]);
    const u32 a_base_l = cvt_smem(&As_l[m_base + (lane & 15)][(lane >> 4) * 8]);
    const int q = lane >> 3;
    u32 b_base_h, b_base_l;
    if (!TRANSB){
        b_base_h = cvt_smem(&Bs_h[(q & 1) * 8 + (lane & 7)][n_base + (q >> 1) * 8]);
        b_base_l = cvt_smem(&Bs_l[(q & 1) * 8 + (lane & 7)][n_base + (q >> 1) * 8]);
    } else {
        b_base_h = cvt_smem(&Bs_h[n_base + (q & 1) * 8 + (lane & 7)][(q >> 1) * 8]);
        b_base_l = cvt_smem(&Bs_l[n_base + (q & 1) * 8 + (lane & 7)][(q >> 1) * 8]);
    }

    float acc[4][4][4];
    #pragma unroll
    for (int i=0;i<4;i++)
        #pragma unroll
        for (int j=0;j<4;j++)
            #pragma unroll
            for (int r=0;r<4;r++) acc[i][j][r]=0.f;

    float4 areg[4], breg[4];

    auto load_tiles = [&](int kt){
        #pragma unroll
        for (int i=0;i<4;i++){
            int idx = tid + i*256;
            areg[i] = *(const float4*)(A + (size_t)(bm + (idx>>3))*K + kt*BKK + (idx&7)*4);
        }
        if (!TRANSB){
            #pragma unroll
            for (int i=0;i<4;i++){
                int idx = tid + i*256;
                breg[i] = *(const float4*)(Bm + (size_t)(kt*BKK + (idx>>5))*N + bn + (idx&31)*4);
            }
        } else {
            #pragma unroll
            for (int i=0;i<4;i++){
                int idx = tid + i*256;
                breg[i] = *(const float4*)(Bm + (size_t)(bn + (idx>>3))*K + kt*BKK + (idx&7)*4);
            }
        }
    };

    auto store_tiles = [&](){
        #pragma unroll
        for (int i=0;i<4;i++){
            int idx = tid + i*256;
            int row = idx>>3, c = (idx&7)*4;
            u32 h0,l0,h1,l1;
            split2(areg[i].x, areg[i].y, h0, l0);
            split2(areg[i].z, areg[i].w, h1, l1);
            *reinterpret_cast<uint2*>(&As_h[row][c]) = make_uint2(h0,h1);
            *reinterpret_cast<uint2*>(&As_l[row][c]) = make_uint2(l0,l1);
        }
        #pragma unroll
        for (int i=0;i<4;i++){
            int idx = tid + i*256;
            int row, c;
            if (!TRANSB){ row = idx>>5; c = (idx&31)*4; }
            else        { row = idx>>3; c = (idx&7)*4; }
            u32 h0,l0,h1,l1;
            split2(breg[i].x, breg[i].y, h0, l0);
            split2(breg[i].z, breg[i].w, h1, l1);
            *reinterpret_cast<uint2*>(&Bs_h[row][c]) = make_uint2(h0,h1);
            *reinterpret_cast<uint2*>(&Bs_l[row][c]) = make_uint2(l0,l1);
        }
    };

    auto compute = [&](){
        #pragma unroll
        for (int ks=0; ks<2; ks++){
            u32 ah[4][4], al[4][4], bh[4][2], bl[4][2];
            #pragma unroll
            for (int mi=0;mi<4;mi++){
                u32 off = (u32)(mi*(16*AKP*2) + ks*32);
                ldsm4(ah[mi][0],ah[mi][1],ah[mi][2],ah[mi][3], a_base_h + off);
                ldsm4(al[mi][0],al[mi][1],al[mi][2],al[mi][3], a_base_l + off);
            }
            if (!TRANSB){
                #pragma unroll
                for (int p=0;p<2;p++){
                    u32 off = (u32)(ks*(16*BCC*2) + p*32);
                    u32 r0,r1,r2,r3;
                    ldsm4t(r0,r1,r2,r3, b_base_h + off);
                    bh[2*p][0]=r0; bh[2*p][1]=r1; bh[2*p+1][0]=r2; bh[2*p+1][1]=r3;
                    ldsm4t(r0,r1,r2,r3, b_base_l + off);
                    bl[2*p][0]=r0; bl[2*p][1]=r1; bl[2*p+1][0]=r2; bl[2*p+1][1]=r3;
                }
            } else {
                #pragma unroll
                for (int p=0;p<2;p++){
                    u32 off = (u32)(p*(16*BCC*2) + ks*32);
                    u32 r0,r1,r2,r3;
                    ldsm4(r0,r1,r2,r3, b_base_h + off);
                    bh[2*p][0]=r0; bh[2*p][1]=r2; bh[2*p+1][0]=r1; bh[2*p+1][1]=r3;
                    ldsm4(r0,r1,r2,r3, b_base_l + off);
                    bl[2*p][0]=r0; bl[2*p][1]=r2; bl[2*p+1][0]=r1; bl[2*p+1][1]=r3;
                }
            }
            #pragma unroll
            for (int mi=0;mi<4;mi++)
                #pragma unroll
                for (int nj=0;nj<4;nj++){
                    mma16816(acc[mi][nj], ah[mi], bh[nj]);
                    mma16816(acc[mi][nj], ah[mi], bl[nj]);
                    mma16816(acc[mi][nj], al[mi], bh[nj]);
                }
        }
    };

    const int nk = K / BKK;
    load_tiles(0);
    store_tiles();
    __syncthreads();
    for (int kt=0; kt<nk; kt++){
        if (kt+1 < nk) load_tiles(kt+1);
        compute();
        if (kt+1 < nk){
            __syncthreads();
            store_tiles();
            __syncthreads();
        }
    }

    // ---- epilogue ----
    #pragma unroll
    for (int mi=0; mi<4; mi++){
        #pragma unroll
        for (int r=0; r<2; r++){
            int gm = bm + m_base + mi*16 + (lane>>2) + r*8;
            #pragma unroll
            for (int nj=0; nj<4; nj++){
                int gn = bn + n_base + nj*8 + (lane&3)*2;
                float v0 = acc[mi][nj][r*2+0];
                float v1 = acc[mi][nj][r*2+1];
                if (EPI != 3){ v0 += bias[gn]; v1 += bias[gn+1]; }
                if (EPI == 1){ v0 = geluf(v0); v1 = geluf(v1); }
                size_t base = (size_t)gm*N + gn;
                if (EPI == 2){
                    float2 rr = *(const float2*)(res + base);
                    v0 += rr.x; v1 += rr.y;
                }
                *(float2*)(C + base) = make_float2(v0, v1);
            }
        }
    }
}

// ---------------- flash attention ----------------
__global__ void __launch_bounds__(256) k_attn(const float* __restrict__ Q,
                                              const float* __restrict__ K,
                                              const float* __restrict__ V,
                                              float* __restrict__ O)
{
    __shared__ float Qs[64][65];
    __shared__ float Ks[32][65];
    __shared__ float Vs[32][65];
    __shared__ float Ps[64][33];

    int tid = threadIdx.x;
    int qt = blockIdx.x;
    int bh = blockIdx.y;
    int bb = bh >> 4;
    int hh = bh & 15;
    int r  = tid >> 2;
    int qc = tid & 3;

    {
        const float* qp = Q + ((bb*S_ + qt*64 + r)*D_) + hh*DK_ + qc*16;
        #pragma unroll
        for (int u=0; u<4; u++){
            float4 t = *(const float4*)(qp + 4*u);
            int c = qc*16 + 4*u;
            Qs[r][c]=t.x; Qs[r][c+1]=t.y; Qs[r][c+2]=t.z; Qs[r][c+3]=t.w;
        }
    }

    float m = -1e30f, l = 0.f;
    float acc[16];
    #pragma unroll
    for (int j=0;j<16;j++) acc[j]=0.f;

    int krow = tid >> 3, cg = tid & 7;
    int qg = qt*64 + r;
    int nkt = 2*qt + 2;

    for (int kt=0; kt<nkt; kt++){
        __syncthreads();
        {
            int srow = (bb*S_ + kt*32 + krow)*D_ + hh*DK_ + cg*8;
            #pragma unroll
            for (int u=0;u<2;u++){
                float4 t  = *(const float4*)(K + srow + 4*u);
                float4 tv = *(const float4*)(V + srow + 4*u);
                int c = cg*8 + 4*u;
                Ks[krow][c]=t.x;  Ks[krow][c+1]=t.y;  Ks[krow][c+2]=t.z;  Ks[krow][c+3]=t.w;
                Vs[krow][c]=tv.x; Vs[krow][c+1]=tv.y; Vs[krow][c+2]=tv.z; Vs[krow][c+3]=tv.w;
            }
        }
        __syncthreads();

        float sc[8];
        #pragma unroll
        for (int j=0;j<8;j++) sc[j]=0.f;
        #pragma unroll 16
        for (int d=0; d<DK_; d++){
            float qv = Qs[r][d];
            #pragma unroll
            for (int j=0;j<8;j++) sc[j] += qv * Ks[qc*8+j][d];
        }
        float tmax = -1e30f;
        #pragma unroll
        for (int j=0;j<8;j++){
            int kg = kt*32 + qc*8 + j;
            sc[j] = (kg <= qg) ? sc[j]*0.125f : -1e30f;
            tmax = fmaxf(tmax, sc[j]);
        }
        tmax = fmaxf(tmax, __shfl_xor_sync(0xffffffffu, tmax, 1));
        tmax = fmaxf(tmax, __shfl_xor_sync(0xffffffffu, tmax, 2));
        float mnew = fmaxf(m, tmax);
        float corr = __expf(m - mnew);
        float psum = 0.f;
        #pragma unroll
        for (int j=0;j<8;j++){
            float p = __expf(sc[j] - mnew);
            Ps[r][qc*8+j] = p;
            psum += p;
        }
        psum += __shfl_xor_sync(0xffffffffu, psum, 1);
        psum += __shfl_xor_sync(0xffffffffu, psum, 2);
        l = l*corr + psum;
        m = mnew;
        #pragma unroll
        for (int j=0;j<16;j++) acc[j] *= corr;
        __syncthreads();
        #pragma unroll 8
        for (int k=0;k<32;k++){
            float p = Ps[r][k];
            #pragma unroll
            for (int j=0;j<16;j++) acc[j] += p * Vs[k][qc + 4*j];
        }
    }
    float inv = 1.0f/l;
    float* op = O + ((bb*S_ + qg)*D_) + hh*DK_;
    #pragma unroll
    for (int j=0;j<16;j++) op[qc + 4*j] = acc[j]*inv;
}

// ---------------- orchestration ----------------
extern "C" void kernel_launch(void* const* d_in, const int* in_sizes, int n_in,
                              void* d_out, int out_size)
{
    (void)in_sizes; (void)n_in; (void)out_size;
    const int*   ids  = (const int*)  d_in[0];
    const float* emb  = (const float*)d_in[1];
    const float* wq   = (const float*)d_in[2];
    const float* bq   = (const float*)d_in[3];
    const float* wk   = (const float*)d_in[4];
    const float* bk   = (const float*)d_in[5];
    const float* wv   = (const float*)d_in[6];
    const float* bv   = (const float*)d_in[7];
    const float* wo   = (const float*)d_in[8];
    const float* bo   = (const float*)d_in[9];
    const float* ln1g = (const float*)d_in[10];
    const float* ln1b = (const float*)d_in[11];
    const float* ln2g = (const float*)d_in[12];
    const float* ln2b = (const float*)d_in[13];
    const float* w1   = (const float*)d_in[14];
    const float* b1   = (const float*)d_in[15];
    const float* w2   = (const float*)d_in[16];
    const float* b2   = (const float*)d_in[17];
    const float* lnfg = (const float*)d_in[18];
    const float* lnfb = (const float*)d_in[19];
    float* out = (float*)d_out;

    float *px,*ph,*pq,*pk,*pv,*pa,*pf;
    cudaGetSymbolAddress((void**)&px, g_x);
    cudaGetSymbolAddress((void**)&ph, g_h);
    cudaGetSymbolAddress((void**)&pq, g_q);
    cudaGetSymbolAddress((void**)&pk, g_k);
    cudaGetSymbolAddress((void**)&pv, g_v);
    cudaGetSymbolAddress((void**)&pa, g_ao);
    cudaGetSymbolAddress((void**)&pf, g_ff);

    k_embed<<<(M_*D_+255)/256, 256>>>(ids, emb, px);

    for (int l=0; l<L_; l++){
        size_t odd = (size_t)l*D_*D_;
        k_ln<<<M_,256>>>(px, ln1g+l*D_, ln1b+l*D_, ph);
        k_gemm<false,0><<<dim3(D_/BN, M_/BM, 3),256>>>(D_, D_, ph,
            wq+odd, wk+odd, wv+odd,
            bq+l*D_, bk+l*D_, bv+l*D_,
            nullptr, pq, pk, pv);
        k_attn<<<dim3(S_/64, B_*H_),256>>>(pq, pk, pv, pa);
        k_gemm<false,2><<<dim3(D_/BN, M_/BM, 1),256>>>(D_, D_, pa,
            wo+odd, wo+odd, wo+odd,
            bo+l*D_, bo+l*D_, bo+l*D_,
            px, px, px, px);
        k_ln<<<M_,256>>>(px, ln2g+l*D_, ln2b+l*D_, ph);
        k_gemm<false,1><<<dim3(F_/BN, M_/BM, 1),256>>>(F_, D_, ph,
            w1+(size_t)l*D_*F_, w1+(size_t)l*D_*F_, w1+(size_t)l*D_*F_,
            b1+l*F_, b1+l*F_, b1+l*F_,
            nullptr, pf, pf, pf);
        k_gemm<false,2><<<dim3(D_/BN, M_/BM, 1),256>>>(D_, F_, pf,
            w2+(size_t)l*F_*D_, w2+(size_t)l*F_*D_, w2+(size_t)l*F_*D_,
            b2+l*D_, b2+l*D_, b2+l*D_,
            px, px, px, px);
    }
    k_ln<<<M_,256>>>(px, lnfg, lnfb, ph);
    k_gemm<true,3><<<dim3(V_/BN, M_/BM, 1),256>>>(V_, D_, ph,
        emb, emb, emb,
        nullptr, nullptr, nullptr,
        nullptr, out, out, out);
}

// round 6
// speedup vs baseline: 3.9996x; 2.3595x over previous
#include <cuda_runtime.h>
#include <cuda_bf16.h>
#include <cstdint>
#include <math.h>

typedef unsigned int u32;
typedef __nv_bfloat16 bf16;

#define B_  2
#define S_  1024
#define D_  1024
#define H_  16
#define F_  4096
#define L_  6
#define V_  32000
#define DK_ 64
#define M_  (B_*S_)

#define BM 128
#define BN 128

// ---------------- persistent scratch ----------------
// residual stream (fp32) + all bf16 hi/lo operands
__device__ __align__(16) float g_x [M_*D_];
__device__ __align__(16) bf16 g_h_h[M_*D_],  g_h_l[M_*D_];
__device__ __align__(16) bf16 g_q_h[M_*D_],  g_q_l[M_*D_];
__device__ __align__(16) bf16 g_k_h[M_*D_],  g_k_l[M_*D_];
__device__ __align__(16) bf16 g_v_h[M_*D_],  g_v_l[M_*D_];
__device__ __align__(16) bf16 g_a_h[M_*D_],  g_a_l[M_*D_];
__device__ __align__(16) bf16 g_f_h[M_*F_],  g_f_l[M_*F_];
// pre-split weights
__device__ __align__(16) bf16 g_wq_h[L_*D_*D_], g_wq_l[L_*D_*D_];
__device__ __align__(16) bf16 g_wk_h[L_*D_*D_], g_wk_l[L_*D_*D_];
__device__ __align__(16) bf16 g_wv_h[L_*D_*D_], g_wv_l[L_*D_*D_];
__device__ __align__(16) bf16 g_wo_h[L_*D_*D_], g_wo_l[L_*D_*D_];
__device__ __align__(16) bf16 g_w1_h[L_*D_*F_], g_w1_l[L_*D_*F_];
__device__ __align__(16) bf16 g_w2_h[L_*F_*D_], g_w2_l[L_*F_*D_];
__device__ __align__(16) bf16 g_et_h[(size_t)D_*V_], g_et_l[(size_t)D_*V_]; // emb^T [D][V]

// ---------------- helpers ----------------
__device__ __forceinline__ u32 cvt_smem(const void* p){
    return (u32)__cvta_generic_to_shared(p);
}
__device__ __forceinline__ void cp16(u32 s, const void* g){
    asm volatile("cp.async.cg.shared.global [%0],[%1],16;\n"::"r"(s),"l"(g));
}
__device__ __forceinline__ void cp_commit(){ asm volatile("cp.async.commit_group;\n"::); }
template<int NN> __device__ __forceinline__ void cp_wait(){
    asm volatile("cp.async.wait_group %0;\n"::"n"(NN));
}
__device__ __forceinline__ void ldsm4(u32 &r0,u32 &r1,u32 &r2,u32 &r3, u32 a){
    asm volatile("ldmatrix.sync.aligned.m8n8.x4.shared.b16 {%0,%1,%2,%3},[%4];\n"
        : "=r"(r0),"=r"(r1),"=r"(r2),"=r"(r3) : "r"(a));
}
__device__ __forceinline__ void ldsm4t(u32 &r0,u32 &r1,u32 &r2,u32 &r3, u32 a){
    asm volatile("ldmatrix.sync.aligned.m8n8.x4.trans.shared.b16 {%0,%1,%2,%3},[%4];\n"
        : "=r"(r0),"=r"(r1),"=r"(r2),"=r"(r3) : "r"(a));
}
__device__ __forceinline__ void mma16816(float* c, const u32* a, const u32* b){
    asm volatile("mma.sync.aligned.m16n8k16.row.col.f32.bf16.bf16.f32 "
        "{%0,%1,%2,%3},{%4,%5,%6,%7},{%8,%9},{%0,%1,%2,%3};\n"
        : "+f"(c[0]),"+f"(c[1]),"+f"(c[2]),"+f"(c[3])
        : "r"(a[0]),"r"(a[1]),"r"(a[2]),"r"(a[3]),"r"(b[0]),"r"(b[1]));
}
__device__ __forceinline__ u32 pack2(bf16 h0, bf16 h1){
    unsigned short u0 = *reinterpret_cast<unsigned short*>(&h0);
    unsigned short u1 = *reinterpret_cast<unsigned short*>(&h1);
    return (u32)u0 | ((u32)u1 << 16);
}
__device__ __forceinline__ void split2(float x0, float x1, u32 &hi, u32 &lo){
    bf16 h0 = __float2bfloat16_rn(x0);
    bf16 h1 = __float2bfloat16_rn(x1);
    float f0 = __bfloat162float(h0), f1 = __bfloat162float(h1);
    hi = pack2(h0, h1);
    lo = pack2(__float2bfloat16_rn(x0 - f0), __float2bfloat16_rn(x1 - f1));
}
__device__ __forceinline__ float geluf(float x){
    return 0.5f*x*(1.0f + erff(x*0.7071067811865476f));
}

// ---------------- conversion kernels ----------------
__global__ void k_cvt(const float4* __restrict__ src, uint2* __restrict__ dh,
                      uint2* __restrict__ dl, int n4)
{
    int i = blockIdx.x*256 + threadIdx.x;
    if (i >= n4) return;
    float4 v = src[i];
    u32 h0,l0,h1,l1;
    split2(v.x,v.y,h0,l0); split2(v.z,v.w,h1,l1);
    dh[i] = make_uint2(h0,h1);
    dl[i] = make_uint2(l0,l1);
}

// emb [V][D] fp32 -> emb^T [D][V] bf16 hi/lo, tiled transpose
__global__ void k_cvt_t(const float* __restrict__ src, bf16* __restrict__ dh,
                        bf16* __restrict__ dl)
{
    __shared__ float t[32][33];
    int v0 = blockIdx.x*32, d0 = blockIdx.y*32;
    int tx = threadIdx.x, ty = threadIdx.y;   // 32 x 8
    #pragma unroll
    for (int i=0;i<4;i++)
        t[ty+8*i][tx] = src[(size_t)(v0+ty+8*i)*D_ + d0 + tx];
    __syncthreads();
    #pragma unroll
    for (int i=0;i<4;i++){
        int dy = ty + 8*i;
        float val = t[tx][dy];
        bf16 hh = __float2bfloat16_rn(val);
        size_t o = (size_t)(d0+dy)*V_ + v0 + tx;
        dh[o] = hh;
        dl[o] = __float2bfloat16_rn(val - __bfloat162float(hh));
    }
}

// ---------------- embedding + sinusoidal PE ----------------
__global__ void k_embed(const int* __restrict__ ids, const float* __restrict__ emb,
                        float* __restrict__ x)
{
    int idx = blockIdx.x * 256 + threadIdx.x;
    if (idx >= M_*D_) return;
    int d  = idx & (D_-1);
    int ms = idx >> 10;
    int s  = ms & (S_-1);
    int tok = ids[ms];
    int i2 = d & ~1;
    float freq = expf((float)i2 * (-9.210340371976184f / (float)D_));
    float ang  = (float)s * freq;
    float pe   = (d & 1) ? cosf(ang) : sinf(ang);
    x[idx] = emb[tok*D_ + d] * 32.0f + pe;
}

// ---------------- layernorm: fp32 in, bf16 hi/lo out ----------------
__global__ void __launch_bounds__(256) k_ln(const float* __restrict__ x,
                                            const float* __restrict__ g,
                                            const float* __restrict__ b,
                                            bf16* __restrict__ oh,
                                            bf16* __restrict__ ol)
{
    int row = blockIdx.x;
    int t = threadIdx.x;
    float4 v = ((const float4*)(x + (size_t)row*D_))[t];
    float s  = v.x+v.y+v.z+v.w;
    float ss = v.x*v.x+v.y*v.y+v.z*v.z+v.w*v.w;
    #pragma unroll
    for (int o=16;o>0;o>>=1){
        s  += __shfl_xor_sync(0xffffffffu, s,  o);
        ss += __shfl_xor_sync(0xffffffffu, ss, o);
    }
    __shared__ float rs[8], rss[8];
    if ((t&31)==0){ rs[t>>5]=s; rss[t>>5]=ss; }
    __syncthreads();
    float tot=0.f, tot2=0.f;
    #pragma unroll
    for (int i=0;i<8;i++){ tot += rs[i]; tot2 += rss[i]; }
    float mean = tot * (1.0f/D_);
    float var  = tot2 * (1.0f/D_) - mean*mean;
    float rstd = rsqrtf(var + 1e-5f);
    float4 gv = ((const float4*)g)[t];
    float4 bv = ((const float4*)b)[t];
    float o0=(v.x-mean)*rstd*gv.x+bv.x, o1=(v.y-mean)*rstd*gv.y+bv.y;
    float o2=(v.z-mean)*rstd*gv.z+bv.z, o3=(v.w-mean)*rstd*gv.w+bv.w;
    u32 h0,l0,h1,l1;
    split2(o0,o1,h0,l0); split2(o2,o3,h1,l1);
    ((uint2*)(oh + (size_t)row*D_))[t] = make_uint2(h0,h1);
    ((uint2*)(ol + (size_t)row*D_))[t] = make_uint2(l0,l1);
}

// ---------------- tensor-core GEMM, pre-split bf16 operands ----------------
// C[M,N] = A[M,K] @ B[K,N]   (A,B given as hi/lo bf16)
// EPI: 0 = bf16split(+bias), 1 = bf16split gelu(+bias), 2 = fp32 +bias+residual, 3 = fp32 plain
template<int EPI>
__global__ void __launch_bounds__(256) k_gemm(
    int N, int K,
    const bf16* __restrict__ Ah, const bf16* __restrict__ Al,
    const bf16* Bh0, const bf16* Bl0, const bf16* Bh1, const bf16* Bl1,
    const bf16* Bh2, const bf16* Bl2,
    const float* bias0, const float* bias1, const float* bias2,
    const float* __restrict__ res,
    void* C0a, void* C0b, void* C1a, void* C1b, void* C2a, void* C2b)
{
    constexpr int AKP = 24;        // 16 + 8 pad -> 48B stride (16B-aligned, conflict-free)
    constexpr int BNP = BN + 8;    // 136 -> 272B stride (16B-aligned, conflict-free)
    __shared__ __align__(16) bf16 As_h[2][BM][AKP];
    __shared__ __align__(16) bf16 As_l[2][BM][AKP];
    __shared__ __align__(16) bf16 Bs_h[2][16][BNP];
    __shared__ __align__(16) bf16 Bs_l[2][16][BNP];

    const int z = blockIdx.z;
    const bf16* Bh = (z==0)?Bh0:((z==1)?Bh1:Bh2);
    const bf16* Bl = (z==0)?Bl0:((z==1)?Bl1:Bl2);
    const float* bias = (z==0)?bias0:((z==1)?bias1:bias2);
    void* Ca = (z==0)?C0a:((z==1)?C1a:C2a);
    void* Cb = (z==0)?C0b:((z==1)?C1b:C2b);

    const int tid = threadIdx.x;
    const int lane = tid & 31, wid = tid>>5;
    const int m_base = (wid&1)*64, n_base = (wid>>1)*32;
    const int bm = blockIdx.y*BM, bn = blockIdx.x*BN;

    // cp.async assignments: 1 x 16B chunk per thread per buffer
    const int ar = tid>>1, ac = (tid&1)*8;    // A: 128 rows x 2 chunks
    const int br = tid>>4, bc = (tid&15)*8;   // B: 16 rows x 16 chunks
    const bf16* Agh = Ah + (size_t)(bm+ar)*K + ac;
    const bf16* Agl = Al + (size_t)(bm+ar)*K + ac;
    const bf16* Bgh = Bh + (size_t)br*N + bn + bc;
    const bf16* Bgl = Bl + (size_t)br*N + bn + bc;

    const int q2 = lane>>3;
    u32 abh[2], abl[2], bbh[2], bbl[2];
    #pragma unroll
    for (int st=0; st<2; st++){
        abh[st] = cvt_smem(&As_h[st][m_base + (lane&15)][(lane>>4)*8]);
        abl[st] = cvt_smem(&As_l[st][m_base + (lane&15)][(lane>>4)*8]);
        bbh[st] = cvt_smem(&Bs_h[st][(q2&1)*8 + (lane&7)][n_base + (q2>>1)*8]);
        bbl[st] = cvt_smem(&Bs_l[st][(q2&1)*8 + (lane&7)][n_base + (q2>>1)*8]);
    }

    float acc[4][4][4];
    #pragma unroll
    for (int i=0;i<4;i++)
        #pragma unroll
        for (int j=0;j<4;j++)
            #pragma unroll
            for (int r=0;r<4;r++) acc[i][j][r]=0.f;

    auto issue = [&](int kt, int st){
        cp16(cvt_smem(&As_h[st][ar][ac]), Agh + kt*16);
        cp16(cvt_smem(&As_l[st][ar][ac]), Agl + kt*16);
        cp16(cvt_smem(&Bs_h[st][br][bc]), Bgh + (size_t)kt*16*N);
        cp16(cvt_smem(&Bs_l[st][br][bc]), Bgl + (size_t)kt*16*N);
        cp_commit();
    };

    const int nk = K/16;   // always >= 64
    issue(0,0);
    issue(1,1);

    for (int kt=0; kt<nk; kt++){
        if (kt+1<nk) cp_wait<1>(); else cp_wait<0>();
        __syncthreads();
        const int st = kt & 1;

        u32 fah[4][4], fal[4][4];
        #pragma unroll
        for (int mi=0;mi<4;mi++){
            ldsm4(fah[mi][0],fah[mi][1],fah[mi][2],fah[mi][3], abh[st] + mi*768);
            ldsm4(fal[mi][0],fal[mi][1],fal[mi][2],fal[mi][3], abl[st] + mi*768);
        }
        u32 fbh[4][2], fbl[4][2];
        #pragma unroll
        for (int p=0;p<2;p++){
            u32 r0,r1,r2,r3;
            ldsm4t(r0,r1,r2,r3, bbh[st] + p*32);
            fbh[2*p][0]=r0; fbh[2*p][1]=r1; fbh[2*p+1][0]=r2; fbh[2*p+1][1]=r3;
            ldsm4t(r0,r1,r2,r3, bbl[st] + p*32);
            fbl[2*p][0]=r0; fbl[2*p][1]=r1; fbl[2*p+1][0]=r2; fbl[2*p+1][1]=r3;
        }
        #pragma unroll
        for (int mi=0;mi<4;mi++)
            #pragma unroll
            for (int nj=0;nj<4;nj++){
                mma16816(acc[mi][nj], fah[mi], fbh[nj]);
                mma16816(acc[mi][nj], fah[mi], fbl[nj]);
                mma16816(acc[mi][nj], fal[mi], fbh[nj]);
            }
        if (kt+2 < nk){
            __syncthreads();
            issue(kt+2, st);
        }
    }

    // ---- epilogue ----
    #pragma unroll
    for (int mi=0; mi<4; mi++){
        #pragma unroll
        for (int r=0; r<2; r++){
            int gm = bm + m_base + mi*16 + (lane>>2) + r*8;
            #pragma unroll
            for (int nj=0; nj<4; nj++){
                int gn = bn + n_base + nj*8 + (lane&3)*2;
                float v0 = acc[mi][nj][r*2+0];
                float v1 = acc[mi][nj][r*2+1];
                if (EPI != 3){ v0 += bias[gn]; v1 += bias[gn+1]; }
                if (EPI == 1){ v0 = geluf(v0); v1 = geluf(v1); }
                size_t base = (size_t)gm*N + gn;
                if (EPI == 2){
                    float2 rr = *(const float2*)(res + base);
                    *(float2*)((float*)Ca + base) = make_float2(v0+rr.x, v1+rr.y);
                } else if (EPI == 3){
                    *(float2*)((float*)Ca + base) = make_float2(v0, v1);
                } else {
                    u32 h_,l_;
                    split2(v0, v1, h_, l_);
                    *(u32*)((bf16*)Ca + base) = h_;
                    *(u32*)((bf16*)Cb + base) = l_;
                }
            }
        }
    }
}

// ---------------- tensor-core flash attention ----------------
// grid (S/64, B*H), 128 threads (4 warps, 16 q-rows each)
__global__ void __launch_bounds__(128) k_attn(
    const bf16* __restrict__ Qh, const bf16* __restrict__ Ql,
    const bf16* __restrict__ Kh, const bf16* __restrict__ Kl,
    const bf16* __restrict__ Vh, const bf16* __restrict__ Vl,
    bf16* __restrict__ Oh, bf16* __restrict__ Ol)
{
    __shared__ __align__(16) bf16 Ka_h[64][72];  // Q first, then K
    __shared__ __align__(16) bf16 Ka_l[64][72];
    __shared__ __align__(16) bf16 Va_h[64][72];
    __shared__ __align__(16) bf16 Va_l[64][72];

    const int tid = threadIdx.x;
    const int lane = tid & 31;
    const int w = tid >> 5;
    const int qt = blockIdx.x;
    const int bh = blockIdx.y;
    const int bb = bh >> 4;
    const int hh = bh & 15;
    const int g  = lane >> 2;
    const int n2 = (lane & 3) * 2;
    const int q2 = lane >> 3;

    const size_t qrow0 = (size_t)bb*S_ + qt*64;
    const int col0 = hh*DK_;

    // ---- load Q tile (64 x 64) hi/lo ----
    #pragma unroll
    for (int i=0;i<4;i++){
        int cid = tid + i*128;
        int r = cid >> 3, ch = cid & 7;
        size_t go = (qrow0 + r)*D_ + col0 + ch*8;
        cp16(cvt_smem(&Ka_h[r][ch*8]), Qh + go);
        cp16(cvt_smem(&Ka_l[r][ch*8]), Ql + go);
    }
    cp_commit();
    cp_wait<0>();
    __syncthreads();

    // ---- extract Q fragments ----
    u32 qfh[4][4], qfl[4][4];
    {
        u32 ah = cvt_smem(&Ka_h[w*16 + (lane&15)][(lane>>4)*8]);
        u32 al = cvt_smem(&Ka_l[w*16 + (lane&15)][(lane>>4)*8]);
        #pragma unroll
        for (int ks=0; ks<4; ks++){
            ldsm4(qfh[ks][0],qfh[ks][1],qfh[ks][2],qfh[ks][3], ah + ks*32);
            ldsm4(qfl[ks][0],qfl[ks][1],qfl[ks][2],qfl[ks][3], al + ks*32);
        }
    }

    float m[2]    = {-1e30f, -1e30f};
    float lsum[2] = {0.f, 0.f};
    float oa[8][4];
    #pragma unroll
    for (int i=0;i<8;i++)
        #pragma unroll
        for (int j=0;j<4;j++) oa[i][j]=0.f;

    for (int kt=0; kt<=qt; kt++){
        __syncthreads();   // Q frags extracted / previous tile fully read
        // ---- load K,V tile (64 keys x 64 dims) hi/lo ----
        #pragma unroll
        for (int i=0;i<4;i++){
            int cid = tid + i*128;
            int r = cid >> 3, ch = cid & 7;
            size_t go = ((size_t)bb*S_ + kt*64 + r)*D_ + col0 + ch*8;
            cp16(cvt_smem(&Ka_h[r][ch*8]), Kh + go);
            cp16(cvt_smem(&Ka_l[r][ch*8]), Kl + go);
            cp16(cvt_smem(&Va_h[r][ch*8]), Vh + go);
            cp16(cvt_smem(&Va_l[r][ch*8]), Vl + go);
        }
        cp_commit();
        cp_wait<0>();
        __syncthreads();

        // ---- scores: S = Q K^T (3-pass split) ----
        float s[8][4];
        #pragma unroll
        for (int nt=0;nt<8;nt++)
            #pragma unroll
            for (int j=0;j<4;j++) s[nt][j]=0.f;

        #pragma unroll
        for (int ks=0; ks<4; ks++){
            u32 kbh[8][2], kbl[8][2];
            #pragma unroll
            for (int pr=0; pr<4; pr++){
                u32 r0,r1,r2,r3;
                u32 a = cvt_smem(&Ka_h[pr*16 + (q2&1)*8 + (lane&7)][(q2>>1)*8]) + ks*32;
                ldsm4(r0,r1,r2,r3, a);
                kbh[2*pr][0]=r0; kbh[2*pr][1]=r2; kbh[2*pr+1][0]=r1; kbh[2*pr+1][1]=r3;
                u32 b = cvt_smem(&Ka_l[pr*16 + (q2&1)*8 + (lane&7)][(q2>>1)*8]) + ks*32;
                ldsm4(r0,r1,r2,r3, b);
                kbl[2*pr][0]=r0; kbl[2*pr][1]=r2; kbl[2*pr+1][0]=r1; kbl[2*pr+1][1]=r3;
            }
            #pragma unroll
            for (int nt=0; nt<8; nt++){
                mma16816(s[nt], qfh[ks], kbh[nt]);
                mma16816(s[nt], qfh[ks], kbl[nt]);
                mma16816(s[nt], qfl[ks], kbh[nt]);
            }
        }

        // ---- scale + causal mask ----
        const bool diag = (kt == qt);
        #pragma unroll
        for (int nt=0;nt<8;nt++)
            #pragma unroll
            for (int j=0;j<4;j++){
                float v = s[nt][j]*0.125f;
                if (diag){
                    int col  = nt*8 + n2 + (j&1);
                    int rowl = w*16 + g + (j>>1)*8;
                    if (col > rowl) v = -1e30f;
                }
                s[nt][j] = v;
            }

        // ---- online softmax ----
        float mx0=-1e30f, mx1=-1e30f;
        #pragma unroll
        for (int nt=0;nt<8;nt++){
            mx0 = fmaxf(mx0, fmaxf(s[nt][0], s[nt][1]));
            mx1 = fmaxf(mx1, fmaxf(s[nt][2], s[nt][3]));
        }
        mx0 = fmaxf(mx0, __shfl_xor_sync(0xffffffffu, mx0, 1));
        mx0 = fmaxf(mx0, __shfl_xor_sync(0xffffffffu, mx0, 2));
        mx1 = fmaxf(mx1, __shfl_xor_sync(0xffffffffu, mx1, 1));
        mx1 = fmaxf(mx1, __shfl_xor_sync(0xffffffffu, mx1, 2));
        float mn0 = fmaxf(m[0], mx0), mn1 = fmaxf(m[1], mx1);
        float c0 = __expf(m[0]-mn0), c1 = __expf(m[1]-mn1);
        float ps0=0.f, ps1=0.f;
        #pragma unroll
        for (int nt=0;nt<8;nt++){
            s[nt][0] = __expf(s[nt][0]-mn0); ps0 += s[nt][0];
            s[nt][1] = __expf(s[nt][1]-mn0); ps0 += s[nt][1];
            s[nt][2] = __expf(s[nt][2]-mn1); ps1 += s[nt][2];
            s[nt][3] = __expf(s[nt][3]-mn1); ps1 += s[nt][3];
        }
        ps0 += __shfl_xor_sync(0xffffffffu, ps0, 1);
        ps0 += __shfl_xor_sync(0xffffffffu, ps0, 2);
        ps1 += __shfl_xor_sync(0xffffffffu, ps1, 1);
        ps1 += __shfl_xor_sync(0xffffffffu, ps1, 2);
        lsum[0] = lsum[0]*c0 + ps0;
        lsum[1] = lsum[1]*c1 + ps1;
        m[0] = mn0; m[1] = mn1;
        #pragma unroll
        for (int dt=0;dt<8;dt++){
            oa[dt][0]*=c0; oa[dt][1]*=c0; oa[dt][2]*=c1; oa[dt][3]*=c1;
        }

        // ---- O += P V (3-pass split; P fragments straight from registers) ----
        #pragma unroll
        for (int ks=0; ks<4; ks++){
            u32 pfh[4], pfl[4];
            split2(s[2*ks  ][0], s[2*ks  ][1], pfh[0], pfl[0]);
            split2(s[2*ks  ][2], s[2*ks  ][3], pfh[1], pfl[1]);
            split2(s[2*ks+1][0], s[2*ks+1][1], pfh[2], pfl[2]);
            split2(s[2*ks+1][2], s[2*ks+1][3], pfh[3], pfl[3]);

            u32 vbh[8][2], vbl[8][2];
            #pragma unroll
            for (int dp=0; dp<4; dp++){
                u32 r0,r1,r2,r3;
                u32 a = cvt_smem(&Va_h[ks*16 + (q2&1)*8 + (lane&7)][dp*16 + (q2>>1)*8]);
                ldsm4t(r0,r1,r2,r3, a);
                vbh[2*dp][0]=r0; vbh[2*dp][1]=r1; vbh[2*dp+1][0]=r2; vbh[2*dp+1][1]=r3;
                u32 b = cvt_smem(&Va_l[ks*16 + (q2&1)*8 + (lane&7)][dp*16 + (q2>>1)*8]);
                ldsm4t(r0,r1,r2,r3, b);
                vbl[2*dp][0]=r0; vbl[2*dp][1]=r1; vbl[2*dp+1][0]=r2; vbl[2*dp+1][1]=r3;
            }
            #pragma unroll
            for (int dt=0; dt<8; dt++){
                mma16816(oa[dt], pfh, vbh[dt]);
                mma16816(oa[dt], pfh, vbl[dt]);
                mma16816(oa[dt], pfl, vbh[dt]);
            }
        }
    }

    // ---- epilogue ----
    float inv0 = 1.0f/lsum[0], inv1 = 1.0f/lsum[1];
    size_t r0 = qrow0 + w*16 + g;
    size_t r1 = r0 + 8;
    #pragma unroll
    for (int dt=0; dt<8; dt++){
        int col = col0 + dt*8 + n2;
        u32 h_,l_;
        split2(oa[dt][0]*inv0, oa[dt][1]*inv0, h_, l_);
        *(u32*)(Oh + r0*D_ + col) = h_;
        *(u32*)(Ol + r0*D_ + col) = l_;
        split2(oa[dt][2]*inv1, oa[dt][3]*inv1, h_, l_);
        *(u32*)(Oh + r1*D_ + col) = h_;
        *(u32*)(Ol + r1*D_ + col) = l_;
    }
}

// ---------------- orchestration ----------------
extern "C" void kernel_launch(void* const* d_in, const int* in_sizes, int n_in,
                              void* d_out, int out_size)
{
    (void)in_sizes; (void)n_in; (void)out_size;
    const int*   ids  = (const int*)  d_in[0];
    const float* emb  = (const float*)d_in[1];
    const float* wq   = (const float*)d_in[2];
    const float* bq   = (const float*)d_in[3];
    const float* wk   = (const float*)d_in[4];
    const float* bk   = (const float*)d_in[5];
    const float* wv   = (const float*)d_in[6];
    const float* bv   = (const float*)d_in[7];
    const float* wo   = (const float*)d_in[8];
    const float* bo   = (const float*)d_in[9];
    const float* ln1g = (const float*)d_in[10];
    const float* ln1b = (const float*)d_in[11];
    const float* ln2g = (const float*)d_in[12];
    const float* ln2b = (const float*)d_in[13];
    const float* w1   = (const float*)d_in[14];
    const float* b1   = (const float*)d_in[15];
    const float* w2   = (const float*)d_in[16];
    const float* b2   = (const float*)d_in[17];
    const float* lnfg = (const float*)d_in[18];
    const float* lnfb = (const float*)d_in[19];
    float* out = (float*)d_out;

    float* px;  cudaGetSymbolAddress((void**)&px,  g_x);
    bf16 *hh,*hl,*qh,*ql,*kh,*kl,*vh,*vl,*ah,*al,*fh,*fl;
    cudaGetSymbolAddress((void**)&hh, g_h_h); cudaGetSymbolAddress((void**)&hl, g_h_l);
    cudaGetSymbolAddress((void**)&qh, g_q_h); cudaGetSymbolAddress((void**)&ql, g_q_l);
    cudaGetSymbolAddress((void**)&kh, g_k_h); cudaGetSymbolAddress((void**)&kl, g_k_l);
    cudaGetSymbolAddress((void**)&vh, g_v_h); cudaGetSymbolAddress((void**)&vl, g_v_l);
    cudaGetSymbolAddress((void**)&ah, g_a_h); cudaGetSymbolAddress((void**)&al, g_a_l);
    cudaGetSymbolAddress((void**)&fh, g_f_h); cudaGetSymbolAddress((void**)&fl, g_f_l);
    bf16 *wqh,*wql,*wkh,*wkl,*wvh,*wvl,*woh,*wol,*w1h,*w1l,*w2h,*w2l,*eth,*etl;
    cudaGetSymbolAddress((void**)&wqh, g_wq_h); cudaGetSymbolAddress((void**)&wql, g_wq_l);
    cudaGetSymbolAddress((void**)&wkh, g_wk_h); cudaGetSymbolAddress((void**)&wkl, g_wk_l);
    cudaGetSymbolAddress((void**)&wvh, g_wv_h); cudaGetSymbolAddress((void**)&wvl, g_wv_l);
    cudaGetSymbolAddress((void**)&woh, g_wo_h); cudaGetSymbolAddress((void**)&wol, g_wo_l);
    cudaGetSymbolAddress((void**)&w1h, g_w1_h); cudaGetSymbolAddress((void**)&w1l, g_w1_l);
    cudaGetSymbolAddress((void**)&w2h, g_w2_h); cudaGetSymbolAddress((void**)&w2l, g_w2_l);
    cudaGetSymbolAddress((void**)&eth, g_et_h); cudaGetSymbolAddress((void**)&etl, g_et_l);

    // ---- weight conversion (per launch; ~150us, memory-bound) ----
    {
        int nA = L_*D_*D_/4;   // 1.57M float4
        k_cvt<<<(nA+255)/256,256>>>((const float4*)wq, (uint2*)wqh, (uint2*)wql, nA);
        k_cvt<<<(nA+255)/256,256>>>((const float4*)wk, (uint2*)wkh, (uint2*)wkl, nA);
        k_cvt<<<(nA+255)/256,256>>>((const float4*)wv, (uint2*)wvh, (uint2*)wvl, nA);
        k_cvt<<<(nA+255)/256,256>>>((const float4*)wo, (uint2*)woh, (uint2*)wol, nA);
        int nF = L_*D_*F_/4;
        k_cvt<<<(nF+255)/256,256>>>((const float4*)w1, (uint2*)w1h, (uint2*)w1l, nF);
        k_cvt<<<(nF+255)/256,256>>>((const float4*)w2, (uint2*)w2h, (uint2*)w2l, nF);
        k_cvt_t<<<dim3(V_/32, D_/32), dim3(32,8)>>>(emb, eth, etl);
    }

    k_embed<<<(M_*D_+255)/256, 256>>>(ids, emb, px);

    for (int l=0; l<L_; l++){
        size_t odd = (size_t)l*D_*D_;
        size_t off = (size_t)l*D_*F_;
        k_ln<<<M_,256>>>(px, ln1g+l*D_, ln1b+l*D_, hh, hl);
        // fused QKV
        k_gemm<0><<<dim3(D_/BN, M_/BM, 3),256>>>(D_, D_, hh, hl,
            wqh+odd, wql+odd, wkh+odd, wkl+odd, wvh+odd, wvl+odd,
            bq+l*D_, bk+l*D_, bv+l*D_,
            nullptr, qh, ql, kh, kl, vh, vl);
        k_attn<<<dim3(S_/64, B_*H_),128>>>(qh, ql, kh, kl, vh, vl, ah, al);
        // x = x + attn @ Wo + bo
        k_gemm<2><<<dim3(D_/BN, M_/BM, 1),256>>>(D_, D_, ah, al,
            woh+odd, wol+odd, woh+odd, wol+odd, woh+odd, wol+odd,
            bo+l*D_, bo+l*D_, bo+l*D_,
            px, px, nullptr, px, nullptr, px, nullptr);
        k_ln<<<M_,256>>>(px, ln2g+l*D_, ln2b+l*D_, hh, hl);
        // ffn1: gelu(h @ W1 + b1) -> bf16 split
        k_gemm<1><<<dim3(F_/BN, M_/BM, 1),256>>>(F_, D_, hh, hl,
            w1h+off, w1l+off, w1h+off, w1l+off, w1h+off, w1l+off,
            b1+l*F_, b1+l*F_, b1+l*F_,
            nullptr, fh, fl, fh, fl, fh, fl);
        // ffn2: x = x + f @ W2 + b2
        k_gemm<2><<<dim3(D_/BN, M_/BM, 1),256>>>(D_, F_, fh, fl,
            w2h+off, w2l+off, w2h+off, w2l+off, w2h+off, w2l+off,
            b2+l*D_, b2+l*D_, b2+l*D_,
            px, px, nullptr, px, nullptr, px, nullptr);
    }
    k_ln<<<M_,256>>>(px, lnfg, lnfb, hh, hl);
    // logits = h @ emb^T  via pre-transposed emb_t [D][V]
    k_gemm<3><<<dim3(V_/BN, M_/BM, 1),256>>>(V_, D_, hh, hl,
        eth, etl, eth, etl, eth, etl,
        nullptr, nullptr, nullptr,
        nullptr, out, nullptr, out, nullptr, out, nullptr);
}

// round 8
// speedup vs baseline: 4.4761x; 1.1191x over previous
#include <cuda_runtime.h>
#include <cuda_bf16.h>
#include <cstdint>
#include <math.h>

typedef unsigned int u32;
typedef __nv_bfloat16 bf16;

#define B_  2
#define S_  1024
#define D_  1024
#define H_  16
#define F_  4096
#define L_  6
#define V_  32000
#define DK_ 64
#define M_  (B_*S_)

#define BM 128
#define BN 128

// ---------------- persistent scratch ----------------
__device__ __align__(16) float g_x [M_*D_];
__device__ __align__(16) bf16 g_h_h[M_*D_],  g_h_l[M_*D_];
__device__ __align__(16) bf16 g_q_h[M_*D_],  g_q_l[M_*D_];
__device__ __align__(16) bf16 g_k_h[M_*D_],  g_k_l[M_*D_];
__device__ __align__(16) bf16 g_v_h[M_*D_],  g_v_l[M_*D_];
__device__ __align__(16) bf16 g_a_h[M_*D_],  g_a_l[M_*D_];
__device__ __align__(16) bf16 g_f_h[M_*F_],  g_f_l[M_*F_];
__device__ __align__(16) bf16 g_wq_h[L_*D_*D_], g_wq_l[L_*D_*D_];
__device__ __align__(16) bf16 g_wk_h[L_*D_*D_], g_wk_l[L_*D_*D_];
__device__ __align__(16) bf16 g_wv_h[L_*D_*D_], g_wv_l[L_*D_*D_];
__device__ __align__(16) bf16 g_wo_h[L_*D_*D_], g_wo_l[L_*D_*D_];
__device__ __align__(16) bf16 g_w1_h[L_*D_*F_], g_w1_l[L_*D_*F_];
__device__ __align__(16) bf16 g_w2_h[L_*F_*D_], g_w2_l[L_*F_*D_];
__device__ __align__(16) bf16 g_et_h[(size_t)D_*V_], g_et_l[(size_t)D_*V_];

// ---------------- helpers ----------------
__device__ __forceinline__ u32 cvt_smem(const void* p){
    return (u32)__cvta_generic_to_shared(p);
}
__device__ __forceinline__ void cp16(u32 s, const void* g){
    asm volatile("cp.async.cg.shared.global [%0],[%1],16;\n"::"r"(s),"l"(g));
}
__device__ __forceinline__ void cp_commit(){ asm volatile("cp.async.commit_group;\n"::); }
template<int NN> __device__ __forceinline__ void cp_wait(){
    asm volatile("cp.async.wait_group %0;\n"::"n"(NN));
}
__device__ __forceinline__ void ldsm4(u32 &r0,u32 &r1,u32 &r2,u32 &r3, u32 a){
    asm volatile("ldmatrix.sync.aligned.m8n8.x4.shared.b16 {%0,%1,%2,%3},[%4];\n"
        : "=r"(r0),"=r"(r1),"=r"(r2),"=r"(r3) : "r"(a));
}
__device__ __forceinline__ void ldsm4t(u32 &r0,u32 &r1,u32 &r2,u32 &r3, u32 a){
    asm volatile("ldmatrix.sync.aligned.m8n8.x4.trans.shared.b16 {%0,%1,%2,%3},[%4];\n"
        : "=r"(r0),"=r"(r1),"=r"(r2),"=r"(r3) : "r"(a));
}
__device__ __forceinline__ void mma16816(float* c, const u32* a, const u32* b){
    asm volatile("mma.sync.aligned.m16n8k16.row.col.f32.bf16.bf16.f32 "
        "{%0,%1,%2,%3},{%4,%5,%6,%7},{%8,%9},{%0,%1,%2,%3};\n"
        : "+f"(c[0]),"+f"(c[1]),"+f"(c[2]),"+f"(c[3])
        : "r"(a[0]),"r"(a[1]),"r"(a[2]),"r"(a[3]),"r"(b[0]),"r"(b[1]));
}
__device__ __forceinline__ u32 pack2(bf16 h0, bf16 h1){
    unsigned short u0 = *reinterpret_cast<unsigned short*>(&h0);
    unsigned short u1 = *reinterpret_cast<unsigned short*>(&h1);
    return (u32)u0 | ((u32)u1 << 16);
}
__device__ __forceinline__ void split2(float x0, float x1, u32 &hi, u32 &lo){
    bf16 h0 = __float2bfloat16_rn(x0);
    bf16 h1 = __float2bfloat16_rn(x1);
    float f0 = __bfloat162float(h0), f1 = __bfloat162float(h1);
    hi = pack2(h0, h1);
    lo = pack2(__float2bfloat16_rn(x0 - f0), __float2bfloat16_rn(x1 - f1));
}
__device__ __forceinline__ float geluf(float x){
    return 0.5f*x*(1.0f + erff(x*0.7071067811865476f));
}

// ---------------- conversion kernels ----------------
__global__ void k_cvt(const float4* __restrict__ src, uint2* __restrict__ dh,
                      uint2* __restrict__ dl, int n4)
{
    int i = blockIdx.x*256 + threadIdx.x;
    if (i >= n4) return;
    float4 v = src[i];
    u32 h0,l0,h1,l1;
    split2(v.x,v.y,h0,l0); split2(v.z,v.w,h1,l1);
    dh[i] = make_uint2(h0,h1);
    dl[i] = make_uint2(l0,l1);
}

__global__ void k_cvt_t(const float* __restrict__ src, bf16* __restrict__ dh,
                        bf16* __restrict__ dl)
{
    __shared__ float t[32][33];
    int v0 = blockIdx.x*32, d0 = blockIdx.y*32;
    int tx = threadIdx.x, ty = threadIdx.y;   // 32 x 8
    #pragma unroll
    for (int i=0;i<4;i++)
        t[ty+8*i][tx] = src[(size_t)(v0+ty+8*i)*D_ + d0 + tx];
    __syncthreads();
    #pragma unroll
    for (int i=0;i<4;i++){
        int dy = ty + 8*i;
        float val = t[tx][dy];
        bf16 hh = __float2bfloat16_rn(val);
        size_t o = (size_t)(d0+dy)*V_ + v0 + tx;
        dh[o] = hh;
        dl[o] = __float2bfloat16_rn(val - __bfloat162float(hh));
    }
}

// ---------------- embedding + sinusoidal PE ----------------
__global__ void k_embed(const int* __restrict__ ids, const float* __restrict__ emb,
                        float* __restrict__ x)
{
    int idx = blockIdx.x * 256 + threadIdx.x;
    if (idx >= M_*D_) return;
    int d  = idx & (D_-1);
    int ms = idx >> 10;
    int s  = ms & (S_-1);
    int tok = ids[ms];
    int i2 = d & ~1;
    float freq = expf((float)i2 * (-9.210340371976184f / (float)D_));
    float ang  = (float)s * freq;
    float pe   = (d & 1) ? cosf(ang) : sinf(ang);
    x[idx] = emb[tok*D_ + d] * 32.0f + pe;
}

// ---------------- layernorm ----------------
__global__ void __launch_bounds__(256) k_ln(const float* __restrict__ x,
                                            const float* __restrict__ g,
                                            const float* __restrict__ b,
                                            bf16* __restrict__ oh,
                                            bf16* __restrict__ ol)
{
    int row = blockIdx.x;
    int t = threadIdx.x;
    float4 v = ((const float4*)(x + (size_t)row*D_))[t];
    float s  = v.x+v.y+v.z+v.w;
    float ss = v.x*v.x+v.y*v.y+v.z*v.z+v.w*v.w;
    #pragma unroll
    for (int o=16;o>0;o>>=1){
        s  += __shfl_xor_sync(0xffffffffu, s,  o);
        ss += __shfl_xor_sync(0xffffffffu, ss, o);
    }
    __shared__ float rs[8], rss[8];
    if ((t&31)==0){ rs[t>>5]=s; rss[t>>5]=ss; }
    __syncthreads();
    float tot=0.f, tot2=0.f;
    #pragma unroll
    for (int i=0;i<8;i++){ tot += rs[i]; tot2 += rss[i]; }
    float mean = tot * (1.0f/D_);
    float var  = tot2 * (1.0f/D_) - mean*mean;
    float rstd = rsqrtf(var + 1e-5f);
    float4 gv = ((const float4*)g)[t];
    float4 bv = ((const float4*)b)[t];
    float o0=(v.x-mean)*rstd*gv.x+bv.x, o1=(v.y-mean)*rstd*gv.y+bv.y;
    float o2=(v.z-mean)*rstd*gv.z+bv.z, o3=(v.w-mean)*rstd*gv.w+bv.w;
    u32 h0,l0,h1,l1;
    split2(o0,o1,h0,l0); split2(o2,o3,h1,l1);
    ((uint2*)(oh + (size_t)row*D_))[t] = make_uint2(h0,h1);
    ((uint2*)(ol + (size_t)row*D_))[t] = make_uint2(l0,l1);
}

// ---------------- tensor-core GEMM, 4-stage cp.async pipeline ----------------
// dyn smem layout (bf16 elems):
//   sAh: 4 stages x 128x24 = 12288   (stage stride 3072 elems / 6144 B)
//   sAl: +12288  (byte offset +24576)
//   sBh: 4 stages x 16x136 = 8704    (stage stride 2176 elems / 4352 B)
//   sBl: +8704   (byte offset +17408)
#define GEMM_SMEM 83968
template<int EPI>
__global__ void __launch_bounds__(256) k_gemm(
    int N, int K,
    const bf16* __restrict__ Ah, const bf16* __restrict__ Al,
    const bf16* Bh0, const bf16* Bl0, const bf16* Bh1, const bf16* Bl1,
    const bf16* Bh2, const bf16* Bl2,
    const float* bias0, const float* bias1, const float* bias2,
    const float* __restrict__ res,
    void* C0a, void* C0b, void* C1a, void* C1b, void* C2a, void* C2b)
{
    extern __shared__ __align__(16) bf16 sm[];
    bf16* sAh = sm;
    bf16* sBh = sm + 24576;

    const int z = blockIdx.z;
    const bf16* Bh = (z==0)?Bh0:((z==1)?Bh1:Bh2);
    const bf16* Bl = (z==0)?Bl0:((z==1)?Bl1:Bl2);
    const float* bias = (z==0)?bias0:((z==1)?bias1:bias2);
    void* Ca = (z==0)?C0a:((z==1)?C1a:C2a);
    void* Cb = (z==0)?C0b:((z==1)?C1b:C2b);

    const int tid = threadIdx.x;
    const int lane = tid & 31, wid = tid>>5;
    const int m_base = (wid&1)*64, n_base = (wid>>1)*32;
    const int bm = blockIdx.y*BM, bn = blockIdx.x*BN;

    const int ar = tid>>1, ac = (tid&1)*8;
    const int br = tid>>4, bc = (tid&15)*8;
    const bf16* Agh = Ah + (size_t)(bm+ar)*K + ac;
    const bf16* Agl = Al + (size_t)(bm+ar)*K + ac;
    const bf16* Bgh = Bh + (size_t)br*N + bn + bc;
    const bf16* Bgl = Bl + (size_t)br*N + bn + bc;

    const u32 aWr = cvt_smem(sAh + ar*24 + ac);
    const u32 bWr = cvt_smem(sBh + br*136 + bc);

    const int q2 = lane>>3;
    const u32 aRd = cvt_smem(sAh + (m_base + (lane&15))*24 + (lane>>4)*8);
    const u32 bRd = cvt_smem(sBh + ((q2&1)*8 + (lane&7))*136 + n_base + (q2>>1)*8);

    float acc[4][4][4];
    #pragma unroll
    for (int i=0;i<4;i++)
        #pragma unroll
        for (int j=0;j<4;j++)
            #pragma unroll
            for (int r=0;r<4;r++) acc[i][j][r]=0.f;

    auto issue = [&](int kt, int st){
        u32 a = aWr + st*6144;
        cp16(a,         Agh + kt*16);
        cp16(a + 24576, Agl + kt*16);
        u32 b = bWr + st*4352;
        cp16(b,         Bgh + (size_t)kt*16*N);
        cp16(b + 17408, Bgl + (size_t)kt*16*N);
        cp_commit();
    };

    const int nk = K/16;   // >= 64
    issue(0,0); issue(1,1); issue(2,2);

    for (int kt=0; kt<nk; kt++){
        if (kt+2 < nk)      cp_wait<2>();
        else if (kt+1 < nk) cp_wait<1>();
        else                cp_wait<0>();
        __syncthreads();
        const int st = kt & 3;

        u32 fah[4][4], fal[4][4];
        const u32 ab = aRd + st*6144;
        #pragma unroll
        for (int mi=0;mi<4;mi++){
            ldsm4(fah[mi][0],fah[mi][1],fah[mi][2],fah[mi][3], ab + mi*768);
            ldsm4(fal[mi][0],fal[mi][1],fal[mi][2],fal[mi][3], ab + mi*768 + 24576);
        }
        u32 fbh[4][2], fbl[4][2];
        const u32 bb2 = bRd + st*4352;
        #pragma unroll
        for (int p=0;p<2;p++){
            u32 r0,r1,r2,r3;
            ldsm4t(r0,r1,r2,r3, bb2 + p*32);
            fbh[2*p][0]=r0; fbh[2*p][1]=r1; fbh[2*p+1][0]=r2; fbh[2*p+1][1]=r3;
            ldsm4t(r0,r1,r2,r3, bb2 + p*32 + 17408);
            fbl[2*p][0]=r0; fbl[2*p][1]=r1; fbl[2*p+1][0]=r2; fbl[2*p+1][1]=r3;
        }
        if (kt+3 < nk) issue(kt+3, (kt+3)&3);

        #pragma unroll
        for (int mi=0;mi<4;mi++)
            #pragma unroll
            for (int nj=0;nj<4;nj++){
                mma16816(acc[mi][nj], fah[mi], fbh[nj]);
                mma16816(acc[mi][nj], fah[mi], fbl[nj]);
                mma16816(acc[mi][nj], fal[mi], fbh[nj]);
            }
    }

    // ---- epilogue ----
    #pragma unroll
    for (int mi=0; mi<4; mi++){
        #pragma unroll
        for (int r=0; r<2; r++){
            int gm = bm + m_base + mi*16 + (lane>>2) + r*8;
            #pragma unroll
            for (int nj=0; nj<4; nj++){
                int gn = bn + n_base + nj*8 + (lane&3)*2;
                float v0 = acc[mi][nj][r*2+0];
                float v1 = acc[mi][nj][r*2+1];
                if (EPI != 3){ v0 += bias[gn]; v1 += bias[gn+1]; }
                if (EPI == 1){ v0 = geluf(v0); v1 = geluf(v1); }
                size_t base = (size_t)gm*N + gn;
                if (EPI == 2){
                    float2 rr = *(const float2*)(res + base);
                    *(float2*)((float*)Ca + base) = make_float2(v0+rr.x, v1+rr.y);
                } else if (EPI == 3){
                    *(float2*)((float*)Ca + base) = make_float2(v0, v1);
                } else {
                    u32 h_,l_;
                    split2(v0, v1, h_, l_);
                    *(u32*)((bf16*)Ca + base) = h_;
                    *(u32*)((bf16*)Cb + base) = l_;
                }
            }
        }
    }
}

// ---------------- tensor-core flash attention, 2-stage K/V pipeline ----------------
// dyn smem (bf16 elems, 64x72 = 4608 per region):
//   sQh @0, sQl @4608, sKh 2 stages @9216, sKl @18432, sVh @27648, sVl @36864
// byte offsets from sKh: Kl +18432, Vh +36864, Vl +55296; stage stride 9216 B
#define ATTN_SMEM 92160
__global__ void __launch_bounds__(128) k_attn(
    const bf16* __restrict__ Qh, const bf16* __restrict__ Ql,
    const bf16* __restrict__ Kh, const bf16* __restrict__ Kl,
    const bf16* __restrict__ Vh, const bf16* __restrict__ Vl,
    bf16* __restrict__ Oh, bf16* __restrict__ Ol)
{
    extern __shared__ __align__(16) bf16 sm[];
    bf16* sQh = sm;
    bf16* sKh = sm + 9216;
    bf16* sVh = sm + 27648;

    const int tid = threadIdx.x;
    const int lane = tid & 31;
    const int w = tid >> 5;
    const int qt = blockIdx.x;
    const int bh = blockIdx.y;
    const int bb = bh >> 4;
    const int hh = bh & 15;
    const int g  = lane >> 2;
    const int n2 = (lane & 3) * 2;
    const int q2 = lane >> 3;

    const size_t qrow0 = (size_t)bb*S_ + qt*64;
    const int col0 = hh*DK_;

    // ---- load Q tile ----
    #pragma unroll
    for (int i=0;i<4;i++){
        int cid = tid + i*128;
        int r = cid >> 3, ch = (cid & 7)*8;
        size_t go = (qrow0 + r)*D_ + col0 + ch;
        u32 s = cvt_smem(sQh + r*72 + ch);
        cp16(s, Qh + go);
        cp16(s + 9216, Ql + go);
    }
    cp_commit();

    auto issueKV = [&](int kt, int st){
        #pragma unroll
        for (int i=0;i<4;i++){
            int cid = tid + i*128;
            int r = cid >> 3, ch = (cid & 7)*8;
            size_t go = ((size_t)bb*S_ + kt*64 + r)*D_ + col0 + ch;
            u32 s = cvt_smem(sKh + st*4608 + r*72 + ch);
            cp16(s,         Kh + go);
            cp16(s + 18432, Kl + go);
            cp16(s + 36864, Vh + go);
            cp16(s + 55296, Vl + go);
        }
        cp_commit();
    };

    issueKV(0, 0);

    // ---- Q fragments (wait for Q group: 1 group (KV0) may still be in flight) ----
    cp_wait<1>();
    __syncthreads();
    u32 qfh[4][4], qfl[4][4];
    {
        u32 a = cvt_smem(sQh + (w*16 + (lane&15))*72 + (lane>>4)*8);
        #pragma unroll
        for (int ks=0; ks<4; ks++){
            ldsm4(qfh[ks][0],qfh[ks][1],qfh[ks][2],qfh[ks][3], a + ks*32);
            ldsm4(qfl[ks][0],qfl[ks][1],qfl[ks][2],qfl[ks][3], a + ks*32 + 9216);
        }
    }

    float m[2]    = {-1e30f, -1e30f};
    float lsum[2] = {0.f, 0.f};
    float oa[8][4];
    #pragma unroll
    for (int i=0;i<8;i++)
        #pragma unroll
        for (int j=0;j<4;j++) oa[i][j]=0.f;

    for (int kt=0; kt<=qt; kt++){
        const int st = kt & 1;
        if (kt+1 <= qt){ issueKV(kt+1, st^1); cp_wait<1>(); }
        else           { cp_wait<0>(); }
        __syncthreads();

        // ---- scores: S = Q K^T (3-pass split) ----
        float s[8][4];
        #pragma unroll
        for (int nt=0;nt<8;nt++)
            #pragma unroll
            for (int j=0;j<4;j++) s[nt][j]=0.f;

        #pragma unroll
        for (int ks=0; ks<4; ks++){
            u32 kbh[8][2], kbl[8][2];
            #pragma unroll
            for (int pr=0; pr<4; pr++){
                u32 r0,r1,r2,r3;
                u32 a = cvt_smem(sKh + st*4608 + (pr*16 + (q2&1)*8 + (lane&7))*72 + (q2>>1)*8) + ks*32;
                ldsm4(r0,r1,r2,r3, a);
                kbh[2*pr][0]=r0; kbh[2*pr][1]=r2; kbh[2*pr+1][0]=r1; kbh[2*pr+1][1]=r3;
                ldsm4(r0,r1,r2,r3, a + 18432);
                kbl[2*pr][0]=r0; kbl[2*pr][1]=r2; kbl[2*pr+1][0]=r1; kbl[2*pr+1][1]=r3;
            }
            #pragma unroll
            for (int nt=0; nt<8; nt++){
                mma16816(s[nt], qfh[ks], kbh[nt]);
                mma16816(s[nt], qfh[ks], kbl[nt]);
                mma16816(s[nt], qfl[ks], kbh[nt]);
            }
        }

        // ---- scale + causal mask ----
        const bool diag = (kt == qt);
        #pragma unroll
        for (int nt=0;nt<8;nt++)
            #pragma unroll
            for (int j=0;j<4;j++){
                float v = s[nt][j]*0.125f;
                if (diag){
                    int col  = nt*8 + n2 + (j&1);
                    int rowl = w*16 + g + (j>>1)*8;
                    if (col > rowl) v = -1e30f;
                }
                s[nt][j] = v;
            }

        // ---- online softmax ----
        float mx0=-1e30f, mx1=-1e30f;
        #pragma unroll
        for (int nt=0;nt<8;nt++){
            mx0 = fmaxf(mx0, fmaxf(s[nt][0], s[nt][1]));
            mx1 = fmaxf(mx1, fmaxf(s[nt][2], s[nt][3]));
        }
        mx0 = fmaxf(mx0, __shfl_xor_sync(0xffffffffu, mx0, 1));
        mx0 = fmaxf(mx0, __shfl_xor_sync(0xffffffffu, mx0, 2));
        mx1 = fmaxf(mx1, __shfl_xor_sync(0xffffffffu, mx1, 1));
        mx1 = fmaxf(mx1, __shfl_xor_sync(0xffffffffu, mx1, 2));
        float mn0 = fmaxf(m[0], mx0), mn1 = fmaxf(m[1], mx1);
        float c0 = __expf(m[0]-mn0), c1 = __expf(m[1]-mn1);
        float ps0=0.f, ps1=0.f;
        #pragma unroll
        for (int nt=0;nt<8;nt++){
            s[nt][0] = __expf(s[nt][0]-mn0); ps0 += s[nt][0];
            s[nt][1] = __expf(s[nt][1]-mn0); ps0 += s[nt][1];
            s[nt][2] = __expf(s[nt][2]-mn1); ps1 += s[nt][2];
            s[nt][3] = __expf(s[nt][3]-mn1); ps1 += s[nt][3];
        }
        ps0 += __shfl_xor_sync(0xffffffffu, ps0, 1);
        ps0 += __shfl_xor_sync(0xffffffffu, ps0, 2);
        ps1 += __shfl_xor_sync(0xffffffffu, ps1, 1);
        ps1 += __shfl_xor_sync(0xffffffffu, ps1, 2);
        lsum[0] = lsum[0]*c0 + ps0;
        lsum[1] = lsum[1]*c1 + ps1;
        m[0] = mn0; m[1] = mn1;
        #pragma unroll
        for (int dt=0;dt<8;dt++){
            oa[dt][0]*=c0; oa[dt][1]*=c0; oa[dt][2]*=c1; oa[dt][3]*=c1;
        }

        // ---- O += P V (3-pass split) ----
        #pragma unroll
        for (int ks=0; ks<4; ks++){
            u32 pfh[4], pfl[4];
            split2(s[2*ks  ][0], s[2*ks  ][1], pfh[0], pfl[0]);
            split2(s[2*ks  ][2], s[2*ks  ][3], pfh[1], pfl[1]);
            split2(s[2*ks+1][0], s[2*ks+1][1], pfh[2], pfl[2]);
            split2(s[2*ks+1][2], s[2*ks+1][3], pfh[3], pfl[3]);

            u32 vbh[8][2], vbl[8][2];
            #pragma unroll
            for (int dp=0; dp<4; dp++){
                u32 r0,r1,r2,r3;
                u32 a = cvt_smem(sVh + st*4608 + (ks*16 + (q2&1)*8 + (lane&7))*72 + dp*16 + (q2>>1)*8);
                ldsm4t(r0,r1,r2,r3, a);
                vbh[2*dp][0]=r0; vbh[2*dp][1]=r1; vbh[2*dp+1][0]=r2; vbh[2*dp+1][1]=r3;
                ldsm4t(r0,r1,r2,r3, a + 18432);
                vbl[2*dp][0]=r0; vbl[2*dp][1]=r1; vbl[2*dp+1][0]=r2; vbl[2*dp+1][1]=r3;
            }
            #pragma unroll
            for (int dt=0; dt<8; dt++){
                mma16816(oa[dt], pfh, vbh[dt]);
                mma16816(oa[dt], pfh, vbl[dt]);
                mma16816(oa[dt], pfl, vbh[dt]);
            }
        }
        __syncthreads();   // all reads of stage st done before overwrite next iter
    }

    // ---- epilogue ----
    float inv0 = 1.0f/lsum[0], inv1 = 1.0f/lsum[1];
    size_t r0 = qrow0 + w*16 + g;
    size_t r1 = r0 + 8;
    #pragma unroll
    for (int dt=0; dt<8; dt++){
        int col = col0 + dt*8 + n2;
        u32 h_,l_;
        split2(oa[dt][0]*inv0, oa[dt][1]*inv0, h_, l_);
        *(u32*)(Oh + r0*D_ + col) = h_;
        *(u32*)(Ol + r0*D_ + col) = l_;
        split2(oa[dt][2]*inv1, oa[dt][3]*inv1, h_, l_);
        *(u32*)(Oh + r1*D_ + col) = h_;
        *(u32*)(Ol + r1*D_ + col) = l_;
    }
}

// ---------------- orchestration ----------------
extern "C" void kernel_launch(void* const* d_in, const int* in_sizes, int n_in,
                              void* d_out, int out_size)
{
    (void)in_sizes; (void)n_in; (void)out_size;
    const int*   ids  = (const int*)  d_in[0];
    const float* emb  = (const float*)d_in[1];
    const float* wq   = (const float*)d_in[2];
    const float* bq   = (const float*)d_in[3];
    const float* wk   = (const float*)d_in[4];
    const float* bk   = (const float*)d_in[5];
    const float* wv   = (const float*)d_in[6];
    const float* bv   = (const float*)d_in[7];
    const float* wo   = (const float*)d_in[8];
    const float* bo   = (const float*)d_in[9];
    const float* ln1g = (const float*)d_in[10];
    const float* ln1b = (const float*)d_in[11];
    const float* ln2g = (const float*)d_in[12];
    const float* ln2b = (const float*)d_in[13];
    const float* w1   = (const float*)d_in[14];
    const float* b1   = (const float*)d_in[15];
    const float* w2   = (const float*)d_in[16];
    const float* b2   = (const float*)d_in[17];
    const float* lnfg = (const float*)d_in[18];
    const float* lnfb = (const float*)d_in[19];
    float* out = (float*)d_out;

    cudaFuncSetAttribute((const void*)k_gemm<0>, cudaFuncAttributeMaxDynamicSharedMemorySize, GEMM_SMEM);
    cudaFuncSetAttribute((const void*)k_gemm<1>, cudaFuncAttributeMaxDynamicSharedMemorySize, GEMM_SMEM);
    cudaFuncSetAttribute((const void*)k_gemm<2>, cudaFuncAttributeMaxDynamicSharedMemorySize, GEMM_SMEM);
    cudaFuncSetAttribute((const void*)k_gemm<3>, cudaFuncAttributeMaxDynamicSharedMemorySize, GEMM_SMEM);
    cudaFuncSetAttribute((const void*)k_attn,    cudaFuncAttributeMaxDynamicSharedMemorySize, ATTN_SMEM);

    float* px;  cudaGetSymbolAddress((void**)&px,  g_x);
    bf16 *hh,*hl,*qh,*ql,*kh,*kl,*vh,*vl,*ah,*al,*fh,*fl;
    cudaGetSymbolAddress((void**)&hh, g_h_h); cudaGetSymbolAddress((void**)&hl, g_h_l);
    cudaGetSymbolAddress((void**)&qh, g_q_h); cudaGetSymbolAddress((void**)&ql, g_q_l);
    cudaGetSymbolAddress((void**)&kh, g_k_h); cudaGetSymbolAddress((void**)&kl, g_k_l);
    cudaGetSymbolAddress((void**)&vh, g_v_h); cudaGetSymbolAddress((void**)&vl, g_v_l);
    cudaGetSymbolAddress((void**)&ah, g_a_h); cudaGetSymbolAddress((void**)&al, g_a_l);
    cudaGetSymbolAddress((void**)&fh, g_f_h); cudaGetSymbolAddress((void**)&fl, g_f_l);
    bf16 *wqh,*wql,*wkh,*wkl,*wvh,*wvl,*woh,*wol,*w1h,*w1l,*w2h,*w2l,*eth,*etl;
    cudaGetSymbolAddress((void**)&wqh, g_wq_h); cudaGetSymbolAddress((void**)&wql, g_wq_l);
    cudaGetSymbolAddress((void**)&wkh, g_wk_h); cudaGetSymbolAddress((void**)&wkl, g_wk_l);
    cudaGetSymbolAddress((void**)&wvh, g_wv_h); cudaGetSymbolAddress((void**)&wvl, g_wv_l);
    cudaGetSymbolAddress((void**)&woh, g_wo_h); cudaGetSymbolAddress((void**)&wol, g_wo_l);
    cudaGetSymbolAddress((void**)&w1h, g_w1_h); cudaGetSymbolAddress((void**)&w1l, g_w1_l);
    cudaGetSymbolAddress((void**)&w2h, g_w2_h); cudaGetSymbolAddress((void**)&w2l, g_w2_l);
    cudaGetSymbolAddress((void**)&eth, g_et_h); cudaGetSymbolAddress((void**)&etl, g_et_l);

    // ---- weight conversion ----
    {
        int nA = L_*D_*D_/4;
        k_cvt<<<(nA+255)/256,256>>>((const float4*)wq, (uint2*)wqh, (uint2*)wql, nA);
        k_cvt<<<(nA+255)/256,256>>>((const float4*)wk, (uint2*)wkh, (uint2*)wkl, nA);
        k_cvt<<<(nA+255)/256,256>>>((const float4*)wv, (uint2*)wvh, (uint2*)wvl, nA);
        k_cvt<<<(nA+255)/256,256>>>((const float4*)wo, (uint2*)woh, (uint2*)wol, nA);
        int nF = L_*D_*F_/4;
        k_cvt<<<(nF+255)/256,256>>>((const float4*)w1, (uint2*)w1h, (uint2*)w1l, nF);
        k_cvt<<<(nF+255)/256,256>>>((const float4*)w2, (uint2*)w2h, (uint2*)w2l, nF);
        k_cvt_t<<<dim3(V_/32, D_/32), dim3(32,8)>>>(emb, eth, etl);
    }

    k_embed<<<(M_*D_+255)/256, 256>>>(ids, emb, px);

    for (int l=0; l<L_; l++){
        size_t odd = (size_t)l*D_*D_;
        size_t off = (size_t)l*D_*F_;
        k_ln<<<M_,256>>>(px, ln1g+l*D_, ln1b+l*D_, hh, hl);
        k_gemm<0><<<dim3(D_/BN, M_/BM, 3),256,GEMM_SMEM>>>(D_, D_, hh, hl,
            wqh+odd, wql+odd, wkh+odd, wkl+odd, wvh+odd, wvl+odd,
            bq+l*D_, bk+l*D_, bv+l*D_,
            nullptr, qh, ql, kh, kl, vh, vl);
        k_attn<<<dim3(S_/64, B_*H_),128,ATTN_SMEM>>>(qh, ql, kh, kl, vh, vl, ah, al);
        k_gemm<2><<<dim3(D_/BN, M_/BM, 1),256,GEMM_SMEM>>>(D_, D_, ah, al,
            woh+odd, wol+odd, woh+odd, wol+odd, woh+odd, wol+odd,
            bo+l*D_, bo+l*D_, bo+l*D_,
            px, px, nullptr, px, nullptr, px, nullptr);
        k_ln<<<M_,256>>>(px, ln2g+l*D_, ln2b+l*D_, hh, hl);
        k_gemm<1><<<dim3(F_/BN, M_/BM, 1),256,GEMM_SMEM>>>(F_, D_, hh, hl,
            w1h+off, w1l+off, w1h+off, w1l+off, w1h+off, w1l+off,
            b1+l*F_, b1+l*F_, b1+l*F_,
            nullptr, fh, fl, fh, fl, fh, fl);
        k_gemm<2><<<dim3(D_/BN, M_/BM, 1),256,GEMM_SMEM>>>(D_, F_, fh, fl,
            w2h+off, w2l+off, w2h+off, w2l+off, w2h+off, w2l+off,
            b2+l*D_, b2+l*D_, b2+l*D_,
            px, px, nullptr, px, nullptr, px, nullptr);
    }
    k_ln<<<M_,256>>>(px, lnfg, lnfb, hh, hl);
    k_gemm<3><<<dim3(V_/BN, M_/BM, 1),256,GEMM_SMEM>>>(V_, D_, hh, hl,
        eth, etl, eth, etl, eth, etl,
        nullptr, nullptr, nullptr,
        nullptr, out, nullptr, out, nullptr, out, nullptr);
}

// round 9
// speedup vs baseline: 4.4881x; 1.0027x over previous
#include <cuda_runtime.h>
#include <cuda_bf16.h>
#include <cstdint>
#include <math.h>

typedef unsigned int u32;
typedef __nv_bfloat16 bf16;

#define B_  2
#define S_  1024
#define D_  1024
#define H_  16
#define F_  4096
#define L_  6
#define V_  32000
#define DK_ 64
#define M_  (B_*S_)

#define BM 128
#define BN 128

// ---------------- persistent scratch ----------------
__device__ __align__(16) float g_x [M_*D_];
__device__ __align__(16) bf16 g_h_h[M_*D_],  g_h_l[M_*D_];
__device__ __align__(16) bf16 g_q_h[M_*D_],  g_q_l[M_*D_];
__device__ __align__(16) bf16 g_k_h[M_*D_],  g_k_l[M_*D_];
__device__ __align__(16) bf16 g_v_h[M_*D_],  g_v_l[M_*D_];
__device__ __align__(16) bf16 g_a_h[M_*D_],  g_a_l[M_*D_];
__device__ __align__(16) bf16 g_f_h[M_*F_],  g_f_l[M_*F_];
__device__ __align__(16) bf16 g_wq_h[L_*D_*D_], g_wq_l[L_*D_*D_];
__device__ __align__(16) bf16 g_wk_h[L_*D_*D_], g_wk_l[L_*D_*D_];
__device__ __align__(16) bf16 g_wv_h[L_*D_*D_], g_wv_l[L_*D_*D_];
__device__ __align__(16) bf16 g_wo_h[L_*D_*D_], g_wo_l[L_*D_*D_];
__device__ __align__(16) bf16 g_w1_h[L_*D_*F_], g_w1_l[L_*D_*F_];
__device__ __align__(16) bf16 g_w2_h[L_*F_*D_], g_w2_l[L_*F_*D_];
__device__ __align__(16) bf16 g_et_h[(size_t)D_*V_], g_et_l[(size_t)D_*V_];

// ---------------- helpers ----------------
__device__ __forceinline__ u32 cvt_smem(const void* p){
    return (u32)__cvta_generic_to_shared(p);
}
__device__ __forceinline__ void cp16(u32 s, const void* g){
    asm volatile("cp.async.cg.shared.global [%0],[%1],16;\n"::"r"(s),"l"(g));
}
__device__ __forceinline__ void cp_commit(){ asm volatile("cp.async.commit_group;\n"::); }
template<int NN> __device__ __forceinline__ void cp_wait(){
    asm volatile("cp.async.wait_group %0;\n"::"n"(NN));
}
__device__ __forceinline__ void ldsm4(u32 &r0,u32 &r1,u32 &r2,u32 &r3, u32 a){
    asm volatile("ldmatrix.sync.aligned.m8n8.x4.shared.b16 {%0,%1,%2,%3},[%4];\n"
        : "=r"(r0),"=r"(r1),"=r"(r2),"=r"(r3) : "r"(a));
}
__device__ __forceinline__ void ldsm4t(u32 &r0,u32 &r1,u32 &r2,u32 &r3, u32 a){
    asm volatile("ldmatrix.sync.aligned.m8n8.x4.trans.shared.b16 {%0,%1,%2,%3},[%4];\n"
        : "=r"(r0),"=r"(r1),"=r"(r2),"=r"(r3) : "r"(a));
}
__device__ __forceinline__ void mma16816(float* c, const u32* a, const u32* b){
    asm volatile("mma.sync.aligned.m16n8k16.row.col.f32.bf16.bf16.f32 "
        "{%0,%1,%2,%3},{%4,%5,%6,%7},{%8,%9},{%0,%1,%2,%3};\n"
        : "+f"(c[0]),"+f"(c[1]),"+f"(c[2]),"+f"(c[3])
        : "r"(a[0]),"r"(a[1]),"r"(a[2]),"r"(a[3]),"r"(b[0]),"r"(b[1]));
}
__device__ __forceinline__ u32 pack2(bf16 h0, bf16 h1){
    unsigned short u0 = *reinterpret_cast<unsigned short*>(&h0);
    unsigned short u1 = *reinterpret_cast<unsigned short*>(&h1);
    return (u32)u0 | ((u32)u1 << 16);
}
__device__ __forceinline__ void split2(float x0, float x1, u32 &hi, u32 &lo){
    bf16 h0 = __float2bfloat16_rn(x0);
    bf16 h1 = __float2bfloat16_rn(x1);
    float f0 = __bfloat162float(h0), f1 = __bfloat162float(h1);
    hi = pack2(h0, h1);
    lo = pack2(__float2bfloat16_rn(x0 - f0), __float2bfloat16_rn(x1 - f1));
}
__device__ __forceinline__ float geluf(float x){
    return 0.5f*x*(1.0f + erff(x*0.7071067811865476f));
}

// ---------------- conversion kernels ----------------
__global__ void k_cvt(const float4* __restrict__ src, uint2* __restrict__ dh,
                      uint2* __restrict__ dl, int n4)
{
    int i = blockIdx.x*256 + threadIdx.x;
    if (i >= n4) return;
    float4 v = src[i];
    u32 h0,l0,h1,l1;
    split2(v.x,v.y,h0,l0); split2(v.z,v.w,h1,l1);
    dh[i] = make_uint2(h0,h1);
    dl[i] = make_uint2(l0,l1);
}

__global__ void k_cvt_t(const float* __restrict__ src, bf16* __restrict__ dh,
                        bf16* __restrict__ dl)
{
    __shared__ float t[32][33];
    int v0 = blockIdx.x*32, d0 = blockIdx.y*32;
    int tx = threadIdx.x, ty = threadIdx.y;   // 32 x 8
    #pragma unroll
    for (int i=0;i<4;i++)
        t[ty+8*i][tx] = src[(size_t)(v0+ty+8*i)*D_ + d0 + tx];
    __syncthreads();
    #pragma unroll
    for (int i=0;i<4;i++){
        int dy = ty + 8*i;
        float val = t[tx][dy];
        bf16 hh = __float2bfloat16_rn(val);
        size_t o = (size_t)(d0+dy)*V_ + v0 + tx;
        dh[o] = hh;
        dl[o] = __float2bfloat16_rn(val - __bfloat162float(hh));
    }
}

// ---------------- embedding + sinusoidal PE ----------------
__global__ void k_embed(const int* __restrict__ ids, const float* __restrict__ emb,
                        float* __restrict__ x)
{
    int idx = blockIdx.x * 256 + threadIdx.x;
    if (idx >= M_*D_) return;
    int d  = idx & (D_-1);
    int ms = idx >> 10;
    int s  = ms & (S_-1);
    int tok = ids[ms];
    int i2 = d & ~1;
    float freq = expf((float)i2 * (-9.210340371976184f / (float)D_));
    float ang  = (float)s * freq;
    float pe   = (d & 1) ? cosf(ang) : sinf(ang);
    x[idx] = emb[tok*D_ + d] * 32.0f + pe;
}

// ---------------- layernorm ----------------
__global__ void __launch_bounds__(256) k_ln(const float* __restrict__ x,
                                            const float* __restrict__ g,
                                            const float* __restrict__ b,
                                            bf16* __restrict__ oh,
                                            bf16* __restrict__ ol)
{
    int row = blockIdx.x;
    int t = threadIdx.x;
    float4 v = ((const float4*)(x + (size_t)row*D_))[t];
    float s  = v.x+v.y+v.z+v.w;
    float ss = v.x*v.x+v.y*v.y+v.z*v.z+v.w*v.w;
    #pragma unroll
    for (int o=16;o>0;o>>=1){
        s  += __shfl_xor_sync(0xffffffffu, s,  o);
        ss += __shfl_xor_sync(0xffffffffu, ss, o);
    }
    __shared__ float rs[8], rss[8];
    if ((t&31)==0){ rs[t>>5]=s; rss[t>>5]=ss; }
    __syncthreads();
    float tot=0.f, tot2=0.f;
    #pragma unroll
    for (int i=0;i<8;i++){ tot += rs[i]; tot2 += rss[i]; }
    float mean = tot * (1.0f/D_);
    float var  = tot2 * (1.0f/D_) - mean*mean;
    float rstd = rsqrtf(var + 1e-5f);
    float4 gv = ((const float4*)g)[t];
    float4 bv = ((const float4*)b)[t];
    float o0=(v.x-mean)*rstd*gv.x+bv.x, o1=(v.y-mean)*rstd*gv.y+bv.y;
    float o2=(v.z-mean)*rstd*gv.z+bv.z, o3=(v.w-mean)*rstd*gv.w+bv.w;
    u32 h0,l0,h1,l1;
    split2(o0,o1,h0,l0); split2(o2,o3,h1,l1);
    ((uint2*)(oh + (size_t)row*D_))[t] = make_uint2(h0,h1);
    ((uint2*)(ol + (size_t)row*D_))[t] = make_uint2(l0,l1);
}

// ---------------- tensor-core GEMM, 4-stage cp.async pipeline ----------------
// dyn smem layout (bf16 elems):
//   sAh: 4 stages x 128x24 = 12288   (stage stride 3072 elems / 6144 B)
//   sAl: +12288  (byte offset +24576)
//   sBh: 4 stages x 16x136 = 8704    (stage stride 2176 elems / 4352 B)
//   sBl: +8704   (byte offset +17408)
#define GEMM_SMEM 83968
template<int EPI>
__global__ void __launch_bounds__(256) k_gemm(
    int N, int K,
    const bf16* __restrict__ Ah, const bf16* __restrict__ Al,
    const bf16* Bh0, const bf16* Bl0, const bf16* Bh1, const bf16* Bl1,
    const bf16* Bh2, const bf16* Bl2,
    const float* bias0, const float* bias1, const float* bias2,
    const float* __restrict__ res,
    void* C0a, void* C0b, void* C1a, void* C1b, void* C2a, void* C2b)
{
    extern __shared__ __align__(16) bf16 sm[];
    bf16* sAh = sm;
    bf16* sBh = sm + 24576;

    const int z = blockIdx.z;
    const bf16* Bh = (z==0)?Bh0:((z==1)?Bh1:Bh2);
    const bf16* Bl = (z==0)?Bl0:((z==1)?Bl1:Bl2);
    const float* bias = (z==0)?bias0:((z==1)?bias1:bias2);
    void* Ca = (z==0)?C0a:((z==1)?C1a:C2a);
    void* Cb = (z==0)?C0b:((z==1)?C1b:C2b);

    const int tid = threadIdx.x;
    const int lane = tid & 31, wid = tid>>5;
    const int m_base = (wid&1)*64, n_base = (wid>>1)*32;
    const int bm = blockIdx.y*BM, bn = blockIdx.x*BN;

    const int ar = tid>>1, ac = (tid&1)*8;
    const int br = tid>>4, bc = (tid&15)*8;
    const bf16* Agh = Ah + (size_t)(bm+ar)*K + ac;
    const bf16* Agl = Al + (size_t)(bm+ar)*K + ac;
    const bf16* Bgh = Bh + (size_t)br*N + bn + bc;
    const bf16* Bgl = Bl + (size_t)br*N + bn + bc;

    const u32 aWr = cvt_smem(sAh + ar*24 + ac);
    const u32 bWr = cvt_smem(sBh + br*136 + bc);

    const int q2 = lane>>3;
    const u32 aRd = cvt_smem(sAh + (m_base + (lane&15))*24 + (lane>>4)*8);
    const u32 bRd = cvt_smem(sBh + ((q2&1)*8 + (lane&7))*136 + n_base + (q2>>1)*8);

    float acc[4][4][4];
    #pragma unroll
    for (int i=0;i<4;i++)
        #pragma unroll
        for (int j=0;j<4;j++)
            #pragma unroll
            for (int r=0;r<4;r++) acc[i][j][r]=0.f;

    auto issue = [&](int kt, int st){
        u32 a = aWr + st*6144;
        cp16(a,         Agh + kt*16);
        cp16(a + 24576, Agl + kt*16);
        u32 b = bWr + st*4352;
        cp16(b,         Bgh + (size_t)kt*16*N);
        cp16(b + 17408, Bgl + (size_t)kt*16*N);
        cp_commit();
    };

    const int nk = K/16;   // >= 64
    issue(0,0); issue(1,1); issue(2,2);

    for (int kt=0; kt<nk; kt++){
        if (kt+2 < nk)      cp_wait<2>();
        else if (kt+1 < nk) cp_wait<1>();
        else                cp_wait<0>();
        __syncthreads();
        const int st = kt & 3;

        u32 fah[4][4], fal[4][4];
        const u32 ab = aRd + st*6144;
        #pragma unroll
        for (int mi=0;mi<4;mi++){
            ldsm4(fah[mi][0],fah[mi][1],fah[mi][2],fah[mi][3], ab + mi*768);
            ldsm4(fal[mi][0],fal[mi][1],fal[mi][2],fal[mi][3], ab + mi*768 + 24576);
        }
        u32 fbh[4][2], fbl[4][2];
        const u32 bb2 = bRd + st*4352;
        #pragma unroll
        for (int p=0;p<2;p++){
            u32 r0,r1,r2,r3;
            ldsm4t(r0,r1,r2,r3, bb2 + p*32);
            fbh[2*p][0]=r0; fbh[2*p][1]=r1; fbh[2*p+1][0]=r2; fbh[2*p+1][1]=r3;
            ldsm4t(r0,r1,r2,r3, bb2 + p*32 + 17408);
            fbl[2*p][0]=r0; fbl[2*p][1]=r1; fbl[2*p+1][0]=r2; fbl[2*p+1][1]=r3;
        }
        if (kt+3 < nk) issue(kt+3, (kt+3)&3);

        #pragma unroll
        for (int mi=0;mi<4;mi++)
            #pragma unroll
            for (int nj=0;nj<4;nj++){
                mma16816(acc[mi][nj], fah[mi], fbh[nj]);
                mma16816(acc[mi][nj], fah[mi], fbl[nj]);
                mma16816(acc[mi][nj], fal[mi], fbh[nj]);
            }
    }

    // ---- epilogue ----
    #pragma unroll
    for (int mi=0; mi<4; mi++){
        #pragma unroll
        for (int r=0; r<2; r++){
            int gm = bm + m_base + mi*16 + (lane>>2) + r*8;
            #pragma unroll
            for (int nj=0; nj<4; nj++){
                int gn = bn + n_base + nj*8 + (lane&3)*2;
                float v0 = acc[mi][nj][r*2+0];
                float v1 = acc[mi][nj][r*2+1];
                if (EPI != 3){ v0 += bias[gn]; v1 += bias[gn+1]; }
                if (EPI == 1){ v0 = geluf(v0); v1 = geluf(v1); }
                size_t base = (size_t)gm*N + gn;
                if (EPI == 2){
                    float2 rr = *(const float2*)(res + base);
                    *(float2*)((float*)Ca + base) = make_float2(v0+rr.x, v1+rr.y);
                } else if (EPI == 3){
                    *(float2*)((float*)Ca + base) = make_float2(v0, v1);
                } else {
                    u32 h_,l_;
                    split2(v0, v1, h_, l_);
                    *(u32*)((bf16*)Ca + base) = h_;
                    *(u32*)((bf16*)Cb + base) = l_;
                }
            }
        }
    }
}

// ---------------- tensor-core flash attention, 2-stage K/V pipeline ----------------
// dyn smem (bf16 elems, 64x72 = 4608 per region):
//   sQh @0, sQl @4608, sKh 2 stages @9216, sKl @18432, sVh @27648, sVl @36864
// byte offsets from sKh: Kl +18432, Vh +36864, Vl +55296; stage stride 9216 B
#define ATTN_SMEM 92160
__global__ void __launch_bounds__(128) k_attn(
    const bf16* __restrict__ Qh, const bf16* __restrict__ Ql,
    const bf16* __restrict__ Kh, const bf16* __restrict__ Kl,
    const bf16* __restrict__ Vh, const bf16* __restrict__ Vl,
    bf16* __restrict__ Oh, bf16* __restrict__ Ol)
{
    extern __shared__ __align__(16) bf16 sm[];
    bf16* sQh = sm;
    bf16* sKh = sm + 9216;
    bf16* sVh = sm + 27648;

    const int tid = threadIdx.x;
    const int lane = tid & 31;
    const int w = tid >> 5;
    const int qt = blockIdx.x;
    const int bh = blockIdx.y;
    const int bb = bh >> 4;
    const int hh = bh & 15;
    const int g  = lane >> 2;
    const int n2 = (lane & 3) * 2;
    const int q2 = lane >> 3;

    const size_t qrow0 = (size_t)bb*S_ + qt*64;
    const int col0 = hh*DK_;

    // ---- load Q tile ----
    #pragma unroll
    for (int i=0;i<4;i++){
        int cid = tid + i*128;
        int r = cid >> 3, ch = (cid & 7)*8;
        size_t go = (qrow0 + r)*D_ + col0 + ch;
        u32 s = cvt_smem(sQh + r*72 + ch);
        cp16(s, Qh + go);
        cp16(s + 9216, Ql + go);
    }
    cp_commit();

    auto issueKV = [&](int kt, int st){
        #pragma unroll
        for (int i=0;i<4;i++){
            int cid = tid + i*128;
            int r = cid >> 3, ch = (cid & 7)*8;
            size_t go = ((size_t)bb*S_ + kt*64 + r)*D_ + col0 + ch;
            u32 s = cvt_smem(sKh + st*4608 + r*72 + ch);
            cp16(s,         Kh + go);
            cp16(s + 18432, Kl + go);
            cp16(s + 36864, Vh + go);
            cp16(s + 55296, Vl + go);
        }
        cp_commit();
    };

    issueKV(0, 0);

    // ---- Q fragments (wait for Q group: 1 group (KV0) may still be in flight) ----
    cp_wait<1>();
    __syncthreads();
    u32 qfh[4][4], qfl[4][4];
    {
        u32 a = cvt_smem(sQh + (w*16 + (lane&15))*72 + (lane>>4)*8);
        #pragma unroll
        for (int ks=0; ks<4; ks++){
            ldsm4(qfh[ks][0],qfh[ks][1],qfh[ks][2],qfh[ks][3], a + ks*32);
            ldsm4(qfl[ks][0],qfl[ks][1],qfl[ks][2],qfl[ks][3], a + ks*32 + 9216);
        }
    }

    float m[2]    = {-1e30f, -1e30f};
    float lsum[2] = {0.f, 0.f};
    float oa[8][4];
    #pragma unroll
    for (int i=0;i<8;i++)
        #pragma unroll
        for (int j=0;j<4;j++) oa[i][j]=0.f;

    for (int kt=0; kt<=qt; kt++){
        const int st = kt & 1;
        if (kt+1 <= qt){ issueKV(kt+1, st^1); cp_wait<1>(); }
        else           { cp_wait<0>(); }
        __syncthreads();

        // ---- scores: S = Q K^T (3-pass split) ----
        float s[8][4];
        #pragma unroll
        for (int nt=0;nt<8;nt++)
            #pragma unroll
            for (int j=0;j<4;j++) s[nt][j]=0.f;

        #pragma unroll
        for (int ks=0; ks<4; ks++){
            u32 kbh[8][2], kbl[8][2];
            #pragma unroll
            for (int pr=0; pr<4; pr++){
                u32 r0,r1,r2,r3;
                u32 a = cvt_smem(sKh + st*4608 + (pr*16 + (q2&1)*8 + (lane&7))*72 + (q2>>1)*8) + ks*32;
                ldsm4(r0,r1,r2,r3, a);
                kbh[2*pr][0]=r0; kbh[2*pr][1]=r2; kbh[2*pr+1][0]=r1; kbh[2*pr+1][1]=r3;
                ldsm4(r0,r1,r2,r3, a + 18432);
                kbl[2*pr][0]=r0; kbl[2*pr][1]=r2; kbl[2*pr+1][0]=r1; kbl[2*pr+1][1]=r3;
            }
            #pragma unroll
            for (int nt=0; nt<8; nt++){
                mma16816(s[nt], qfh[ks], kbh[nt]);
                mma16816(s[nt], qfh[ks], kbl[nt]);
                mma16816(s[nt], qfl[ks], kbh[nt]);
            }
        }

        // ---- scale + causal mask ----
        const bool diag = (kt == qt);
        #pragma unroll
        for (int nt=0;nt<8;nt++)
            #pragma unroll
            for (int j=0;j<4;j++){
                float v = s[nt][j]*0.125f;
                if (diag){
                    int col  = nt*8 + n2 + (j&1);
                    int rowl = w*16 + g + (j>>1)*8;
                    if (col > rowl) v = -1e30f;
                }
                s[nt][j] = v;
            }

        // ---- online softmax ----
        float mx0=-1e30f, mx1=-1e30f;
        #pragma unroll
        for (int nt=0;nt<8;nt++){
            mx0 = fmaxf(mx0, fmaxf(s[nt][0], s[nt][1]));
            mx1 = fmaxf(mx1, fmaxf(s[nt][2], s[nt][3]));
        }
        mx0 = fmaxf(mx0, __shfl_xor_sync(0xffffffffu, mx0, 1));
        mx0 = fmaxf(mx0, __shfl_xor_sync(0xffffffffu, mx0, 2));
        mx1 = fmaxf(mx1, __shfl_xor_sync(0xffffffffu, mx1, 1));
        mx1 = fmaxf(mx1, __shfl_xor_sync(0xffffffffu, mx1, 2));
        float mn0 = fmaxf(m[0], mx0), mn1 = fmaxf(m[1], mx1);
        float c0 = __expf(m[0]-mn0), c1 = __expf(m[1]-mn1);
        float ps0=0.f, ps1=0.f;
        #pragma unroll
        for (int nt=0;nt<8;nt++){
            s[nt][0] = __expf(s[nt][0]-mn0); ps0 += s[nt][0];
            s[nt][1] = __expf(s[nt][1]-mn0); ps0 += s[nt][1];
            s[nt][2] = __expf(s[nt][2]-mn1); ps1 += s[nt][2];
            s[nt][3] = __expf(s[nt][3]-mn1); ps1 += s[nt][3];
        }
        ps0 += __shfl_xor_sync(0xffffffffu, ps0, 1);
        ps0 += __shfl_xor_sync(0xffffffffu, ps0, 2);
        ps1 += __shfl_xor_sync(0xffffffffu, ps1, 1);
        ps1 += __shfl_xor_sync(0xffffffffu, ps1, 2);
        lsum[0] = lsum[0]*c0 + ps0;
        lsum[1] = lsum[1]*c1 + ps1;
        m[0] = mn0; m[1] = mn1;
        #pragma unroll
        for (int dt=0;dt<8;dt++){
            oa[dt][0]*=c0; oa[dt][1]*=c0; oa[dt][2]*=c1; oa[dt][3]*=c1;
        }

        // ---- O += P V (3-pass split) ----
        #pragma unroll
        for (int ks=0; ks<4; ks++){
            u32 pfh[4], pfl[4];
            split2(s[2*ks  ][0], s[2*ks  ][1], pfh[0], pfl[0]);
            split2(s[2*ks  ][2], s[2*ks  ][3], pfh[1], pfl[1]);
            split2(s[2*ks+1][0], s[2*ks+1][1], pfh[2], pfl[2]);
            split2(s[2*ks+1][2], s[2*ks+1][3], pfh[3], pfl[3]);

            u32 vbh[8][2], vbl[8][2];
            #pragma unroll
            for (int dp=0; dp<4; dp++){
                u32 r0,r1,r2,r3;
                u32 a = cvt_smem(sVh + st*4608 + (ks*16 + (q2&1)*8 + (lane&7))*72 + dp*16 + (q2>>1)*8);
                ldsm4t(r0,r1,r2,r3, a);
                vbh[2*dp][0]=r0; vbh[2*dp][1]=r1; vbh[2*dp+1][0]=r2; vbh[2*dp+1][1]=r3;
                ldsm4t(r0,r1,r2,r3, a + 18432);
                vbl[2*dp][0]=r0; vbl[2*dp][1]=r1; vbl[2*dp+1][0]=r2; vbl[2*dp+1][1]=r3;
            }
            #pragma unroll
            for (int dt=0; dt<8; dt++){
                mma16816(oa[dt], pfh, vbh[dt]);
                mma16816(oa[dt], pfh, vbl[dt]);
                mma16816(oa[dt], pfl, vbh[dt]);
            }
        }
        __syncthreads();   // all reads of stage st done before overwrite next iter
    }

    // ---- epilogue ----
    float inv0 = 1.0f/lsum[0], inv1 = 1.0f/lsum[1];
    size_t r0 = qrow0 + w*16 + g;
    size_t r1 = r0 + 8;
    #pragma unroll
    for (int dt=0; dt<8; dt++){
        int col = col0 + dt*8 + n2;
        u32 h_,l_;
        split2(oa[dt][0]*inv0, oa[dt][1]*inv0, h_, l_);
        *(u32*)(Oh + r0*D_ + col) = h_;
        *(u32*)(Ol + r0*D_ + col) = l_;
        split2(oa[dt][2]*inv1, oa[dt][3]*inv1, h_, l_);
        *(u32*)(Oh + r1*D_ + col) = h_;
        *(u32*)(Ol + r1*D_ + col) = l_;
    }
}

// ---------------- orchestration ----------------
extern "C" void kernel_launch(void* const* d_in, const int* in_sizes, int n_in,
                              void* d_out, int out_size)
{
    (void)in_sizes; (void)n_in; (void)out_size;
    const int*   ids  = (const int*)  d_in[0];
    const float* emb  = (const float*)d_in[1];
    const float* wq   = (const float*)d_in[2];
    const float* bq   = (const float*)d_in[3];
    const float* wk   = (const float*)d_in[4];
    const float* bk   = (const float*)d_in[5];
    const float* wv   = (const float*)d_in[6];
    const float* bv   = (const float*)d_in[7];
    const float* wo   = (const float*)d_in[8];
    const float* bo   = (const float*)d_in[9];
    const float* ln1g = (const float*)d_in[10];
    const float* ln1b = (const float*)d_in[11];
    const float* ln2g = (const float*)d_in[12];
    const float* ln2b = (const float*)d_in[13];
    const float* w1   = (const float*)d_in[14];
    const float* b1   = (const float*)d_in[15];
    const float* w2   = (const float*)d_in[16];
    const float* b2   = (const float*)d_in[17];
    const float* lnfg = (const float*)d_in[18];
    const float* lnfb = (const float*)d_in[19];
    float* out = (float*)d_out;

    cudaFuncSetAttribute((const void*)k_gemm<0>, cudaFuncAttributeMaxDynamicSharedMemorySize, GEMM_SMEM);
    cudaFuncSetAttribute((const void*)k_gemm<1>, cudaFuncAttributeMaxDynamicSharedMemorySize, GEMM_SMEM);
    cudaFuncSetAttribute((const void*)k_gemm<2>, cudaFuncAttributeMaxDynamicSharedMemorySize, GEMM_SMEM);
    cudaFuncSetAttribute((const void*)k_gemm<3>, cudaFuncAttributeMaxDynamicSharedMemorySize, GEMM_SMEM);
    cudaFuncSetAttribute((const void*)k_attn,    cudaFuncAttributeMaxDynamicSharedMemorySize, ATTN_SMEM);

    float* px;  cudaGetSymbolAddress((void**)&px,  g_x);
    bf16 *hh,*hl,*qh,*ql,*kh,*kl,*vh,*vl,*ah,*al,*fh,*fl;
    cudaGetSymbolAddress((void**)&hh, g_h_h); cudaGetSymbolAddress((void**)&hl, g_h_l);
    cudaGetSymbolAddress((void**)&qh, g_q_h); cudaGetSymbolAddress((void**)&ql, g_q_l);
    cudaGetSymbolAddress((void**)&kh, g_k_h); cudaGetSymbolAddress((void**)&kl, g_k_l);
    cudaGetSymbolAddress((void**)&vh, g_v_h); cudaGetSymbolAddress((void**)&vl, g_v_l);
    cudaGetSymbolAddress((void**)&ah, g_a_h); cudaGetSymbolAddress((void**)&al, g_a_l);
    cudaGetSymbolAddress((void**)&fh, g_f_h); cudaGetSymbolAddress((void**)&fl, g_f_l);
    bf16 *wqh,*wql,*wkh,*wkl,*wvh,*wvl,*woh,*wol,*w1h,*w1l,*w2h,*w2l,*eth,*etl;
    cudaGetSymbolAddress((void**)&wqh, g_wq_h); cudaGetSymbolAddress((void**)&wql, g_wq_l);
    cudaGetSymbolAddress((void**)&wkh, g_wk_h); cudaGetSymbolAddress((void**)&wkl, g_wk_l);
    cudaGetSymbolAddress((void**)&wvh, g_wv_h); cudaGetSymbolAddress((void**)&wvl, g_wv_l);
    cudaGetSymbolAddress((void**)&woh, g_wo_h); cudaGetSymbolAddress((void**)&wol, g_wo_l);
    cudaGetSymbolAddress((void**)&w1h, g_w1_h); cudaGetSymbolAddress((void**)&w1l, g_w1_l);
    cudaGetSymbolAddress((void**)&w2h, g_w2_h); cudaGetSymbolAddress((void**)&w2l, g_w2_l);
    cudaGetSymbolAddress((void**)&eth, g_et_h); cudaGetSymbolAddress((void**)&etl, g_et_l);

    // ---- weight conversion ----
    {
        int nA = L_*D_*D_/4;
        k_cvt<<<(nA+255)/256,256>>>((const float4*)wq, (uint2*)wqh, (uint2*)wql, nA);
        k_cvt<<<(nA+255)/256,256>>>((const float4*)wk, (uint2*)wkh, (uint2*)wkl, nA);
        k_cvt<<<(nA+255)/256,256>>>((const float4*)wv, (uint2*)wvh, (uint2*)wvl, nA);
        k_cvt<<<(nA+255)/256,256>>>((const float4*)wo, (uint2*)woh, (uint2*)wol, nA);
        int nF = L_*D_*F_/4;
        k_cvt<<<(nF+255)/256,256>>>((const float4*)w1, (uint2*)w1h, (uint2*)w1l, nF);
        k_cvt<<<(nF+255)/256,256>>>((const float4*)w2, (uint2*)w2h, (uint2*)w2l, nF);
        k_cvt_t<<<dim3(V_/32, D_/32), dim3(32,8)>>>(emb, eth, etl);
    }

    k_embed<<<(M_*D_+255)/256, 256>>>(ids, emb, px);

    for (int l=0; l<L_; l++){
        size_t odd = (size_t)l*D_*D_;
        size_t off = (size_t)l*D_*F_;
        k_ln<<<M_,256>>>(px, ln1g+l*D_, ln1b+l*D_, hh, hl);
        k_gemm<0><<<dim3(D_/BN, M_/BM, 3),256,GEMM_SMEM>>>(D_, D_, hh, hl,
            wqh+odd, wql+odd, wkh+odd, wkl+odd, wvh+odd, wvl+odd,
            bq+l*D_, bk+l*D_, bv+l*D_,
            nullptr, qh, ql, kh, kl, vh, vl);
        k_attn<<<dim3(S_/64, B_*H_),128,ATTN_SMEM>>>(qh, ql, kh, kl, vh, vl, ah, al);
        k_gemm<2><<<dim3(D_/BN, M_/BM, 1),256,GEMM_SMEM>>>(D_, D_, ah, al,
            woh+odd, wol+odd, woh+odd, wol+odd, woh+odd, wol+odd,
            bo+l*D_, bo+l*D_, bo+l*D_,
            px, px, nullptr, px, nullptr, px, nullptr);
        k_ln<<<M_,256>>>(px, ln2g+l*D_, ln2b+l*D_, hh, hl);
        k_gemm<1><<<dim3(F_/BN, M_/BM, 1),256,GEMM_SMEM>>>(F_, D_, hh, hl,
            w1h+off, w1l+off, w1h+off, w1l+off, w1h+off, w1l+off,
            b1+l*F_, b1+l*F_, b1+l*F_,
            nullptr, fh, fl, fh, fl, fh, fl);
        k_gemm<2><<<dim3(D_/BN, M_/BM, 1),256,GEMM_SMEM>>>(D_, F_, fh, fl,
            w2h+off, w2l+off, w2h+off, w2l+off, w2h+off, w2l+off,
            b2+l*D_, b2+l*D_, b2+l*D_,
            px, px, nullptr, px, nullptr, px, nullptr);
    }
    k_ln<<<M_,256>>>(px, lnfg, lnfb, hh, hl);
    k_gemm<3><<<dim3(V_/BN, M_/BM, 1),256,GEMM_SMEM>>>(V_, D_, hh, hl,
        eth, etl, eth, etl, eth, etl,
        nullptr, nullptr, nullptr,
        nullptr, out, nullptr, out, nullptr, out, nullptr);
}

// round 12
// speedup vs baseline: 4.6473x; 1.0355x over previous
#include <cuda_runtime.h>
#include <cuda_bf16.h>
#include <cstdint>
#include <math.h>

typedef unsigned int u32;
typedef __nv_bfloat16 bf16;

#define B_  2
#define S_  1024
#define D_  1024
#define H_  16
#define F_  4096
#define L_  6
#define V_  32000
#define DK_ 64
#define M_  (B_*S_)

#define BM 128
#define BN 128

__device__ __align__(16) float g_x [M_*D_];
__device__ __align__(16) bf16 g_h_h[M_*D_],  g_h_l[M_*D_];
__device__ __align__(16) bf16 g_q_h[M_*D_],  g_q_l[M_*D_];
__device__ __align__(16) bf16 g_k_h[M_*D_],  g_k_l[M_*D_];
__device__ __align__(16) bf16 g_v_h[M_*D_],  g_v_l[M_*D_];
__device__ __align__(16) bf16 g_a_h[M_*D_],  g_a_l[M_*D_];
__device__ __align__(16) bf16 g_f_h[M_*F_],  g_f_l[M_*F_];
__device__ __align__(16) bf16 g_wq_h[L_*D_*D_], g_wq_l[L_*D_*D_];
__device__ __align__(16) bf16 g_wk_h[L_*D_*D_], g_wk_l[L_*D_*D_];
__device__ __align__(16) bf16 g_wv_h[L_*D_*D_], g_wv_l[L_*D_*D_];
__device__ __align__(16) bf16 g_wo_h[L_*D_*D_], g_wo_l[L_*D_*D_];
__device__ __align__(16) bf16 g_w1_h[L_*D_*F_], g_w1_l[L_*D_*F_];
__device__ __align__(16) bf16 g_w2_h[L_*F_*D_], g_w2_l[L_*F_*D_];
__device__ __align__(16) bf16 g_et_h[(size_t)D_*V_], g_et_l[(size_t)D_*V_];

__device__ __forceinline__ u32 cvt_smem(const void* p){
    return (u32)__cvta_generic_to_shared(p);
}
__device__ __forceinline__ void cp16(u32 s, const void* g){
    asm volatile("cp.async.cg.shared.global [%0],[%1],16;\n"::"r"(s),"l"(g));
}
__device__ __forceinline__ void cp_commit(){ asm volatile("cp.async.commit_group;\n"::); }
template<int NN> __device__ __forceinline__ void cp_wait(){
    asm volatile("cp.async.wait_group %0;\n"::"n"(NN));
}
__device__ __forceinline__ void ldsm4(u32 &r0,u32 &r1,u32 &r2,u32 &r3, u32 a){
    asm volatile("ldmatrix.sync.aligned.m8n8.x4.shared.b16 {%0,%1,%2,%3},[%4];\n"
        : "=r"(r0),"=r"(r1),"=r"(r2),"=r"(r3) : "r"(a));
}
__device__ __forceinline__ void ldsm4t(u32 &r0,u32 &r1,u32 &r2,u32 &r3, u32 a){
    asm volatile("ldmatrix.sync.aligned.m8n8.x4.trans.shared.b16 {%0,%1,%2,%3},[%4];\n"
        : "=r"(r0),"=r"(r1),"=r"(r2),"=r"(r3) : "r"(a));
}
__device__ __forceinline__ void mma16816(float* c, const u32* a, const u32* b){
    asm volatile("mma.sync.aligned.m16n8k16.row.col.f32.bf16.bf16.f32 "
        "{%0,%1,%2,%3},{%4,%5,%6,%7},{%8,%9},{%0,%1,%2,%3};\n"
        : "+f"(c[0]),"+f"(c[1]),"+f"(c[2]),"+f"(c[3])
        : "r"(a[0]),"r"(a[1]),"r"(a[2]),"r"(a[3]),"r"(b[0]),"r"(b[1]));
}
__device__ __forceinline__ u32 pack2(bf16 h0, bf16 h1){
    unsigned short u0 = *reinterpret_cast<unsigned short*>(&h0);
    unsigned short u1 = *reinterpret_cast<unsigned short*>(&h1);
    return (u32)u0 | ((u32)u1 << 16);
}
__device__ __forceinline__ void split2(float x0, float x1, u32 &hi, u32 &lo){
    bf16 h0 = __float2bfloat16_rn(x0);
    bf16 h1 = __float2bfloat16_rn(x1);
    float f0 = __bfloat162float(h0), f1 = __bfloat162float(h1);
    hi = pack2(h0, h1);
    lo = pack2(__float2bfloat16_rn(x0 - f0), __float2bfloat16_rn(x1 - f1));
}
__device__ __forceinline__ float geluf(float x){
    return 0.5f*x*(1.0f + erff(x*0.7071067811865476f));
}

__global__ void k_cvt(const float4* __restrict__ src, uint2* __restrict__ dh,
                      uint2* __restrict__ dl, int n4)
{
    int i = blockIdx.x*256 + threadIdx.x;
    if (i >= n4) return;
    float4 v = src[i];
    u32 h0,l0,h1,l1;
    split2(v.x,v.y,h0,l0); split2(v.z,v.w,h1,l1);
    dh[i] = make_uint2(h0,h1);
    dl[i] = make_uint2(l0,l1);
}

__global__ void k_cvt_t(const float* __restrict__ src, bf16* __restrict__ dh,
                        bf16* __restrict__ dl)
{
    __shared__ float t[32][33];
    int v0 = blockIdx.x*32, d0 = blockIdx.y*32;
    int tx = threadIdx.x, ty = threadIdx.y;   // 32 x 8
    #pragma unroll
    for (int i=0;i<4;i++)
        t[ty+8*i][tx] = src[(size_t)(v0+ty+8*i)*D_ + d0 + tx];
    __syncthreads();
    #pragma unroll
    for (int i=0;i<4;i++){
        int dy = ty + 8*i;
        float val = t[tx][dy];
        bf16 hh = __float2bfloat16_rn(val);
        size_t o = (size_t)(d0+dy)*V_ + v0 + tx;
        dh[o] = hh;
        dl[o] = __float2bfloat16_rn(val - __bfloat162float(hh));
    }
}

__global__ void k_embed(const int* __restrict__ ids, const float* __restrict__ emb,
                        float* __restrict__ x)
{
    int idx = blockIdx.x * 256 + threadIdx.x;
    if (idx >= M_*D_) return;
    int d  = idx & (D_-1);
    int ms = idx >> 10;
    int s  = ms & (S_-1);
    int tok = ids[ms];
    int i2 = d & ~1;
    float freq = expf((float)i2 * (-9.210340371976184f / (float)D_));
    float ang  = (float)s * freq;
    float pe   = (d & 1) ? cosf(ang) : sinf(ang);
    x[idx] = emb[tok*D_ + d] * 32.0f + pe;
}

__global__ void __launch_bounds__(256) k_ln(const float* __restrict__ x,
                                            const float* __restrict__ g,
                                            const float* __restrict__ b,
                                            bf16* __restrict__ oh,
                                            bf16* __restrict__ ol)
{
    int row = blockIdx.x;
    int t = threadIdx.x;
    float4 v = ((const float4*)(x + (size_t)row*D_))[t];
    float s  = v.x+v.y+v.z+v.w;
    float ss = v.x*v.x+v.y*v.y+v.z*v.z+v.w*v.w;
    #pragma unroll
    for (int o=16;o>0;o>>=1){
        s  += __shfl_xor_sync(0xffffffffu, s,  o);
        ss += __shfl_xor_sync(0xffffffffu, ss, o);
    }
    __shared__ float rs[8], rss[8];
    if ((t&31)==0){ rs[t>>5]=s; rss[t>>5]=ss; }
    __syncthreads();
    float tot=0.f, tot2=0.f;
    #pragma unroll
    for (int i=0;i<8;i++){ tot += rs[i]; tot2 += rss[i]; }
    float mean = tot * (1.0f/D_);
    float var  = tot2 * (1.0f/D_) - mean*mean;
    float rstd = rsqrtf(var + 1e-5f);
    float4 gv = ((const float4*)g)[t];
    float4 bv = ((const float4*)b)[t];
    float o0=(v.x-mean)*rstd*gv.x+bv.x, o1=(v.y-mean)*rstd*gv.y+bv.y;
    float o2=(v.z-mean)*rstd*gv.z+bv.z, o3=(v.w-mean)*rstd*gv.w+bv.w;
    u32 h0,l0,h1,l1;
    split2(o0,o1,h0,l0); split2(o2,o3,h1,l1);
    ((uint2*)(oh + (size_t)row*D_))[t] = make_uint2(h0,h1);
    ((uint2*)(ol + (size_t)row*D_))[t] = make_uint2(l0,l1);
}

// ---------------- tensor-core GEMM, 4-stage cp.async pipeline ----------------
#define GEMM_SMEM 83968
template<int EPI>
__global__ void __launch_bounds__(256) k_gemm(
    int N, int K,
    const bf16* __restrict__ Ah, const bf16* __restrict__ Al,
    const bf16* Bh0, const bf16* Bl0, const bf16* Bh1, const bf16* Bl1,
    const bf16* Bh2, const bf16* Bl2,
    const float* bias0, const float* bias1, const float* bias2,
    const float* __restrict__ res,
    void* C0a, void* C0b, void* C1a, void* C1b, void* C2a, void* C2b)
{
    extern __shared__ __align__(16) bf16 sm[];
    bf16* sAh = sm;
    bf16* sBh = sm + 24576;

    const int z = blockIdx.z;
    const bf16* Bh = (z==0)?Bh0:((z==1)?Bh1:Bh2);
    const bf16* Bl = (z==0)?Bl0:((z==1)?Bl1:Bl2);
    const float* bias = (z==0)?bias0:((z==1)?bias1:bias2);
    void* Ca = (z==0)?C0a:((z==1)?C1a:C2a);
    void* Cb = (z==0)?C0b:((z==1)?C1b:C2b);

    const int tid = threadIdx.x;
    const int lane = tid & 31, wid = tid>>5;
    const int m_base = (wid&1)*64, n_base = (wid>>1)*32;
    const int bm = blockIdx.y*BM, bn = blockIdx.x*BN;

    const int ar = tid>>1, ac = (tid&1)*8;
    const int br = tid>>4, bc = (tid&15)*8;
    const bf16* Agh = Ah + (size_t)(bm+ar)*K + ac;
    const bf16* Agl = Al + (size_t)(bm+ar)*K + ac;
    const bf16* Bgh = Bh + (size_t)br*N + bn + bc;
    const bf16* Bgl = Bl + (size_t)br*N + bn + bc;

    const u32 aWr = cvt_smem(sAh + ar*24 + ac);
    const u32 bWr = cvt_smem(sBh + br*136 + bc);

    const int q2 = lane>>3;
    const u32 aRd = cvt_smem(sAh + (m_base + (lane&15))*24 + (lane>>4)*8);
    const u32 bRd = cvt_smem(sBh + ((q2&1)*8 + (lane&7))*136 + n_base + (q2>>1)*8);

    float acc[4][4][4];
    #pragma unroll
    for (int i=0;i<4;i++)
        #pragma unroll
        for (int j=0;j<4;j++)
            #pragma unroll
            for (int r=0;r<4;r++) acc[i][j][r]=0.f;

    auto issue = [&](int kt, int st){
        u32 a = aWr + st*6144;
        cp16(a,         Agh + kt*16);
        cp16(a + 24576, Agl + kt*16);
        u32 b = bWr + st*4352;
        cp16(b,         Bgh + (size_t)kt*16*N);
        cp16(b + 17408, Bgl + (size_t)kt*16*N);
        cp_commit();
    };

    const int nk = K/16;
    issue(0,0); issue(1,1); issue(2,2);

    for (int kt=0; kt<nk; kt++){
        if (kt+2 < nk)      cp_wait<2>();
        else if (kt+1 < nk) cp_wait<1>();
        else                cp_wait<0>();
        __syncthreads();
        const int st = kt & 3;

        u32 fah[4][4], fal[4][4];
        const u32 ab = aRd + st*6144;
        #pragma unroll
        for (int mi=0;mi<4;mi++){
            ldsm4(fah[mi][0],fah[mi][1],fah[mi][2],fah[mi][3], ab + mi*768);
            ldsm4(fal[mi][0],fal[mi][1],fal[mi][2],fal[mi][3], ab + mi*768 + 24576);
        }
        u32 fbh[4][2], fbl[4][2];
        const u32 bb2 = bRd + st*4352;
        #pragma unroll
        for (int p=0;p<2;p++){
            u32 r0,r1,r2,r3;
            ldsm4t(r0,r1,r2,r3, bb2 + p*32);
            fbh[2*p][0]=r0; fbh[2*p][1]=r1; fbh[2*p+1][0]=r2; fbh[2*p+1][1]=r3;
            ldsm4t(r0,r1,r2,r3, bb2 + p*32 + 17408);
            fbl[2*p][0]=r0; fbl[2*p][1]=r1; fbl[2*p+1][0]=r2; fbl[2*p+1][1]=r3;
        }
        if (kt+3 < nk) issue(kt+3, (kt+3)&3);

        // pass-major issue order: all 16 accumulators per pass -> dependency
        // distance 16 HMMA instead of back-to-back RAW chains of 3
        #pragma unroll
        for (int mi=0;mi<4;mi++)
            #pragma unroll
            for (int nj=0;nj<4;nj++)
                mma16816(acc[mi][nj], fah[mi], fbh[nj]);
        #pragma unroll
        for (int mi=0;mi<4;mi++)
            #pragma unroll
            for (int nj=0;nj<4;nj++)
                mma16816(acc[mi][nj], fah[mi], fbl[nj]);
        #pragma unroll
        for (int mi=0;mi<4;mi++)
            #pragma unroll
            for (int nj=0;nj<4;nj++)
                mma16816(acc[mi][nj], fal[mi], fbh[nj]);
    }

    #pragma unroll
    for (int mi=0; mi<4; mi++){
        #pragma unroll
        for (int r=0; r<2; r++){
            int gm = bm + m_base + mi*16 + (lane>>2) + r*8;
            #pragma unroll
            for (int nj=0; nj<4; nj++){
                int gn = bn + n_base + nj*8 + (lane&3)*2;
                float v0 = acc[mi][nj][r*2+0];
                float v1 = acc[mi][nj][r*2+1];
                if (EPI != 3){ v0 += bias[gn]; v1 += bias[gn+1]; }
                if (EPI == 1){ v0 = geluf(v0); v1 = geluf(v1); }
                size_t base = (size_t)gm*N + gn;
                if (EPI == 2){
                    float2 rr = *(const float2*)(res + base);
                    *(float2*)((float*)Ca + base) = make_float2(v0+rr.x, v1+rr.y);
                } else if (EPI == 3){
                    *(float2*)((float*)Ca + base) = make_float2(v0, v1);
                } else {
                    u32 h_,l_;
                    split2(v0, v1, h_, l_);
                    *(u32*)((bf16*)Ca + base) = h_;
                    *(u32*)((bf16*)Cb + base) = l_;
                }
            }
        }
    }
}

// ---------------- tensor-core flash attention, 2-stage K/V pipeline ----------------
#define ATTN_SMEM 92160
__global__ void __launch_bounds__(128) k_attn(
    const bf16* __restrict__ Qh, const bf16* __restrict__ Ql,
    const bf16* __restrict__ Kh, const bf16* __restrict__ Kl,
    const bf16* __restrict__ Vh, const bf16* __restrict__ Vl,
    bf16* __restrict__ Oh, bf16* __restrict__ Ol)
{
    extern __shared__ __align__(16) bf16 sm[];
    bf16* sQh = sm;
    bf16* sKh = sm + 9216;
    bf16* sVh = sm + 27648;

    const int tid = threadIdx.x;
    const int lane = tid & 31;
    const int w = tid >> 5;
    const int qt = blockIdx.x;
    const int bh = blockIdx.y;
    const int bb = bh >> 4;
    const int hh = bh & 15;
    const int g  = lane >> 2;
    const int n2 = (lane & 3) * 2;
    const int q2 = lane >> 3;

    const size_t qrow0 = (size_t)bb*S_ + qt*64;
    const int col0 = hh*DK_;

    #pragma unroll
    for (int i=0;i<4;i++){
        int cid = tid + i*128;
        int r = cid >> 3, ch = (cid & 7)*8;
        size_t go = (qrow0 + r)*D_ + col0 + ch;
        u32 s = cvt_smem(sQh + r*72 + ch);
        cp16(s, Qh + go);
        cp16(s + 9216, Ql + go);
    }
    cp_commit();

    auto issueKV = [&](int kt, int st){
        #pragma unroll
        for (int i=0;i<4;i++){
            int cid = tid + i*128;
            int r = cid >> 3, ch = (cid & 7)*8;
            size_t go = ((size_t)bb*S_ + kt*64 + r)*D_ + col0 + ch;
            u32 s = cvt_smem(sKh + st*4608 + r*72 + ch);
            cp16(s,         Kh + go);
            cp16(s + 18432, Kl + go);
            cp16(s + 36864, Vh + go);
            cp16(s + 55296, Vl + go);
        }
        cp_commit();
    };

    issueKV(0, 0);
    cp_wait<1>();
    __syncthreads();
    u32 qfh[4][4], qfl[4][4];
    {
        u32 a = cvt_smem(sQh + (w*16 + (lane&15))*72 + (lane>>4)*8);
        #pragma unroll
        for (int ks=0; ks<4; ks++){
            ldsm4(qfh[ks][0],qfh[ks][1],qfh[ks][2],qfh[ks][3], a + ks*32);
            ldsm4(qfl[ks][0],qfl[ks][1],qfl[ks][2],qfl[ks][3], a + ks*32 + 9216);
        }
    }

    float m[2]    = {-1e30f, -1e30f};
    float lsum[2] = {0.f, 0.f};
    float oa[8][4];
    #pragma unroll
    for (int i=0;i<8;i++)
        #pragma unroll
        for (int j=0;j<4;j++) oa[i][j]=0.f;

    for (int kt=0; kt<=qt; kt++){
        const int st = kt & 1;
        if (kt+1 <= qt){ issueKV(kt+1, st^1); cp_wait<1>(); }
        else           { cp_wait<0>(); }
        __syncthreads();

        float s[8][4];
        #pragma unroll
        for (int nt=0;nt<8;nt++)
            #pragma unroll
            for (int j=0;j<4;j++) s[nt][j]=0.f;

        #pragma unroll
        for (int ks=0; ks<4; ks++){
            u32 kbh[8][2], kbl[8][2];
            #pragma unroll
            for (int pr=0; pr<4; pr++){
                u32 r0,r1,r2,r3;
                u32 a = cvt_smem(sKh + st*4608 + (pr*16 + (q2&1)*8 + (lane&7))*72 + (q2>>1)*8) + ks*32;
                ldsm4(r0,r1,r2,r3, a);
                kbh[2*pr][0]=r0; kbh[2*pr][1]=r2; kbh[2*pr+1][0]=r1; kbh[2*pr+1][1]=r3;
                ldsm4(r0,r1,r2,r3, a + 18432);
                kbl[2*pr][0]=r0; kbl[2*pr][1]=r2; kbl[2*pr+1][0]=r1; kbl[2*pr+1][1]=r3;
            }
            // pass-major: 8 independent mma per pass
            #pragma unroll
            for (int nt=0; nt<8; nt++) mma16816(s[nt], qfh[ks], kbh[nt]);
            #pragma unroll
            for (int nt=0; nt<8; nt++) mma16816(s[nt], qfh[ks], kbl[nt]);
            #pragma unroll
            for (int nt=0; nt<8; nt++) mma16816(s[nt], qfl[ks], kbh[nt]);
        }

        const bool diag = (kt == qt);
        #pragma unroll
        for (int nt=0;nt<8;nt++)
            #pragma unroll
            for (int j=0;j<4;j++){
                float v = s[nt][j]*0.125f;
                if (diag){
                    int col  = nt*8 + n2 + (j&1);
                    int rowl = w*16 + g + (j>>1)*8;
                    if (col > rowl) v = -1e30f;
                }
                s[nt][j] = v;
            }

        float mx0=-1e30f, mx1=-1e30f;
        #pragma unroll
        for (int nt=0;nt<8;nt++){
            mx0 = fmaxf(mx0, fmaxf(s[nt][0], s[nt][1]));
            mx1 = fmaxf(mx1, fmaxf(s[nt][2], s[nt][3]));
        }
        mx0 = fmaxf(mx0, __shfl_xor_sync(0xffffffffu, mx0, 1));
        mx0 = fmaxf(mx0, __shfl_xor_sync(0xffffffffu, mx0, 2));
        mx1 = fmaxf(mx1, __shfl_xor_sync(0xffffffffu, mx1, 1));
        mx1 = fmaxf(mx1, __shfl_xor_sync(0xffffffffu, mx1, 2));
        float mn0 = fmaxf(m[0], mx0), mn1 = fmaxf(m[1], mx1);
        float c0 = __expf(m[0]-mn0), c1 = __expf(m[1]-mn1);
        float ps0=0.f, ps1=0.f;
        #pragma unroll
        for (int nt=0;nt<8;nt++){
            s[nt][0] = __expf(s[nt][0]-mn0); ps0 += s[nt][0];
            s[nt][1] = __expf(s[nt][1]-mn0); ps0 += s[nt][1];
            s[nt][2] = __expf(s[nt][2]-mn1); ps1 += s[nt][2];
            s[nt][3] = __expf(s[nt][3]-mn1); ps1 += s[nt][3];
        }
        ps0 += __shfl_xor_sync(0xffffffffu, ps0, 1);
        ps0 += __shfl_xor_sync(0xffffffffu, ps0, 2);
        ps1 += __shfl_xor_sync(0xffffffffu, ps1, 1);
        ps1 += __shfl_xor_sync(0xffffffffu, ps1, 2);
        lsum[0] = lsum[0]*c0 + ps0;
        lsum[1] = lsum[1]*c1 + ps1;
        m[0] = mn0; m[1] = mn1;
        #pragma unroll
        for (int dt=0;dt<8;dt++){
            oa[dt][0]*=c0; oa[dt][1]*=c0; oa[dt][2]*=c1; oa[dt][3]*=c1;
        }

        #pragma unroll
        for (int ks=0; ks<4; ks++){
            u32 pfh[4], pfl[4];
            split2(s[2*ks  ][0], s[2*ks  ][1], pfh[0], pfl[0]);
            split2(s[2*ks  ][2], s[2*ks  ][3], pfh[1], pfl[1]);
            split2(s[2*ks+1][0], s[2*ks+1][1], pfh[2], pfl[2]);
            split2(s[2*ks+1][2], s[2*ks+1][3], pfh[3], pfl[3]);

            u32 vbh[8][2], vbl[8][2];
            #pragma unroll
            for (int dp=0; dp<4; dp++){
                u32 r0,r1,r2,r3;
                u32 a = cvt_smem(sVh + st*4608 + (ks*16 + (q2&1)*8 + (lane&7))*72 + dp*16 + (q2>>1)*8);
                ldsm4t(r0,r1,r2,r3, a);
                vbh[2*dp][0]=r0; vbh[2*dp][1]=r1; vbh[2*dp+1][0]=r2; vbh[2*dp+1][1]=r3;
                ldsm4t(r0,r1,r2,r3, a + 18432);
                vbl[2*dp][0]=r0; vbl[2*dp][1]=r1; vbl[2*dp+1][0]=r2; vbl[2*dp+1][1]=r3;
            }
            // pass-major: 8 independent mma per pass
            #pragma unroll
            for (int dt=0; dt<8; dt++) mma16816(oa[dt], pfh, vbh[dt]);
            #pragma unroll
            for (int dt=0; dt<8; dt++) mma16816(oa[dt], pfh, vbl[dt]);
            #pragma unroll
            for (int dt=0; dt<8; dt++) mma16816(oa[dt], pfl, vbh[dt]);
        }
        __syncthreads();
    }

    float inv0 = 1.0f/lsum[0], inv1 = 1.0f/lsum[1];
    size_t r0 = qrow0 + w*16 + g;
    size_t r1 = r0 + 8;
    #pragma unroll
    for (int dt=0; dt<8; dt++){
        int col = col0 + dt*8 + n2;
        u32 h_,l_;
        split2(oa[dt][0]*inv0, oa[dt][1]*inv0, h_, l_);
        *(u32*)(Oh + r0*D_ + col) = h_;
        *(u32*)(Ol + r0*D_ + col) = l_;
        split2(oa[dt][2]*inv1, oa[dt][3]*inv1, h_, l_);
        *(u32*)(Oh + r1*D_ + col) = h_;
        *(u32*)(Ol + r1*D_ + col) = l_;
    }
}

extern "C" void kernel_launch(void* const* d_in, const int* in_sizes, int n_in,
                              void* d_out, int out_size)
{
    (void)in_sizes; (void)n_in; (void)out_size;
    const int*   ids  = (const int*)  d_in[0];
    const float* emb  = (const float*)d_in[1];
    const float* wq   = (const float*)d_in[2];
    const float* bq   = (const float*)d_in[3];
    const float* wk   = (const float*)d_in[4];
    const float* bk   = (const float*)d_in[5];
    const float* wv   = (const float*)d_in[6];
    const float* bv   = (const float*)d_in[7];
    const float* wo   = (const float*)d_in[8];
    const float* bo   = (const float*)d_in[9];
    const float* ln1g = (const float*)d_in[10];
    const float* ln1b = (const float*)d_in[11];
    const float* ln2g = (const float*)d_in[12];
    const float* ln2b = (const float*)d_in[13];
    const float* w1   = (const float*)d_in[14];
    const float* b1   = (const float*)d_in[15];
    const float* w2   = (const float*)d_in[16];
    const float* b2   = (const float*)d_in[17];
    const float* lnfg = (const float*)d_in[18];
    const float* lnfb = (const float*)d_in[19];
    float* out = (float*)d_out;

    cudaFuncSetAttribute((const void*)k_gemm<0>, cudaFuncAttributeMaxDynamicSharedMemorySize, GEMM_SMEM);
    cudaFuncSetAttribute((const void*)k_gemm<1>, cudaFuncAttributeMaxDynamicSharedMemorySize, GEMM_SMEM);
    cudaFuncSetAttribute((const void*)k_gemm<2>, cudaFuncAttributeMaxDynamicSharedMemorySize, GEMM_SMEM);
    cudaFuncSetAttribute((const void*)k_gemm<3>, cudaFuncAttributeMaxDynamicSharedMemorySize, GEMM_SMEM);
    cudaFuncSetAttribute((const void*)k_attn,    cudaFuncAttributeMaxDynamicSharedMemorySize, ATTN_SMEM);

    float* px;  cudaGetSymbolAddress((void**)&px,  g_x);
    bf16 *hh,*hl,*qh,*ql,*kh,*kl,*vh,*vl,*ah,*al,*fh,*fl;
    cudaGetSymbolAddress((void**)&hh, g_h_h); cudaGetSymbolAddress((void**)&hl, g_h_l);
    cudaGetSymbolAddress((void**)&qh, g_q_h); cudaGetSymbolAddress((void**)&ql, g_q_l);
    cudaGetSymbolAddress((void**)&kh, g_k_h); cudaGetSymbolAddress((void**)&kl, g_k_l);
    cudaGetSymbolAddress((void**)&vh, g_v_h); cudaGetSymbolAddress((void**)&vl, g_v_l);
    cudaGetSymbolAddress((void**)&ah, g_a_h); cudaGetSymbolAddress((void**)&al, g_a_l);
    cudaGetSymbolAddress((void**)&fh, g_f_h); cudaGetSymbolAddress((void**)&fl, g_f_l);
    bf16 *wqh,*wql,*wkh,*wkl,*wvh,*wvl,*woh,*wol,*w1h,*w1l,*w2h,*w2l,*eth,*etl;
    cudaGetSymbolAddress((void**)&wqh, g_wq_h); cudaGetSymbolAddress((void**)&wql, g_wq_l);
    cudaGetSymbolAddress((void**)&wkh, g_wk_h); cudaGetSymbolAddress((void**)&wkl, g_wk_l);
    cudaGetSymbolAddress((void**)&wvh, g_wv_h); cudaGetSymbolAddress((void**)&wvl, g_wv_l);
    cudaGetSymbolAddress((void**)&woh, g_wo_h); cudaGetSymbolAddress((void**)&wol, g_wo_l);
    cudaGetSymbolAddress((void**)&w1h, g_w1_h); cudaGetSymbolAddress((void**)&w1l, g_w1_l);
    cudaGetSymbolAddress((void**)&w2h, g_w2_h); cudaGetSymbolAddress((void**)&w2l, g_w2_l);
    cudaGetSymbolAddress((void**)&eth, g_et_h); cudaGetSymbolAddress((void**)&etl, g_et_l);

    {
        int nA = L_*D_*D_/4;
        k_cvt<<<(nA+255)/256,256>>>((const float4*)wq, (uint2*)wqh, (uint2*)wql, nA);
        k_cvt<<<(nA+255)/256,256>>>((const float4*)wk, (uint2*)wkh, (uint2*)wkl, nA);
        k_cvt<<<(nA+255)/256,256>>>((const float4*)wv, (uint2*)wvh, (uint2*)wvl, nA);
        k_cvt<<<(nA+255)/256,256>>>((const float4*)wo, (uint2*)woh, (uint2*)wol, nA);
        int nF = L_*D_*F_/4;
        k_cvt<<<(nF+255)/256,256>>>((const float4*)w1, (uint2*)w1h, (uint2*)w1l, nF);
        k_cvt<<<(nF+255)/256,256>>>((const float4*)w2, (uint2*)w2h, (uint2*)w2l, nF);
        k_cvt_t<<<dim3(V_/32, D_/32), dim3(32,8)>>>(emb, eth, etl);
    }

    k_embed<<<(M_*D_+255)/256, 256>>>(ids, emb, px);

    for (int l=0; l<L_; l++){
        size_t odd = (size_t)l*D_*D_;
        size_t off = (size_t)l*D_*F_;
        k_ln<<<M_,256>>>(px, ln1g+l*D_, ln1b+l*D_, hh, hl);
        k_gemm<0><<<dim3(D_/BN, M_/BM, 3),256,GEMM_SMEM>>>(D_, D_, hh, hl,
            wqh+odd, wql+odd, wkh+odd, wkl+odd, wvh+odd, wvl+odd,
            bq+l*D_, bk+l*D_, bv+l*D_,
            nullptr, qh, ql, kh, kl, vh, vl);
        k_attn<<<dim3(S_/64, B_*H_),128,ATTN_SMEM>>>(qh, ql, kh, kl, vh, vl, ah, al);
        k_gemm<2><<<dim3(D_/BN, M_/BM, 1),256,GEMM_SMEM>>>(D_, D_, ah, al,
            woh+odd, wol+odd, woh+odd, wol+odd, woh+odd, wol+odd,
            bo+l*D_, bo+l*D_, bo+l*D_,
            px, px, nullptr, px, nullptr, px, nullptr);
        k_ln<<<M_,256>>>(px, ln2g+l*D_, ln2b+l*D_, hh, hl);
        k_gemm<1><<<dim3(F_/BN, M_/BM, 1),256,GEMM_SMEM>>>(F_, D_, hh, hl,
            w1h+off, w1l+off, w1h+off, w1l+off, w1h+off, w1l+off,
            b1+l*F_, b1+l*F_, b1+l*F_,
            nullptr, fh, fl, fh, fl, fh, fl);
        k_gemm<2><<<dim3(D_/BN, M_/BM, 1),256,GEMM_SMEM>>>(D_, F_, fh, fl,
            w2h+off, w2l+off, w2h+off, w2l+off, w2h+off, w2l+off,
            b2+l*D_, b2+l*D_, b2+l*D_,
            px, px, nullptr, px, nullptr, px, nullptr);
    }
    k_ln<<<M_,256>>>(px, lnfg, lnfb, hh, hl);
    k_gemm<3><<<dim3(V_/BN, M_/BM, 1),256,GEMM_SMEM>>>(V_, D_, hh, hl,
        eth, etl, eth, etl, eth, etl,
        nullptr, nullptr, nullptr,
        nullptr, out, nullptr, out, nullptr, out, nullptr);
}

// round 13
// speedup vs baseline: 5.6869x; 1.2237x over previous
#include <cuda_runtime.h>
#include <cuda_bf16.h>
#include <cuda_fp16.h>
#include <cstdint>
#include <math.h>

typedef unsigned int u32;
typedef __nv_bfloat16 bf16;

#define B_  2
#define S_  1024
#define D_  1024
#define H_  16
#define F_  4096
#define L_  6
#define V_  32000
#define DK_ 64
#define M_  (B_*S_)

#define BM 128
#define BN 128

__device__ __align__(16) float g_x [M_*D_];
__device__ __align__(16) bf16 g_h_h[M_*D_],  g_h_l[M_*D_];
__device__ __align__(16) bf16 g_q_h[M_*D_],  g_q_l[M_*D_];
__device__ __align__(16) bf16 g_k_h[M_*D_],  g_k_l[M_*D_];
__device__ __align__(16) bf16 g_v_h[M_*D_],  g_v_l[M_*D_];
__device__ __align__(16) bf16 g_a_h[M_*D_],  g_a_l[M_*D_];
__device__ __align__(16) bf16 g_f_h[M_*F_],  g_f_l[M_*F_];        // fp16 bits
__device__ __align__(16) bf16 g_wq_h[L_*D_*D_], g_wq_l[L_*D_*D_];
__device__ __align__(16) bf16 g_wk_h[L_*D_*D_], g_wk_l[L_*D_*D_];
__device__ __align__(16) bf16 g_wv_h[L_*D_*D_], g_wv_l[L_*D_*D_];
__device__ __align__(16) bf16 g_wo_h[L_*D_*D_], g_wo_l[L_*D_*D_];
__device__ __align__(16) bf16 g_w1_h[L_*D_*F_];                   // fp16 bits, hi only
__device__ __align__(16) bf16 g_w2_h[L_*F_*D_];                   // fp16 bits, hi only
__device__ __align__(16) bf16 g_et_h[(size_t)D_*V_];              // fp16 bits, hi only

__device__ __forceinline__ u32 cvt_smem(const void* p){
    return (u32)__cvta_generic_to_shared(p);
}
__device__ __forceinline__ void cp16(u32 s, const void* g){
    asm volatile("cp.async.cg.shared.global [%0],[%1],16;\n"::"r"(s),"l"(g));
}
__device__ __forceinline__ void cp_commit(){ asm volatile("cp.async.commit_group;\n"::); }
template<int NN> __device__ __forceinline__ void cp_wait(){
    asm volatile("cp.async.wait_group %0;\n"::"n"(NN));
}
__device__ __forceinline__ void ldsm4(u32 &r0,u32 &r1,u32 &r2,u32 &r3, u32 a){
    asm volatile("ldmatrix.sync.aligned.m8n8.x4.shared.b16 {%0,%1,%2,%3},[%4];\n"
        : "=r"(r0),"=r"(r1),"=r"(r2),"=r"(r3) : "r"(a));
}
__device__ __forceinline__ void ldsm4t(u32 &r0,u32 &r1,u32 &r2,u32 &r3, u32 a){
    asm volatile("ldmatrix.sync.aligned.m8n8.x4.trans.shared.b16 {%0,%1,%2,%3},[%4];\n"
        : "=r"(r0),"=r"(r1),"=r"(r2),"=r"(r3) : "r"(a));
}
__device__ __forceinline__ void mma16816(float* c, const u32* a, const u32* b){
    asm volatile("mma.sync.aligned.m16n8k16.row.col.f32.bf16.bf16.f32 "
        "{%0,%1,%2,%3},{%4,%5,%6,%7},{%8,%9},{%0,%1,%2,%3};\n"
        : "+f"(c[0]),"+f"(c[1]),"+f"(c[2]),"+f"(c[3])
        : "r"(a[0]),"r"(a[1]),"r"(a[2]),"r"(a[3]),"r"(b[0]),"r"(b[1]));
}
__device__ __forceinline__ void mma16816h(float* c, const u32* a, const u32* b){
    asm volatile("mma.sync.aligned.m16n8k16.row.col.f32.f16.f16.f32 "
        "{%0,%1,%2,%3},{%4,%5,%6,%7},{%8,%9},{%0,%1,%2,%3};\n"
        : "+f"(c[0]),"+f"(c[1]),"+f"(c[2]),"+f"(c[3])
        : "r"(a[0]),"r"(a[1]),"r"(a[2]),"r"(a[3]),"r"(b[0]),"r"(b[1]));
}
__device__ __forceinline__ u32 pack2(bf16 h0, bf16 h1){
    unsigned short u0 = *reinterpret_cast<unsigned short*>(&h0);
    unsigned short u1 = *reinterpret_cast<unsigned short*>(&h1);
    return (u32)u0 | ((u32)u1 << 16);
}
__device__ __forceinline__ void split2(float x0, float x1, u32 &hi, u32 &lo){
    bf16 h0 = __float2bfloat16_rn(x0);
    bf16 h1 = __float2bfloat16_rn(x1);
    float f0 = __bfloat162float(h0), f1 = __bfloat162float(h1);
    hi = pack2(h0, h1);
    lo = pack2(__float2bfloat16_rn(x0 - f0), __float2bfloat16_rn(x1 - f1));
}
__device__ __forceinline__ u32 pack2h(__half h0, __half h1){
    unsigned short u0 = *reinterpret_cast<unsigned short*>(&h0);
    unsigned short u1 = *reinterpret_cast<unsigned short*>(&h1);
    return (u32)u0 | ((u32)u1 << 16);
}
__device__ __forceinline__ void split2h(float x0, float x1, u32 &hi, u32 &lo){
    __half h0 = __float2half_rn(x0);
    __half h1 = __float2half_rn(x1);
    float f0 = __half2float(h0), f1 = __half2float(h1);
    hi = pack2h(h0, h1);
    lo = pack2h(__float2half_rn(x0 - f0), __float2half_rn(x1 - f1));
}
__device__ __forceinline__ float geluf(float x){
    return 0.5f*x*(1.0f + erff(x*0.7071067811865476f));
}

// bf16 hi/lo conversion
__global__ void k_cvt(const float4* __restrict__ src, uint2* __restrict__ dh,
                      uint2* __restrict__ dl, int n4)
{
    int i = blockIdx.x*256 + threadIdx.x;
    if (i >= n4) return;
    float4 v = src[i];
    u32 h0,l0,h1,l1;
    split2(v.x,v.y,h0,l0); split2(v.z,v.w,h1,l1);
    dh[i] = make_uint2(h0,h1);
    dl[i] = make_uint2(l0,l1);
}
// fp16 hi-only conversion
__global__ void k_cvt_h(const float4* __restrict__ src, uint2* __restrict__ dh, int n4)
{
    int i = blockIdx.x*256 + threadIdx.x;
    if (i >= n4) return;
    float4 v = src[i];
    dh[i] = make_uint2(pack2h(__float2half_rn(v.x), __float2half_rn(v.y)),
                       pack2h(__float2half_rn(v.z), __float2half_rn(v.w)));
}
// emb [V][D] fp32 -> emb^T [D][V] fp16 hi-only
__global__ void k_cvt_t_h(const float* __restrict__ src, __half* __restrict__ dh)
{
    __shared__ float t[32][33];
    int v0 = blockIdx.x*32, d0 = blockIdx.y*32;
    int tx = threadIdx.x, ty = threadIdx.y;   // 32 x 8
    #pragma unroll
    for (int i=0;i<4;i++)
        t[ty+8*i][tx] = src[(size_t)(v0+ty+8*i)*D_ + d0 + tx];
    __syncthreads();
    #pragma unroll
    for (int i=0;i<4;i++){
        int dy = ty + 8*i;
        dh[(size_t)(d0+dy)*V_ + v0 + tx] = __float2half_rn(t[tx][dy]);
    }
}

__global__ void k_embed(const int* __restrict__ ids, const float* __restrict__ emb,
                        float* __restrict__ x)
{
    int idx = blockIdx.x * 256 + threadIdx.x;
    if (idx >= M_*D_) return;
    int d  = idx & (D_-1);
    int ms = idx >> 10;
    int s  = ms & (S_-1);
    int tok = ids[ms];
    int i2 = d & ~1;
    float freq = expf((float)i2 * (-9.210340371976184f / (float)D_));
    float ang  = (float)s * freq;
    float pe   = (d & 1) ? cosf(ang) : sinf(ang);
    x[idx] = emb[tok*D_ + d] * 32.0f + pe;
}

// FP16=0: bf16 hi/lo out; FP16=1: fp16 hi/lo out
template<int FP16>
__global__ void __launch_bounds__(256) k_ln(const float* __restrict__ x,
                                            const float* __restrict__ g,
                                            const float* __restrict__ b,
                                            bf16* __restrict__ oh,
                                            bf16* __restrict__ ol)
{
    int row = blockIdx.x;
    int t = threadIdx.x;
    float4 v = ((const float4*)(x + (size_t)row*D_))[t];
    float s  = v.x+v.y+v.z+v.w;
    float ss = v.x*v.x+v.y*v.y+v.z*v.z+v.w*v.w;
    #pragma unroll
    for (int o=16;o>0;o>>=1){
        s  += __shfl_xor_sync(0xffffffffu, s,  o);
        ss += __shfl_xor_sync(0xffffffffu, ss, o);
    }
    __shared__ float rs[8], rss[8];
    if ((t&31)==0){ rs[t>>5]=s; rss[t>>5]=ss; }
    __syncthreads();
    float tot=0.f, tot2=0.f;
    #pragma unroll
    for (int i=0;i<8;i++){ tot += rs[i]; tot2 += rss[i]; }
    float mean = tot * (1.0f/D_);
    float var  = tot2 * (1.0f/D_) - mean*mean;
    float rstd = rsqrtf(var + 1e-5f);
    float4 gv = ((const float4*)g)[t];
    float4 bv = ((const float4*)b)[t];
    float o0=(v.x-mean)*rstd*gv.x+bv.x, o1=(v.y-mean)*rstd*gv.y+bv.y;
    float o2=(v.z-mean)*rstd*gv.z+bv.z, o3=(v.w-mean)*rstd*gv.w+bv.w;
    u32 h0,l0,h1,l1;
    if (FP16){ split2h(o0,o1,h0,l0); split2h(o2,o3,h1,l1); }
    else     { split2 (o0,o1,h0,l0); split2 (o2,o3,h1,l1); }
    ((uint2*)(oh + (size_t)row*D_))[t] = make_uint2(h0,h1);
    ((uint2*)(ol + (size_t)row*D_))[t] = make_uint2(l0,l1);
}

// ---------------- tensor-core GEMM, 4-stage cp.async pipeline ----------------
// PREC 0: bf16 3-pass (Ah.Bh + Ah.Bl + Al.Bh); PREC 1: fp16 2-pass (Ah.Bh + Al.Bh, no Bl)
// EPI: 0 = +bias -> bf16 split, 1 = gelu(+bias) -> fp16 split, 2 = +bias+res -> fp32, 3 = plain fp32
#define GEMM_SMEM 83968
template<int EPI, int PREC>
__global__ void __launch_bounds__(256) k_gemm(
    int N, int K,
    const bf16* __restrict__ Ah, const bf16* __restrict__ Al,
    const bf16* Bh0, const bf16* Bl0, const bf16* Bh1, const bf16* Bl1,
    const bf16* Bh2, const bf16* Bl2,
    const float* bias0, const float* bias1, const float* bias2,
    const float* __restrict__ res,
    void* C0a, void* C0b, void* C1a, void* C1b, void* C2a, void* C2b)
{
    extern __shared__ __align__(16) bf16 sm[];
    bf16* sAh = sm;
    bf16* sBh = sm + 24576;

    const int z = blockIdx.z;
    const bf16* Bh = (z==0)?Bh0:((z==1)?Bh1:Bh2);
    const bf16* Bl = (z==0)?Bl0:((z==1)?Bl1:Bl2);
    const float* bias = (z==0)?bias0:((z==1)?bias1:bias2);
    void* Ca = (z==0)?C0a:((z==1)?C1a:C2a);
    void* Cb = (z==0)?C0b:((z==1)?C1b:C2b);

    const int tid = threadIdx.x;
    const int lane = tid & 31, wid = tid>>5;
    const int m_base = (wid&1)*64, n_base = (wid>>1)*32;
    const int bm = blockIdx.y*BM, bn = blockIdx.x*BN;

    const int ar = tid>>1, ac = (tid&1)*8;
    const int br = tid>>4, bc = (tid&15)*8;
    const bf16* Agh = Ah + (size_t)(bm+ar)*K + ac;
    const bf16* Agl = Al + (size_t)(bm+ar)*K + ac;
    const bf16* Bgh = Bh + (size_t)br*N + bn + bc;
    const bf16* Bgl = (PREC==0) ? (Bl + (size_t)br*N + bn + bc) : nullptr;

    const u32 aWr = cvt_smem(sAh + ar*24 + ac);
    const u32 bWr = cvt_smem(sBh + br*136 + bc);

    const int q2 = lane>>3;
    const u32 aRd = cvt_smem(sAh + (m_base + (lane&15))*24 + (lane>>4)*8);
    const u32 bRd = cvt_smem(sBh + ((q2&1)*8 + (lane&7))*136 + n_base + (q2>>1)*8);

    float acc[4][4][4];
    #pragma unroll
    for (int i=0;i<4;i++)
        #pragma unroll
        for (int j=0;j<4;j++)
            #pragma unroll
            for (int r=0;r<4;r++) acc[i][j][r]=0.f;

    auto issue = [&](int kt, int st){
        u32 a = aWr + st*6144;
        cp16(a,         Agh + kt*16);
        cp16(a + 24576, Agl + kt*16);
        u32 b = bWr + st*4352;
        cp16(b,         Bgh + (size_t)kt*16*N);
        if (PREC==0) cp16(b + 17408, Bgl + (size_t)kt*16*N);
        cp_commit();
    };

    const int nk = K/16;
    issue(0,0); issue(1,1); issue(2,2);

    for (int kt=0; kt<nk; kt++){
        if (kt+2 < nk)      cp_wait<2>();
        else if (kt+1 < nk) cp_wait<1>();
        else                cp_wait<0>();
        __syncthreads();
        const int st = kt & 3;

        u32 fah[4][4], fal[4][4];
        const u32 ab = aRd + st*6144;
        #pragma unroll
        for (int mi=0;mi<4;mi++){
            ldsm4(fah[mi][0],fah[mi][1],fah[mi][2],fah[mi][3], ab + mi*768);
            ldsm4(fal[mi][0],fal[mi][1],fal[mi][2],fal[mi][3], ab + mi*768 + 24576);
        }
        u32 fbh[4][2], fbl[4][2];
        const u32 bb2 = bRd + st*4352;
        #pragma unroll
        for (int p=0;p<2;p++){
            u32 r0,r1,r2,r3;
            ldsm4t(r0,r1,r2,r3, bb2 + p*32);
            fbh[2*p][0]=r0; fbh[2*p][1]=r1; fbh[2*p+1][0]=r2; fbh[2*p+1][1]=r3;
            if (PREC==0){
                ldsm4t(r0,r1,r2,r3, bb2 + p*32 + 17408);
                fbl[2*p][0]=r0; fbl[2*p][1]=r1; fbl[2*p+1][0]=r2; fbl[2*p+1][1]=r3;
            }
        }
        if (kt+3 < nk) issue(kt+3, (kt+3)&3);

        if (PREC==0){
            #pragma unroll
            for (int mi=0;mi<4;mi++)
                #pragma unroll
                for (int nj=0;nj<4;nj++)
                    mma16816(acc[mi][nj], fah[mi], fbh[nj]);
            #pragma unroll
            for (int mi=0;mi<4;mi++)
                #pragma unroll
                for (int nj=0;nj<4;nj++)
                    mma16816(acc[mi][nj], fah[mi], fbl[nj]);
            #pragma unroll
            for (int mi=0;mi<4;mi++)
                #pragma unroll
                for (int nj=0;nj<4;nj++)
                    mma16816(acc[mi][nj], fal[mi], fbh[nj]);
        } else {
            #pragma unroll
            for (int mi=0;mi<4;mi++)
                #pragma unroll
                for (int nj=0;nj<4;nj++)
                    mma16816h(acc[mi][nj], fah[mi], fbh[nj]);
            #pragma unroll
            for (int mi=0;mi<4;mi++)
                #pragma unroll
                for (int nj=0;nj<4;nj++)
                    mma16816h(acc[mi][nj], fal[mi], fbh[nj]);
        }
    }

    #pragma unroll
    for (int mi=0; mi<4; mi++){
        #pragma unroll
        for (int r=0; r<2; r++){
            int gm = bm + m_base + mi*16 + (lane>>2) + r*8;
            #pragma unroll
            for (int nj=0; nj<4; nj++){
                int gn = bn + n_base + nj*8 + (lane&3)*2;
                float v0 = acc[mi][nj][r*2+0];
                float v1 = acc[mi][nj][r*2+1];
                if (EPI != 3){ v0 += bias[gn]; v1 += bias[gn+1]; }
                if (EPI == 1){ v0 = geluf(v0); v1 = geluf(v1); }
                size_t base = (size_t)gm*N + gn;
                if (EPI == 2){
                    float2 rr = *(const float2*)(res + base);
                    *(float2*)((float*)Ca + base) = make_float2(v0+rr.x, v1+rr.y);
                } else if (EPI == 3){
                    *(float2*)((float*)Ca + base) = make_float2(v0, v1);
                } else {
                    u32 h_,l_;
                    if (PREC==1) split2h(v0, v1, h_, l_);
                    else         split2 (v0, v1, h_, l_);
                    *(u32*)((bf16*)Ca + base) = h_;
                    *(u32*)((bf16*)Cb + base) = l_;
                }
            }
        }
    }
}

// ---------------- tensor-core flash attention (bf16 3-pass, unchanged) ----------------
#define ATTN_SMEM 92160
__global__ void __launch_bounds__(128) k_attn(
    const bf16* __restrict__ Qh, const bf16* __restrict__ Ql,
    const bf16* __restrict__ Kh, const bf16* __restrict__ Kl,
    const bf16* __restrict__ Vh, const bf16* __restrict__ Vl,
    bf16* __restrict__ Oh, bf16* __restrict__ Ol)
{
    extern __shared__ __align__(16) bf16 sm[];
    bf16* sQh = sm;
    bf16* sKh = sm + 9216;
    bf16* sVh = sm + 27648;

    const int tid = threadIdx.x;
    const int lane = tid & 31;
    const int w = tid >> 5;
    const int qt = blockIdx.x;
    const int bh = blockIdx.y;
    const int bb = bh >> 4;
    const int hh = bh & 15;
    const int g  = lane >> 2;
    const int n2 = (lane & 3) * 2;
    const int q2 = lane >> 3;

    const size_t qrow0 = (size_t)bb*S_ + qt*64;
    const int col0 = hh*DK_;

    #pragma unroll
    for (int i=0;i<4;i++){
        int cid = tid + i*128;
        int r = cid >> 3, ch = (cid & 7)*8;
        size_t go = (qrow0 + r)*D_ + col0 + ch;
        u32 s = cvt_smem(sQh + r*72 + ch);
        cp16(s, Qh + go);
        cp16(s + 9216, Ql + go);
    }
    cp_commit();

    auto issueKV = [&](int kt, int st){
        #pragma unroll
        for (int i=0;i<4;i++){
            int cid = tid + i*128;
            int r = cid >> 3, ch = (cid & 7)*8;
            size_t go = ((size_t)bb*S_ + kt*64 + r)*D_ + col0 + ch;
            u32 s = cvt_smem(sKh + st*4608 + r*72 + ch);
            cp16(s,         Kh + go);
            cp16(s + 18432, Kl + go);
            cp16(s + 36864, Vh + go);
            cp16(s + 55296, Vl + go);
        }
        cp_commit();
    };

    issueKV(0, 0);
    cp_wait<1>();
    __syncthreads();
    u32 qfh[4][4], qfl[4][4];
    {
        u32 a = cvt_smem(sQh + (w*16 + (lane&15))*72 + (lane>>4)*8);
        #pragma unroll
        for (int ks=0; ks<4; ks++){
            ldsm4(qfh[ks][0],qfh[ks][1],qfh[ks][2],qfh[ks][3], a + ks*32);
            ldsm4(qfl[ks][0],qfl[ks][1],qfl[ks][2],qfl[ks][3], a + ks*32 + 9216);
        }
    }

    float m[2]    = {-1e30f, -1e30f};
    float lsum[2] = {0.f, 0.f};
    float oa[8][4];
    #pragma unroll
    for (int i=0;i<8;i++)
        #pragma unroll
        for (int j=0;j<4;j++) oa[i][j]=0.f;

    for (int kt=0; kt<=qt; kt++){
        const int st = kt & 1;
        if (kt+1 <= qt){ issueKV(kt+1, st^1); cp_wait<1>(); }
        else           { cp_wait<0>(); }
        __syncthreads();

        float s[8][4];
        #pragma unroll
        for (int nt=0;nt<8;nt++)
            #pragma unroll
            for (int j=0;j<4;j++) s[nt][j]=0.f;

        #pragma unroll
        for (int ks=0; ks<4; ks++){
            u32 kbh[8][2], kbl[8][2];
            #pragma unroll
            for (int pr=0; pr<4; pr++){
                u32 r0,r1,r2,r3;
                u32 a = cvt_smem(sKh + st*4608 + (pr*16 + (q2&1)*8 + (lane&7))*72 + (q2>>1)*8) + ks*32;
                ldsm4(r0,r1,r2,r3, a);
                kbh[2*pr][0]=r0; kbh[2*pr][1]=r2; kbh[2*pr+1][0]=r1; kbh[2*pr+1][1]=r3;
                ldsm4(r0,r1,r2,r3, a + 18432);
                kbl[2*pr][0]=r0; kbl[2*pr][1]=r2; kbl[2*pr+1][0]=r1; kbl[2*pr+1][1]=r3;
            }
            #pragma unroll
            for (int nt=0; nt<8; nt++) mma16816(s[nt], qfh[ks], kbh[nt]);
            #pragma unroll
            for (int nt=0; nt<8; nt++) mma16816(s[nt], qfh[ks], kbl[nt]);
            #pragma unroll
            for (int nt=0; nt<8; nt++) mma16816(s[nt], qfl[ks], kbh[nt]);
        }

        const bool diag = (kt == qt);
        #pragma unroll
        for (int nt=0;nt<8;nt++)
            #pragma unroll
            for (int j=0;j<4;j++){
                float v = s[nt][j]*0.125f;
                if (diag){
                    int col  = nt*8 + n2 + (j&1);
                    int rowl = w*16 + g + (j>>1)*8;
                    if (col > rowl) v = -1e30f;
                }
                s[nt][j] = v;
            }

        float mx0=-1e30f, mx1=-1e30f;
        #pragma unroll
        for (int nt=0;nt<8;nt++){
            mx0 = fmaxf(mx0, fmaxf(s[nt][0], s[nt][1]));
            mx1 = fmaxf(mx1, fmaxf(s[nt][2], s[nt][3]));
        }
        mx0 = fmaxf(mx0, __shfl_xor_sync(0xffffffffu, mx0, 1));
        mx0 = fmaxf(mx0, __shfl_xor_sync(0xffffffffu, mx0, 2));
        mx1 = fmaxf(mx1, __shfl_xor_sync(0xffffffffu, mx1, 1));
        mx1 = fmaxf(mx1, __shfl_xor_sync(0xffffffffu, mx1, 2));
        float mn0 = fmaxf(m[0], mx0), mn1 = fmaxf(m[1], mx1);
        float c0 = __expf(m[0]-mn0), c1 = __expf(m[1]-mn1);
        float ps0=0.f, ps1=0.f;
        #pragma unroll
        for (int nt=0;nt<8;nt++){
            s[nt][0] = __expf(s[nt][0]-mn0); ps0 += s[nt][0];
            s[nt][1] = __expf(s[nt][1]-mn0); ps0 += s[nt][1];
            s[nt][2] = __expf(s[nt][2]-mn1); ps1 += s[nt][2];
            s[nt][3] = __expf(s[nt][3]-mn1); ps1 += s[nt][3];
        }
        ps0 += __shfl_xor_sync(0xffffffffu, ps0, 1);
        ps0 += __shfl_xor_sync(0xffffffffu, ps0, 2);
        ps1 += __shfl_xor_sync(0xffffffffu, ps1, 1);
        ps1 += __shfl_xor_sync(0xffffffffu, ps1, 2);
        lsum[0] = lsum[0]*c0 + ps0;
        lsum[1] = lsum[1]*c1 + ps1;
        m[0] = mn0; m[1] = mn1;
        #pragma unroll
        for (int dt=0;dt<8;dt++){
            oa[dt][0]*=c0; oa[dt][1]*=c0; oa[dt][2]*=c1; oa[dt][3]*=c1;
        }

        #pragma unroll
        for (int ks=0; ks<4; ks++){
            u32 pfh[4], pfl[4];
            split2(s[2*ks  ][0], s[2*ks  ][1], pfh[0], pfl[0]);
            split2(s[2*ks  ][2], s[2*ks  ][3], pfh[1], pfl[1]);
            split2(s[2*ks+1][0], s[2*ks+1][1], pfh[2], pfl[2]);
            split2(s[2*ks+1][2], s[2*ks+1][3], pfh[3], pfl[3]);

            u32 vbh[8][2], vbl[8][2];
            #pragma unroll
            for (int dp=0; dp<4; dp++){
                u32 r0,r1,r2,r3;
                u32 a = cvt_smem(sVh + st*4608 + (ks*16 + (q2&1)*8 + (lane&7))*72 + dp*16 + (q2>>1)*8);
                ldsm4t(r0,r1,r2,r3, a);
                vbh[2*dp][0]=r0; vbh[2*dp][1]=r1; vbh[2*dp+1][0]=r2; vbh[2*dp+1][1]=r3;
                ldsm4t(r0,r1,r2,r3, a + 18432);
                vbl[2*dp][0]=r0; vbl[2*dp][1]=r1; vbl[2*dp+1][0]=r2; vbl[2*dp+1][1]=r3;
            }
            #pragma unroll
            for (int dt=0; dt<8; dt++) mma16816(oa[dt], pfh, vbh[dt]);
            #pragma unroll
            for (int dt=0; dt<8; dt++) mma16816(oa[dt], pfh, vbl[dt]);
            #pragma unroll
            for (int dt=0; dt<8; dt++) mma16816(oa[dt], pfl, vbh[dt]);
        }
        __syncthreads();
    }

    float inv0 = 1.0f/lsum[0], inv1 = 1.0f/lsum[1];
    size_t r0 = qrow0 + w*16 + g;
    size_t r1 = r0 + 8;
    #pragma unroll
    for (int dt=0; dt<8; dt++){
        int col = col0 + dt*8 + n2;
        u32 h_,l_;
        split2(oa[dt][0]*inv0, oa[dt][1]*inv0, h_, l_);
        *(u32*)(Oh + r0*D_ + col) = h_;
        *(u32*)(Ol + r0*D_ + col) = l_;
        split2(oa[dt][2]*inv1, oa[dt][3]*inv1, h_, l_);
        *(u32*)(Oh + r1*D_ + col) = h_;
        *(u32*)(Ol + r1*D_ + col) = l_;
    }
}

extern "C" void kernel_launch(void* const* d_in, const int* in_sizes, int n_in,
                              void* d_out, int out_size)
{
    (void)in_sizes; (void)n_in; (void)out_size;
    const int*   ids  = (const int*)  d_in[0];
    const float* emb  = (const float*)d_in[1];
    const float* wq   = (const float*)d_in[2];
    const float* bq   = (const float*)d_in[3];
    const float* wk   = (const float*)d_in[4];
    const float* bk   = (const float*)d_in[5];
    const float* wv   = (const float*)d_in[6];
    const float* bv   = (const float*)d_in[7];
    const float* wo   = (const float*)d_in[8];
    const float* bo   = (const float*)d_in[9];
    const float* ln1g = (const float*)d_in[10];
    const float* ln1b = (const float*)d_in[11];
    const float* ln2g = (const float*)d_in[12];
    const float* ln2b = (const float*)d_in[13];
    const float* w1   = (const float*)d_in[14];
    const float* b1   = (const float*)d_in[15];
    const float* w2   = (const float*)d_in[16];
    const float* b2   = (const float*)d_in[17];
    const float* lnfg = (const float*)d_in[18];
    const float* lnfb = (const float*)d_in[19];
    float* out = (float*)d_out;

    cudaFuncSetAttribute((const void*)k_gemm<0,0>, cudaFuncAttributeMaxDynamicSharedMemorySize, GEMM_SMEM);
    cudaFuncSetAttribute((const void*)k_gemm<2,0>, cudaFuncAttributeMaxDynamicSharedMemorySize, GEMM_SMEM);
    cudaFuncSetAttribute((const void*)k_gemm<1,1>, cudaFuncAttributeMaxDynamicSharedMemorySize, GEMM_SMEM);
    cudaFuncSetAttribute((const void*)k_gemm<2,1>, cudaFuncAttributeMaxDynamicSharedMemorySize, GEMM_SMEM);
    cudaFuncSetAttribute((const void*)k_gemm<3,1>, cudaFuncAttributeMaxDynamicSharedMemorySize, GEMM_SMEM);
    cudaFuncSetAttribute((const void*)k_attn,      cudaFuncAttributeMaxDynamicSharedMemorySize, ATTN_SMEM);

    float* px;  cudaGetSymbolAddress((void**)&px,  g_x);
    bf16 *hh,*hl,*qh,*ql,*kh,*kl,*vh,*vl,*ah,*al,*fh,*fl;
    cudaGetSymbolAddress((void**)&hh, g_h_h); cudaGetSymbolAddress((void**)&hl, g_h_l);
    cudaGetSymbolAddress((void**)&qh, g_q_h); cudaGetSymbolAddress((void**)&ql, g_q_l);
    cudaGetSymbolAddress((void**)&kh, g_k_h); cudaGetSymbolAddress((void**)&kl, g_k_l);
    cudaGetSymbolAddress((void**)&vh, g_v_h); cudaGetSymbolAddress((void**)&vl, g_v_l);
    cudaGetSymbolAddress((void**)&ah, g_a_h); cudaGetSymbolAddress((void**)&al, g_a_l);
    cudaGetSymbolAddress((void**)&fh, g_f_h); cudaGetSymbolAddress((void**)&fl, g_f_l);
    bf16 *wqh,*wql,*wkh,*wkl,*wvh,*wvl,*woh,*wol,*w1h,*w2h,*eth;
    cudaGetSymbolAddress((void**)&wqh, g_wq_h); cudaGetSymbolAddress((void**)&wql, g_wq_l);
    cudaGetSymbolAddress((void**)&wkh, g_wk_h); cudaGetSymbolAddress((void**)&wkl, g_wk_l);
    cudaGetSymbolAddress((void**)&wvh, g_wv_h); cudaGetSymbolAddress((void**)&wvl, g_wv_l);
    cudaGetSymbolAddress((void**)&woh, g_wo_h); cudaGetSymbolAddress((void**)&wol, g_wo_l);
    cudaGetSymbolAddress((void**)&w1h, g_w1_h);
    cudaGetSymbolAddress((void**)&w2h, g_w2_h);
    cudaGetSymbolAddress((void**)&eth, g_et_h);

    {
        int nA = L_*D_*D_/4;
        k_cvt<<<(nA+255)/256,256>>>((const float4*)wq, (uint2*)wqh, (uint2*)wql, nA);
        k_cvt<<<(nA+255)/256,256>>>((const float4*)wk, (uint2*)wkh, (uint2*)wkl, nA);
        k_cvt<<<(nA+255)/256,256>>>((const float4*)wv, (uint2*)wvh, (uint2*)wvl, nA);
        k_cvt<<<(nA+255)/256,256>>>((const float4*)wo, (uint2*)woh, (uint2*)wol, nA);
        int nF = L_*D_*F_/4;
        k_cvt_h<<<(nF+255)/256,256>>>((const float4*)w1, (uint2*)w1h, nF);
        k_cvt_h<<<(nF+255)/256,256>>>((const float4*)w2, (uint2*)w2h, nF);
        k_cvt_t_h<<<dim3(V_/32, D_/32), dim3(32,8)>>>(emb, (__half*)eth);
    }

    k_embed<<<(M_*D_+255)/256, 256>>>(ids, emb, px);

    for (int l=0; l<L_; l++){
        size_t odd = (size_t)l*D_*D_;
        size_t off = (size_t)l*D_*F_;
        k_ln<0><<<M_,256>>>(px, ln1g+l*D_, ln1b+l*D_, hh, hl);
        k_gemm<0,0><<<dim3(D_/BN, M_/BM, 3),256,GEMM_SMEM>>>(D_, D_, hh, hl,
            wqh+odd, wql+odd, wkh+odd, wkl+odd, wvh+odd, wvl+odd,
            bq+l*D_, bk+l*D_, bv+l*D_,
            nullptr, qh, ql, kh, kl, vh, vl);
        k_attn<<<dim3(S_/64, B_*H_),128,ATTN_SMEM>>>(qh, ql, kh, kl, vh, vl, ah, al);
        k_gemm<2,0><<<dim3(D_/BN, M_/BM, 1),256,GEMM_SMEM>>>(D_, D_, ah, al,
            woh+odd, wol+odd, woh+odd, wol+odd, woh+odd, wol+odd,
            bo+l*D_, bo+l*D_, bo+l*D_,
            px, px, nullptr, px, nullptr, px, nullptr);
        k_ln<1><<<M_,256>>>(px, ln2g+l*D_, ln2b+l*D_, hh, hl);
        k_gemm<1,1><<<dim3(F_/BN, M_/BM, 1),256,GEMM_SMEM>>>(F_, D_, hh, hl,
            w1h+off, nullptr, w1h+off, nullptr, w1h+off, nullptr,
            b1+l*F_, b1+l*F_, b1+l*F_,
            nullptr, fh, fl, fh, fl, fh, fl);
        k_gemm<2,1><<<dim3(D_/BN, M_/BM, 1),256,GEMM_SMEM>>>(D_, F_, fh, fl,
            w2h+off, nullptr, w2h+off, nullptr, w2h+off, nullptr,
            b2+l*D_, b2+l*D_, b2+l*D_,
            px, px, nullptr, px, nullptr, px, nullptr);
    }
    k_ln<1><<<M_,256>>>(px, lnfg, lnfb, hh, hl);
    k_gemm<3,1><<<dim3(V_/BN, M_/BM, 1),256,GEMM_SMEM>>>(V_, D_, hh, hl,
        eth, nullptr, eth, nullptr, eth, nullptr,
        nullptr, nullptr, nullptr,
        nullptr, out, nullptr, out, nullptr, out, nullptr);
}

// round 16
// speedup vs baseline: 6.3891x; 1.1235x over previous
#include <cuda_runtime.h>
#include <cuda_bf16.h>
#include <cuda_fp16.h>
#include <cstdint>
#include <math.h>

typedef unsigned int u32;
typedef __nv_bfloat16 bf16;   // storage type for 16-bit words (fp16 bit patterns)

#define B_  2
#define S_  1024
#define D_  1024
#define H_  16
#define F_  4096
#define L_  6
#define V_  32000
#define DK_ 64
#define M_  (B_*S_)

#define BM 128
#define BN 128

__device__ __align__(16) float g_x [M_*D_];
__device__ __align__(16) bf16 g_h_h[M_*D_],  g_h_l[M_*D_];
__device__ __align__(16) bf16 g_q_h[M_*D_],  g_q_l[M_*D_];
__device__ __align__(16) bf16 g_k_h[M_*D_],  g_k_l[M_*D_];
__device__ __align__(16) bf16 g_v_h[M_*D_],  g_v_l[M_*D_];
__device__ __align__(16) bf16 g_a_h[M_*D_],  g_a_l[M_*D_];
__device__ __align__(16) bf16 g_f_h[M_*F_],  g_f_l[M_*F_];
__device__ __align__(16) bf16 g_wq_h[L_*D_*D_];
__device__ __align__(16) bf16 g_wk_h[L_*D_*D_];
__device__ __align__(16) bf16 g_wv_h[L_*D_*D_];
__device__ __align__(16) bf16 g_wo_h[L_*D_*D_];
__device__ __align__(16) bf16 g_w1_h[L_*D_*F_];
__device__ __align__(16) bf16 g_w2_h[L_*F_*D_];
__device__ __align__(16) bf16 g_et_h[(size_t)D_*V_];

__device__ __forceinline__ u32 cvt_smem(const void* p){
    return (u32)__cvta_generic_to_shared(p);
}
__device__ __forceinline__ void cp16(u32 s, const void* g){
    asm volatile("cp.async.cg.shared.global [%0],[%1],16;\n"::"r"(s),"l"(g));
}
__device__ __forceinline__ void cp_commit(){ asm volatile("cp.async.commit_group;\n"::); }
template<int NN> __device__ __forceinline__ void cp_wait(){
    asm volatile("cp.async.wait_group %0;\n"::"n"(NN));
}
__device__ __forceinline__ void ldsm4(u32 &r0,u32 &r1,u32 &r2,u32 &r3, u32 a){
    asm volatile("ldmatrix.sync.aligned.m8n8.x4.shared.b16 {%0,%1,%2,%3},[%4];\n"
        : "=r"(r0),"=r"(r1),"=r"(r2),"=r"(r3) : "r"(a));
}
__device__ __forceinline__ void ldsm4t(u32 &r0,u32 &r1,u32 &r2,u32 &r3, u32 a){
    asm volatile("ldmatrix.sync.aligned.m8n8.x4.trans.shared.b16 {%0,%1,%2,%3},[%4];\n"
        : "=r"(r0),"=r"(r1),"=r"(r2),"=r"(r3) : "r"(a));
}
__device__ __forceinline__ void mma16816h(float* c, const u32* a, const u32* b){
    asm volatile("mma.sync.aligned.m16n8k16.row.col.f32.f16.f16.f32 "
        "{%0,%1,%2,%3},{%4,%5,%6,%7},{%8,%9},{%0,%1,%2,%3};\n"
        : "+f"(c[0]),"+f"(c[1]),"+f"(c[2]),"+f"(c[3])
        : "r"(a[0]),"r"(a[1]),"r"(a[2]),"r"(a[3]),"r"(b[0]),"r"(b[1]));
}
__device__ __forceinline__ u32 pack2h(__half h0, __half h1){
    unsigned short u0 = *reinterpret_cast<unsigned short*>(&h0);
    unsigned short u1 = *reinterpret_cast<unsigned short*>(&h1);
    return (u32)u0 | ((u32)u1 << 16);
}
__device__ __forceinline__ void split2h(float x0, float x1, u32 &hi, u32 &lo){
    __half h0 = __float2half_rn(x0);
    __half h1 = __float2half_rn(x1);
    float f0 = __half2float(h0), f1 = __half2float(h1);
    hi = pack2h(h0, h1);
    lo = pack2h(__float2half_rn(x0 - f0), __float2half_rn(x1 - f1));
}
__device__ __forceinline__ float geluf(float x){
    return 0.5f*x*(1.0f + erff(x*0.7071067811865476f));
}

// fp16 hi-only weight conversion
__global__ void k_cvt_h(const float4* __restrict__ src, uint2* __restrict__ dh, int n4)
{
    int i = blockIdx.x*256 + threadIdx.x;
    if (i >= n4) return;
    float4 v = src[i];
    dh[i] = make_uint2(pack2h(__float2half_rn(v.x), __float2half_rn(v.y)),
                       pack2h(__float2half_rn(v.z), __float2half_rn(v.w)));
}
// emb [V][D] fp32 -> emb^T [D][V] fp16
__global__ void k_cvt_t_h(const float* __restrict__ src, __half* __restrict__ dh)
{
    __shared__ float t[32][33];
    int v0 = blockIdx.x*32, d0 = blockIdx.y*32;
    int tx = threadIdx.x, ty = threadIdx.y;   // 32 x 8
    #pragma unroll
    for (int i=0;i<4;i++)
        t[ty+8*i][tx] = src[(size_t)(v0+ty+8*i)*D_ + d0 + tx];
    __syncthreads();
    #pragma unroll
    for (int i=0;i<4;i++){
        int dy = ty + 8*i;
        dh[(size_t)(d0+dy)*V_ + v0 + tx] = __float2half_rn(t[tx][dy]);
    }
}

__global__ void k_embed(const int* __restrict__ ids, const float* __restrict__ emb,
                        float* __restrict__ x)
{
    int idx = blockIdx.x * 256 + threadIdx.x;
    if (idx >= M_*D_) return;
    int d  = idx & (D_-1);
    int ms = idx >> 10;
    int s  = ms & (S_-1);
    int tok = ids[ms];
    int i2 = d & ~1;
    float freq = expf((float)i2 * (-9.210340371976184f / (float)D_));
    float ang  = (float)s * freq;
    float pe   = (d & 1) ? cosf(ang) : sinf(ang);
    x[idx] = emb[tok*D_ + d] * 32.0f + pe;
}

__global__ void __launch_bounds__(256) k_ln(const float* __restrict__ x,
                                            const float* __restrict__ g,
                                            const float* __restrict__ b,
                                            bf16* __restrict__ oh,
                                            bf16* __restrict__ ol)
{
    int row = blockIdx.x;
    int t = threadIdx.x;
    float4 v = ((const float4*)(x + (size_t)row*D_))[t];
    float s  = v.x+v.y+v.z+v.w;
    float ss = v.x*v.x+v.y*v.y+v.z*v.z+v.w*v.w;
    #pragma unroll
    for (int o=16;o>0;o>>=1){
        s  += __shfl_xor_sync(0xffffffffu, s,  o);
        ss += __shfl_xor_sync(0xffffffffu, ss, o);
    }
    __shared__ float rs[8], rss[8];
    if ((t&31)==0){ rs[t>>5]=s; rss[t>>5]=ss; }
    __syncthreads();
    float tot=0.f, tot2=0.f;
    #pragma unroll
    for (int i=0;i<8;i++){ tot += rs[i]; tot2 += rss[i]; }
    float mean = tot * (1.0f/D_);
    float var  = tot2 * (1.0f/D_) - mean*mean;
    float rstd = rsqrtf(var + 1e-5f);
    float4 gv = ((const float4*)g)[t];
    float4 bv = ((const float4*)b)[t];
    float o0=(v.x-mean)*rstd*gv.x+bv.x, o1=(v.y-mean)*rstd*gv.y+bv.y;
    float o2=(v.z-mean)*rstd*gv.z+bv.z, o3=(v.w-mean)*rstd*gv.w+bv.w;
    u32 h0,l0,h1,l1;
    split2h(o0,o1,h0,l0); split2h(o2,o3,h1,l1);
    ((uint2*)(oh + (size_t)row*D_))[t] = make_uint2(h0,h1);
    ((uint2*)(ol + (size_t)row*D_))[t] = make_uint2(l0,l1);
}

// ---------------- fp16 2-pass tensor-core GEMM (Ah.Bh + Al.Bh), 4-stage pipeline ----------------
// smem (elems): sAh 4st x 128x24 = 12288 ; sAl +12288 (byte +24576) ; sBh @24576, 4st x 16x136 = 8704
// EPI: 0 = +bias -> fp16 split, 1 = gelu(+bias) -> fp16 split, 2 = +bias+res -> fp32, 3 = plain fp32
#define GEMM_SMEM 66560
template<int EPI>
__global__ void __launch_bounds__(256) k_gemm(
    int N, int K,
    const bf16* __restrict__ Ah, const bf16* __restrict__ Al,
    const bf16* Bh0, const bf16* Bh1, const bf16* Bh2,
    const float* bias0, const float* bias1, const float* bias2,
    const float* __restrict__ res,
    void* C0a, void* C0b, void* C1a, void* C1b, void* C2a, void* C2b)
{
    extern __shared__ __align__(16) bf16 sm[];
    bf16* sAh = sm;
    bf16* sBh = sm + 24576;

    const int z = blockIdx.z;
    const bf16* Bh = (z==0)?Bh0:((z==1)?Bh1:Bh2);
    const float* bias = (z==0)?bias0:((z==1)?bias1:bias2);
    void* Ca = (z==0)?C0a:((z==1)?C1a:C2a);
    void* Cb = (z==0)?C0b:((z==1)?C1b:C2b);

    const int tid = threadIdx.x;
    const int lane = tid & 31, wid = tid>>5;
    const int m_base = (wid&1)*64, n_base = (wid>>1)*32;
    const int bm = blockIdx.y*BM, bn = blockIdx.x*BN;

    const int ar = tid>>1, ac = (tid&1)*8;
    const int br = tid>>4, bc = (tid&15)*8;
    const bf16* Agh = Ah + (size_t)(bm+ar)*K + ac;
    const bf16* Agl = Al + (size_t)(bm+ar)*K + ac;
    const bf16* Bgh = Bh + (size_t)br*N + bn + bc;

    const u32 aWr = cvt_smem(sAh + ar*24 + ac);
    const u32 bWr = cvt_smem(sBh + br*136 + bc);

    const int q2 = lane>>3;
    const u32 aRd = cvt_smem(sAh + (m_base + (lane&15))*24 + (lane>>4)*8);
    const u32 bRd = cvt_smem(sBh + ((q2&1)*8 + (lane&7))*136 + n_base + (q2>>1)*8);

    float acc[4][4][4];
    #pragma unroll
    for (int i=0;i<4;i++)
        #pragma unroll
        for (int j=0;j<4;j++)
            #pragma unroll
            for (int r=0;r<4;r++) acc[i][j][r]=0.f;

    auto issue = [&](int kt, int st){
        u32 a = aWr + st*6144;
        cp16(a,         Agh + kt*16);
        cp16(a + 24576, Agl + kt*16);
        cp16(bWr + st*4352, Bgh + (size_t)kt*16*N);
        cp_commit();
    };

    const int nk = K/16;
    issue(0,0); issue(1,1); issue(2,2);

    for (int kt=0; kt<nk; kt++){
        if (kt+2 < nk)      cp_wait<2>();
        else if (kt+1 < nk) cp_wait<1>();
        else                cp_wait<0>();
        __syncthreads();
        const int st = kt & 3;

        u32 fah[4][4], fal[4][4];
        const u32 ab = aRd + st*6144;
        #pragma unroll
        for (int mi=0;mi<4;mi++){
            ldsm4(fah[mi][0],fah[mi][1],fah[mi][2],fah[mi][3], ab + mi*768);
            ldsm4(fal[mi][0],fal[mi][1],fal[mi][2],fal[mi][3], ab + mi*768 + 24576);
        }
        u32 fbh[4][2];
        const u32 bb2 = bRd + st*4352;
        #pragma unroll
        for (int p=0;p<2;p++){
            u32 r0,r1,r2,r3;
            ldsm4t(r0,r1,r2,r3, bb2 + p*32);
            fbh[2*p][0]=r0; fbh[2*p][1]=r1; fbh[2*p+1][0]=r2; fbh[2*p+1][1]=r3;
        }
        if (kt+3 < nk) issue(kt+3, (kt+3)&3);

        #pragma unroll
        for (int mi=0;mi<4;mi++)
            #pragma unroll
            for (int nj=0;nj<4;nj++)
                mma16816h(acc[mi][nj], fah[mi], fbh[nj]);
        #pragma unroll
        for (int mi=0;mi<4;mi++)
            #pragma unroll
            for (int nj=0;nj<4;nj++)
                mma16816h(acc[mi][nj], fal[mi], fbh[nj]);
    }

    #pragma unroll
    for (int mi=0; mi<4; mi++){
        #pragma unroll
        for (int r=0; r<2; r++){
            int gm = bm + m_base + mi*16 + (lane>>2) + r*8;
            #pragma unroll
            for (int nj=0; nj<4; nj++){
                int gn = bn + n_base + nj*8 + (lane&3)*2;
                float v0 = acc[mi][nj][r*2+0];
                float v1 = acc[mi][nj][r*2+1];
                if (EPI != 3){ v0 += bias[gn]; v1 += bias[gn+1]; }
                if (EPI == 1){ v0 = geluf(v0); v1 = geluf(v1); }
                size_t base = (size_t)gm*N + gn;
                if (EPI == 2){
                    float2 rr = *(const float2*)(res + base);
                    *(float2*)((float*)Ca + base) = make_float2(v0+rr.x, v1+rr.y);
                } else if (EPI == 3){
                    *(float2*)((float*)Ca + base) = make_float2(v0, v1);
                } else {
                    u32 h_,l_;
                    split2h(v0, v1, h_, l_);
                    *(u32*)((bf16*)Ca + base) = h_;
                    *(u32*)((bf16*)Cb + base) = l_;
                }
            }
        }
    }
}

// ---------------- fp16 2-pass flash attention, K/V hi-only, 2-stage pipeline ----------------
// smem (elems): sQh @0 (4608), sQl @4608, sKh @9216 (2st x 4608), sVh @18432 (2st x 4608)
#define ATTN_SMEM 55296
__global__ void __launch_bounds__(128) k_attn(
    const bf16* __restrict__ Qh, const bf16* __restrict__ Ql,
    const bf16* __restrict__ Kh, const bf16* __restrict__ Vh,
    bf16* __restrict__ Oh, bf16* __restrict__ Ol)
{
    extern __shared__ __align__(16) bf16 sm[];
    bf16* sQh = sm;
    bf16* sKh = sm + 9216;
    bf16* sVh = sm + 18432;

    const int tid = threadIdx.x;
    const int lane = tid & 31;
    const int w = tid >> 5;
    const int qt = blockIdx.x;
    const int bh = blockIdx.y;
    const int bb = bh >> 4;
    const int hh = bh & 15;
    const int g  = lane >> 2;
    const int n2 = (lane & 3) * 2;
    const int q2 = lane >> 3;

    const size_t qrow0 = (size_t)bb*S_ + qt*64;
    const int col0 = hh*DK_;

    #pragma unroll
    for (int i=0;i<4;i++){
        int cid = tid + i*128;
        int r = cid >> 3, ch = (cid & 7)*8;
        size_t go = (qrow0 + r)*D_ + col0 + ch;
        u32 s = cvt_smem(sQh + r*72 + ch);
        cp16(s, Qh + go);
        cp16(s + 9216, Ql + go);
    }
    cp_commit();

    auto issueKV = [&](int kt, int st){
        #pragma unroll
        for (int i=0;i<4;i++){
            int cid = tid + i*128;
            int r = cid >> 3, ch = (cid & 7)*8;
            size_t go = ((size_t)bb*S_ + kt*64 + r)*D_ + col0 + ch;
            u32 s = cvt_smem(sKh + st*4608 + r*72 + ch);
            cp16(s,         Kh + go);
            cp16(s + 18432, Vh + go);
        }
        cp_commit();
    };

    issueKV(0, 0);
    cp_wait<1>();
    __syncthreads();
    u32 qfh[4][4], qfl[4][4];
    {
        u32 a = cvt_smem(sQh + (w*16 + (lane&15))*72 + (lane>>4)*8);
        #pragma unroll
        for (int ks=0; ks<4; ks++){
            ldsm4(qfh[ks][0],qfh[ks][1],qfh[ks][2],qfh[ks][3], a + ks*32);
            ldsm4(qfl[ks][0],qfl[ks][1],qfl[ks][2],qfl[ks][3], a + ks*32 + 9216);
        }
    }

    float m[2]    = {-1e30f, -1e30f};
    float lsum[2] = {0.f, 0.f};
    float oa[8][4];
    #pragma unroll
    for (int i=0;i<8;i++)
        #pragma unroll
        for (int j=0;j<4;j++) oa[i][j]=0.f;

    for (int kt=0; kt<=qt; kt++){
        const int st = kt & 1;
        if (kt+1 <= qt){ issueKV(kt+1, st^1); cp_wait<1>(); }
        else           { cp_wait<0>(); }
        __syncthreads();

        float s[8][4];
        #pragma unroll
        for (int nt=0;nt<8;nt++)
            #pragma unroll
            for (int j=0;j<4;j++) s[nt][j]=0.f;

        #pragma unroll
        for (int ks=0; ks<4; ks++){
            u32 kbh[8][2];
            #pragma unroll
            for (int pr=0; pr<4; pr++){
                u32 r0,r1,r2,r3;
                u32 a = cvt_smem(sKh + st*4608 + (pr*16 + (q2&1)*8 + (lane&7))*72 + (q2>>1)*8) + ks*32;
                ldsm4(r0,r1,r2,r3, a);
                kbh[2*pr][0]=r0; kbh[2*pr][1]=r2; kbh[2*pr+1][0]=r1; kbh[2*pr+1][1]=r3;
            }
            #pragma unroll
            for (int nt=0; nt<8; nt++) mma16816h(s[nt], qfh[ks], kbh[nt]);
            #pragma unroll
            for (int nt=0; nt<8; nt++) mma16816h(s[nt], qfl[ks], kbh[nt]);
        }

        const bool diag = (kt == qt);
        #pragma unroll
        for (int nt=0;nt<8;nt++)
            #pragma unroll
            for (int j=0;j<4;j++){
                float v = s[nt][j]*0.125f;
                if (diag){
                    int col  = nt*8 + n2 + (j&1);
                    int rowl = w*16 + g + (j>>1)*8;
                    if (col > rowl) v = -1e30f;
                }
                s[nt][j] = v;
            }

        float mx0=-1e30f, mx1=-1e30f;
        #pragma unroll
        for (int nt=0;nt<8;nt++){
            mx0 = fmaxf(mx0, fmaxf(s[nt][0], s[nt][1]));
            mx1 = fmaxf(mx1, fmaxf(s[nt][2], s[nt][3]));
        }
        mx0 = fmaxf(mx0, __shfl_xor_sync(0xffffffffu, mx0, 1));
        mx0 = fmaxf(mx0, __shfl_xor_sync(0xffffffffu, mx0, 2));
        mx1 = fmaxf(mx1, __shfl_xor_sync(0xffffffffu, mx1, 1));
        mx1 = fmaxf(mx1, __shfl_xor_sync(0xffffffffu, mx1, 2));
        float mn0 = fmaxf(m[0], mx0), mn1 = fmaxf(m[1], mx1);
        float c0 = __expf(m[0]-mn0), c1 = __expf(m[1]-mn1);
        float ps0=0.f, ps1=0.f;
        #pragma unroll
        for (int nt=0;nt<8;nt++){
            s[nt][0] = __expf(s[nt][0]-mn0); ps0 += s[nt][0];
            s[nt][1] = __expf(s[nt][1]-mn0); ps0 += s[nt][1];
            s[nt][2] = __expf(s[nt][2]-mn1); ps1 += s[nt][2];
            s[nt][3] = __expf(s[nt][3]-mn1); ps1 += s[nt][3];
        }
        ps0 += __shfl_xor_sync(0xffffffffu, ps0, 1);
        ps0 += __shfl_xor_sync(0xffffffffu, ps0, 2);
        ps1 += __shfl_xor_sync(0xffffffffu, ps1, 1);
        ps1 += __shfl_xor_sync(0xffffffffu, ps1, 2);
        lsum[0] = lsum[0]*c0 + ps0;
        lsum[1] = lsum[1]*c1 + ps1;
        m[0] = mn0; m[1] = mn1;
        #pragma unroll
        for (int dt=0;dt<8;dt++){
            oa[dt][0]*=c0; oa[dt][1]*=c0; oa[dt][2]*=c1; oa[dt][3]*=c1;
        }

        #pragma unroll
        for (int ks=0; ks<4; ks++){
            u32 pfh[4], pfl[4];
            split2h(s[2*ks  ][0], s[2*ks  ][1], pfh[0], pfl[0]);
            split2h(s[2*ks  ][2], s[2*ks  ][3], pfh[1], pfl[1]);
            split2h(s[2*ks+1][0], s[2*ks+1][1], pfh[2], pfl[2]);
            split2h(s[2*ks+1][2], s[2*ks+1][3], pfh[3], pfl[3]);

            u32 vbh[8][2];
            #pragma unroll
            for (int dp=0; dp<4; dp++){
                u32 r0,r1,r2,r3;
                u32 a = cvt_smem(sVh + st*4608 + (ks*16 + (q2&1)*8 + (lane&7))*72 + dp*16 + (q2>>1)*8);
                ldsm4t(r0,r1,r2,r3, a);
                vbh[2*dp][0]=r0; vbh[2*dp][1]=r1; vbh[2*dp+1][0]=r2; vbh[2*dp+1][1]=r3;
            }
            #pragma unroll
            for (int dt=0; dt<8; dt++) mma16816h(oa[dt], pfh, vbh[dt]);
            #pragma unroll
            for (int dt=0; dt<8; dt++) mma16816h(oa[dt], pfl, vbh[dt]);
        }
        __syncthreads();
    }

    float inv0 = 1.0f/lsum[0], inv1 = 1.0f/lsum[1];
    size_t r0 = qrow0 + w*16 + g;
    size_t r1 = r0 + 8;
    #pragma unroll
    for (int dt=0; dt<8; dt++){
        int col = col0 + dt*8 + n2;
        u32 h_,l_;
        split2h(oa[dt][0]*inv0, oa[dt][1]*inv0, h_, l_);
        *(u32*)(Oh + r0*D_ + col) = h_;
        *(u32*)(Ol + r0*D_ + col) = l_;
        split2h(oa[dt][2]*inv1, oa[dt][3]*inv1, h_, l_);
        *(u32*)(Oh + r1*D_ + col) = h_;
        *(u32*)(Ol + r1*D_ + col) = l_;
    }
}

extern "C" void kernel_launch(void* const* d_in, const int* in_sizes, int n_in,
                              void* d_out, int out_size)
{
    (void)in_sizes; (void)n_in; (void)out_size;
    const int*   ids  = (const int*)  d_in[0];
    const float* emb  = (const float*)d_in[1];
    const float* wq   = (const float*)d_in[2];
    const float* bq   = (const float*)d_in[3];
    const float* wk   = (const float*)d_in[4];
    const float* bk   = (const float*)d_in[5];
    const float* wv   = (const float*)d_in[6];
    const float* bv   = (const float*)d_in[7];
    const float* wo   = (const float*)d_in[8];
    const float* bo   = (const float*)d_in[9];
    const float* ln1g = (const float*)d_in[10];
    const float* ln1b = (const float*)d_in[11];
    const float* ln2g = (const float*)d_in[12];
    const float* ln2b = (const float*)d_in[13];
    const float* w1   = (const float*)d_in[14];
    const float* b1   = (const float*)d_in[15];
    const float* w2   = (const float*)d_in[16];
    const float* b2   = (const float*)d_in[17];
    const float* lnfg = (const float*)d_in[18];
    const float* lnfb = (const float*)d_in[19];
    float* out = (float*)d_out;

    cudaFuncSetAttribute((const void*)k_gemm<0>, cudaFuncAttributeMaxDynamicSharedMemorySize, GEMM_SMEM);
    cudaFuncSetAttribute((const void*)k_gemm<1>, cudaFuncAttributeMaxDynamicSharedMemorySize, GEMM_SMEM);
    cudaFuncSetAttribute((const void*)k_gemm<2>, cudaFuncAttributeMaxDynamicSharedMemorySize, GEMM_SMEM);
    cudaFuncSetAttribute((const void*)k_gemm<3>, cudaFuncAttributeMaxDynamicSharedMemorySize, GEMM_SMEM);
    cudaFuncSetAttribute((const void*)k_attn,    cudaFuncAttributeMaxDynamicSharedMemorySize, ATTN_SMEM);

    float* px;  cudaGetSymbolAddress((void**)&px,  g_x);
    bf16 *hh,*hl,*qh,*ql,*kh,*kl,*vh,*vl,*ah,*al,*fh,*fl;
    cudaGetSymbolAddress((void**)&hh, g_h_h); cudaGetSymbolAddress((void**)&hl, g_h_l);
    cudaGetSymbolAddress((void**)&qh, g_q_h); cudaGetSymbolAddress((void**)&ql, g_q_l);
    cudaGetSymbolAddress((void**)&kh, g_k_h); cudaGetSymbolAddress((void**)&kl, g_k_l);
    cudaGetSymbolAddress((void**)&vh, g_v_h); cudaGetSymbolAddress((void**)&vl, g_v_l);
    cudaGetSymbolAddress((void**)&ah, g_a_h); cudaGetSymbolAddress((void**)&al, g_a_l);
    cudaGetSymbolAddress((void**)&fh, g_f_h); cudaGetSymbolAddress((void**)&fl, g_f_l);
    bf16 *wqh,*wkh,*wvh,*woh,*w1h,*w2h,*eth;
    cudaGetSymbolAddress((void**)&wqh, g_wq_h);
    cudaGetSymbolAddress((void**)&wkh, g_wk_h);
    cudaGetSymbolAddress((void**)&wvh, g_wv_h);
    cudaGetSymbolAddress((void**)&woh, g_wo_h);
    cudaGetSymbolAddress((void**)&w1h, g_w1_h);
    cudaGetSymbolAddress((void**)&w2h, g_w2_h);
    cudaGetSymbolAddress((void**)&eth, g_et_h);

    {
        int nA = L_*D_*D_/4;
        k_cvt_h<<<(nA+255)/256,256>>>((const float4*)wq, (uint2*)wqh, nA);
        k_cvt_h<<<(nA+255)/256,256>>>((const float4*)wk, (uint2*)wkh, nA);
        k_cvt_h<<<(nA+255)/256,256>>>((const float4*)wv, (uint2*)wvh, nA);
        k_cvt_h<<<(nA+255)/256,256>>>((const float4*)wo, (uint2*)woh, nA);
        int nF = L_*D_*F_/4;
        k_cvt_h<<<(nF+255)/256,256>>>((const float4*)w1, (uint2*)w1h, nF);
        k_cvt_h<<<(nF+255)/256,256>>>((const float4*)w2, (uint2*)w2h, nF);
        k_cvt_t_h<<<dim3(V_/32, D_/32), dim3(32,8)>>>(emb, (__half*)eth);
    }

    k_embed<<<(M_*D_+255)/256, 256>>>(ids, emb, px);

    for (int l=0; l<L_; l++){
        size_t odd = (size_t)l*D_*D_;
        size_t off = (size_t)l*D_*F_;
        k_ln<<<M_,256>>>(px, ln1g+l*D_, ln1b+l*D_, hh, hl);
        k_gemm<0><<<dim3(D_/BN, M_/BM, 3),256,GEMM_SMEM>>>(D_, D_, hh, hl,
            wqh+odd, wkh+odd, wvh+odd,
            bq+l*D_, bk+l*D_, bv+l*D_,
            nullptr, qh, ql, kh, kl, vh, vl);
        k_attn<<<dim3(S_/64, B_*H_),128,ATTN_SMEM>>>(qh, ql, kh, vh, ah, al);
        k_gemm<2><<<dim3(D_/BN, M_/BM, 1),256,GEMM_SMEM>>>(D_, D_, ah, al,
            woh+odd, woh+odd, woh+odd,
            bo+l*D_, bo+l*D_, bo+l*D_,
            px, px, nullptr, px, nullptr, px, nullptr);
        k_ln<<<M_,256>>>(px, ln2g+l*D_, ln2b+l*D_, hh, hl);
        k_gemm<1><<<dim3(F_/BN, M_/BM, 1),256,GEMM_SMEM>>>(F_, D_, hh, hl,
            w1h+off, w1h+off, w1h+off,
            b1+l*F_, b1+l*F_, b1+l*F_,
            nullptr, fh, fl, fh, fl, fh, fl);
        k_gemm<2><<<dim3(D_/BN, M_/BM, 1),256,GEMM_SMEM>>>(D_, F_, fh, fl,
            w2h+off, w2h+off, w2h+off,
            b2+l*D_, b2+l*D_, b2+l*D_,
            px, px, nullptr, px, nullptr, px, nullptr);
    }
    k_ln<<<M_,256>>>(px, lnfg, lnfb, hh, hl);
    k_gemm<3><<<dim3(V_/BN, M_/BM, 1),256,GEMM_SMEM>>>(V_, D_, hh, hl,
        eth, eth, eth,
        nullptr, nullptr, nullptr,
        nullptr, out, nullptr, out, nullptr, out, nullptr);
}

// round 17
// speedup vs baseline: 9.0057x; 1.4095x over previous
#include <cuda_runtime.h>
#include <cuda_bf16.h>
#include <cuda_fp16.h>
#include <cstdint>
#include <math.h>

typedef unsigned int u32;
typedef __nv_bfloat16 bf16;   // storage for 16-bit words (fp16 bit patterns)

#define B_  2
#define S_  1024
#define D_  1024
#define H_  16
#define F_  4096
#define L_  6
#define V_  32000
#define DK_ 64
#define M_  (B_*S_)

#define BM 128
#define BN 128

__device__ __align__(16) float g_x [M_*D_];
__device__ __align__(16) bf16 g_h_h[M_*D_],  g_h_l[M_*D_];
__device__ __align__(16) bf16 g_q_h[M_*D_],  g_q_l[M_*D_];
__device__ __align__(16) bf16 g_k_h[M_*D_],  g_k_l[M_*D_];
__device__ __align__(16) bf16 g_v_h[M_*D_],  g_v_l[M_*D_];
__device__ __align__(16) bf16 g_a_h[M_*D_],  g_a_l[M_*D_];
__device__ __align__(16) bf16 g_f_h[M_*F_],  g_f_l[M_*F_];
__device__ __align__(16) bf16 g_wq_h[L_*D_*D_];
__device__ __align__(16) bf16 g_wk_h[L_*D_*D_];
__device__ __align__(16) bf16 g_wv_h[L_*D_*D_];
__device__ __align__(16) bf16 g_wo_h[L_*D_*D_];
__device__ __align__(16) bf16 g_w1_h[L_*D_*F_];
__device__ __align__(16) bf16 g_w2_h[L_*F_*D_];
__device__ __align__(16) bf16 g_et_h[(size_t)D_*V_];

__device__ __forceinline__ u32 cvt_smem(const void* p){
    return (u32)__cvta_generic_to_shared(p);
}
__device__ __forceinline__ void cp16(u32 s, const void* g){
    asm volatile("cp.async.cg.shared.global [%0],[%1],16;\n"::"r"(s),"l"(g));
}
__device__ __forceinline__ void cp_commit(){ asm volatile("cp.async.commit_group;\n"::); }
template<int NN> __device__ __forceinline__ void cp_wait(){
    asm volatile("cp.async.wait_group %0;\n"::"n"(NN));
}
__device__ __forceinline__ void ldsm4(u32 &r0,u32 &r1,u32 &r2,u32 &r3, u32 a){
    asm volatile("ldmatrix.sync.aligned.m8n8.x4.shared.b16 {%0,%1,%2,%3},[%4];\n"
        : "=r"(r0),"=r"(r1),"=r"(r2),"=r"(r3) : "r"(a));
}
__device__ __forceinline__ void ldsm4t(u32 &r0,u32 &r1,u32 &r2,u32 &r3, u32 a){
    asm volatile("ldmatrix.sync.aligned.m8n8.x4.trans.shared.b16 {%0,%1,%2,%3},[%4];\n"
        : "=r"(r0),"=r"(r1),"=r"(r2),"=r"(r3) : "r"(a));
}
__device__ __forceinline__ void mma16816h(float* c, const u32* a, const u32* b){
    asm volatile("mma.sync.aligned.m16n8k16.row.col.f32.f16.f16.f32 "
        "{%0,%1,%2,%3},{%4,%5,%6,%7},{%8,%9},{%0,%1,%2,%3};\n"
        : "+f"(c[0]),"+f"(c[1]),"+f"(c[2]),"+f"(c[3])
        : "r"(a[0]),"r"(a[1]),"r"(a[2]),"r"(a[3]),"r"(b[0]),"r"(b[1]));
}
__device__ __forceinline__ u32 pack2h(__half h0, __half h1){
    unsigned short u0 = *reinterpret_cast<unsigned short*>(&h0);
    unsigned short u1 = *reinterpret_cast<unsigned short*>(&h1);
    return (u32)u0 | ((u32)u1 << 16);
}
__device__ __forceinline__ void split2h(float x0, float x1, u32 &hi, u32 &lo){
    __half h0 = __float2half_rn(x0);
    __half h1 = __float2half_rn(x1);
    float f0 = __half2float(h0), f1 = __half2float(h1);
    hi = pack2h(h0, h1);
    lo = pack2h(__float2half_rn(x0 - f0), __float2half_rn(x1 - f1));
}
__device__ __forceinline__ float geluf(float x){
    return 0.5f*x*(1.0f + erff(x*0.7071067811865476f));
}

__global__ void k_cvt_h(const float4* __restrict__ src, uint2* __restrict__ dh, int n4)
{
    int i = blockIdx.x*256 + threadIdx.x;
    if (i >= n4) return;
    float4 v = src[i];
    dh[i] = make_uint2(pack2h(__float2half_rn(v.x), __float2half_rn(v.y)),
                       pack2h(__float2half_rn(v.z), __float2half_rn(v.w)));
}
__global__ void k_cvt_t_h(const float* __restrict__ src, __half* __restrict__ dh)
{
    __shared__ float t[32][33];
    int v0 = blockIdx.x*32, d0 = blockIdx.y*32;
    int tx = threadIdx.x, ty = threadIdx.y;   // 32 x 8
    #pragma unroll
    for (int i=0;i<4;i++)
        t[ty+8*i][tx] = src[(size_t)(v0+ty+8*i)*D_ + d0 + tx];
    __syncthreads();
    #pragma unroll
    for (int i=0;i<4;i++){
        int dy = ty + 8*i;
        dh[(size_t)(d0+dy)*V_ + v0 + tx] = __float2half_rn(t[tx][dy]);
    }
}

__global__ void k_embed(const int* __restrict__ ids, const float* __restrict__ emb,
                        float* __restrict__ x)
{
    int idx = blockIdx.x * 256 + threadIdx.x;
    if (idx >= M_*D_) return;
    int d  = idx & (D_-1);
    int ms = idx >> 10;
    int s  = ms & (S_-1);
    int tok = ids[ms];
    int i2 = d & ~1;
    float freq = expf((float)i2 * (-9.210340371976184f / (float)D_));
    float ang  = (float)s * freq;
    float pe   = (d & 1) ? cosf(ang) : sinf(ang);
    x[idx] = emb[tok*D_ + d] * 32.0f + pe;
}

__global__ void __launch_bounds__(256) k_ln(const float* __restrict__ x,
                                            const float* __restrict__ g,
                                            const float* __restrict__ b,
                                            bf16* __restrict__ oh,
                                            bf16* __restrict__ ol)
{
    int row = blockIdx.x;
    int t = threadIdx.x;
    float4 v = ((const float4*)(x + (size_t)row*D_))[t];
    float s  = v.x+v.y+v.z+v.w;
    float ss = v.x*v.x+v.y*v.y+v.z*v.z+v.w*v.w;
    #pragma unroll
    for (int o=16;o>0;o>>=1){
        s  += __shfl_xor_sync(0xffffffffu, s,  o);
        ss += __shfl_xor_sync(0xffffffffu, ss, o);
    }
    __shared__ float rs[8], rss[8];
    if ((t&31)==0){ rs[t>>5]=s; rss[t>>5]=ss; }
    __syncthreads();
    float tot=0.f, tot2=0.f;
    #pragma unroll
    for (int i=0;i<8;i++){ tot += rs[i]; tot2 += rss[i]; }
    float mean = tot * (1.0f/D_);
    float var  = tot2 * (1.0f/D_) - mean*mean;
    float rstd = rsqrtf(var + 1e-5f);
    float4 gv = ((const float4*)g)[t];
    float4 bv = ((const float4*)b)[t];
    float o0=(v.x-mean)*rstd*gv.x+bv.x, o1=(v.y-mean)*rstd*gv.y+bv.y;
    float o2=(v.z-mean)*rstd*gv.z+bv.z, o3=(v.w-mean)*rstd*gv.w+bv.w;
    u32 h0,l0,h1,l1;
    split2h(o0,o1,h0,l0); split2h(o2,o3,h1,l1);
    ((uint2*)(oh + (size_t)row*D_))[t] = make_uint2(h0,h1);
    ((uint2*)(ol + (size_t)row*D_))[t] = make_uint2(l0,l1);
}

// ---------------- fp16 tensor-core GEMM, 4-stage pipeline ----------------
// NP=2: Ah.Bh + Al.Bh (activation split); NP=1: Ah.Bh only (pure fp16)
// smem: sAh 4st x 128x24; [NP==2: sAl mirror at +24576B]; sBh 4st x 16x136
// EPI: 0 = +bias -> fp16 split, 1 = gelu(+bias) -> fp16 split, 2 = +bias+res -> fp32, 3 = plain fp32
#define GEMM_SMEM2 66560
#define GEMM_SMEM1 41984
template<int EPI, int NP>
__global__ void __launch_bounds__(256) k_gemm(
    int N, int K,
    const bf16* __restrict__ Ah, const bf16* __restrict__ Al,
    const bf16* Bh0, const bf16* Bh1, const bf16* Bh2,
    const float* bias0, const float* bias1, const float* bias2,
    const float* __restrict__ res,
    void* C0a, void* C0b, void* C1a, void* C1b, void* C2a, void* C2b)
{
    extern __shared__ __align__(16) bf16 sm[];
    bf16* sAh = sm;
    bf16* sBh = sm + (NP==2 ? 24576 : 12288);

    const int z = blockIdx.z;
    const bf16* Bh = (z==0)?Bh0:((z==1)?Bh1:Bh2);
    const float* bias = (z==0)?bias0:((z==1)?bias1:bias2);
    void* Ca = (z==0)?C0a:((z==1)?C1a:C2a);
    void* Cb = (z==0)?C0b:((z==1)?C1b:C2b);

    const int tid = threadIdx.x;
    const int lane = tid & 31, wid = tid>>5;
    const int m_base = (wid&1)*64, n_base = (wid>>1)*32;
    const int bm = blockIdx.y*BM, bn = blockIdx.x*BN;

    const int ar = tid>>1, ac = (tid&1)*8;
    const int br = tid>>4, bc = (tid&15)*8;
    const bf16* Agh = Ah + (size_t)(bm+ar)*K + ac;
    const bf16* Agl = (NP==2) ? (Al + (size_t)(bm+ar)*K + ac) : nullptr;
    const bf16* Bgh = Bh + (size_t)br*N + bn + bc;

    const u32 aWr = cvt_smem(sAh + ar*24 + ac);
    const u32 bWr = cvt_smem(sBh + br*136 + bc);

    const int q2 = lane>>3;
    const u32 aRd = cvt_smem(sAh + (m_base + (lane&15))*24 + (lane>>4)*8);
    const u32 bRd = cvt_smem(sBh + ((q2&1)*8 + (lane&7))*136 + n_base + (q2>>1)*8);

    float acc[4][4][4];
    #pragma unroll
    for (int i=0;i<4;i++)
        #pragma unroll
        for (int j=0;j<4;j++)
            #pragma unroll
            for (int r=0;r<4;r++) acc[i][j][r]=0.f;

    auto issue = [&](int kt, int st){
        u32 a = aWr + st*6144;
        cp16(a, Agh + kt*16);
        if (NP==2) cp16(a + 24576, Agl + kt*16);
        cp16(bWr + st*4352, Bgh + (size_t)kt*16*N);
        cp_commit();
    };

    const int nk = K/16;
    issue(0,0); issue(1,1); issue(2,2);

    for (int kt=0; kt<nk; kt++){
        if (kt+2 < nk)      cp_wait<2>();
        else if (kt+1 < nk) cp_wait<1>();
        else                cp_wait<0>();
        __syncthreads();
        const int st = kt & 3;

        u32 fah[4][4], fal[4][4];
        const u32 ab = aRd + st*6144;
        #pragma unroll
        for (int mi=0;mi<4;mi++){
            ldsm4(fah[mi][0],fah[mi][1],fah[mi][2],fah[mi][3], ab + mi*768);
            if (NP==2)
                ldsm4(fal[mi][0],fal[mi][1],fal[mi][2],fal[mi][3], ab + mi*768 + 24576);
        }
        u32 fbh[4][2];
        const u32 bb2 = bRd + st*4352;
        #pragma unroll
        for (int p=0;p<2;p++){
            u32 r0,r1,r2,r3;
            ldsm4t(r0,r1,r2,r3, bb2 + p*32);
            fbh[2*p][0]=r0; fbh[2*p][1]=r1; fbh[2*p+1][0]=r2; fbh[2*p+1][1]=r3;
        }
        if (kt+3 < nk) issue(kt+3, (kt+3)&3);

        #pragma unroll
        for (int mi=0;mi<4;mi++)
            #pragma unroll
            for (int nj=0;nj<4;nj++)
                mma16816h(acc[mi][nj], fah[mi], fbh[nj]);
        if (NP==2){
            #pragma unroll
            for (int mi=0;mi<4;mi++)
                #pragma unroll
                for (int nj=0;nj<4;nj++)
                    mma16816h(acc[mi][nj], fal[mi], fbh[nj]);
        }
    }

    #pragma unroll
    for (int mi=0; mi<4; mi++){
        #pragma unroll
        for (int r=0; r<2; r++){
            int gm = bm + m_base + mi*16 + (lane>>2) + r*8;
            #pragma unroll
            for (int nj=0; nj<4; nj++){
                int gn = bn + n_base + nj*8 + (lane&3)*2;
                float v0 = acc[mi][nj][r*2+0];
                float v1 = acc[mi][nj][r*2+1];
                if (EPI != 3){ v0 += bias[gn]; v1 += bias[gn+1]; }
                if (EPI == 1){ v0 = geluf(v0); v1 = geluf(v1); }
                size_t base = (size_t)gm*N + gn;
                if (EPI == 2){
                    float2 rr = *(const float2*)(res + base);
                    *(float2*)((float*)Ca + base) = make_float2(v0+rr.x, v1+rr.y);
                } else if (EPI == 3){
                    *(float2*)((float*)Ca + base) = make_float2(v0, v1);
                } else {
                    u32 h_,l_;
                    split2h(v0, v1, h_, l_);
                    *(u32*)((bf16*)Ca + base) = h_;
                    *(u32*)((bf16*)Cb + base) = l_;
                }
            }
        }
    }
}

// ---------------- fp16 2-pass flash attention, K/V hi-only, 2-stage pipeline ----------------
#define ATTN_SMEM 55296
__global__ void __launch_bounds__(128) k_attn(
    const bf16* __restrict__ Qh, const bf16* __restrict__ Ql,
    const bf16* __restrict__ Kh, const bf16* __restrict__ Vh,
    bf16* __restrict__ Oh, bf16* __restrict__ Ol)
{
    extern __shared__ __align__(16) bf16 sm[];
    bf16* sQh = sm;
    bf16* sKh = sm + 9216;
    bf16* sVh = sm + 18432;

    const int tid = threadIdx.x;
    const int lane = tid & 31;
    const int w = tid >> 5;
    const int qt = blockIdx.x;
    const int bh = blockIdx.y;
    const int bb = bh >> 4;
    const int hh = bh & 15;
    const int g  = lane >> 2;
    const int n2 = (lane & 3) * 2;
    const int q2 = lane >> 3;

    const size_t qrow0 = (size_t)bb*S_ + qt*64;
    const int col0 = hh*DK_;

    #pragma unroll
    for (int i=0;i<4;i++){
        int cid = tid + i*128;
        int r = cid >> 3, ch = (cid & 7)*8;
        size_t go = (qrow0 + r)*D_ + col0 + ch;
        u32 s = cvt_smem(sQh + r*72 + ch);
        cp16(s, Qh + go);
        cp16(s + 9216, Ql + go);
    }
    cp_commit();

    auto issueKV = [&](int kt, int st){
        #pragma unroll
        for (int i=0;i<4;i++){
            int cid = tid + i*128;
            int r = cid >> 3, ch = (cid & 7)*8;
            size_t go = ((size_t)bb*S_ + kt*64 + r)*D_ + col0 + ch;
            u32 s = cvt_smem(sKh + st*4608 + r*72 + ch);
            cp16(s,         Kh + go);
            cp16(s + 18432, Vh + go);
        }
        cp_commit();
    };

    issueKV(0, 0);
    cp_wait<1>();
    __syncthreads();
    u32 qfh[4][4], qfl[4][4];
    {
        u32 a = cvt_smem(sQh + (w*16 + (lane&15))*72 + (lane>>4)*8);
        #pragma unroll
        for (int ks=0; ks<4; ks++){
            ldsm4(qfh[ks][0],qfh[ks][1],qfh[ks][2],qfh[ks][3], a + ks*32);
            ldsm4(qfl[ks][0],qfl[ks][1],qfl[ks][2],qfl[ks][3], a + ks*32 + 9216);
        }
    }

    float m[2]    = {-1e30f, -1e30f};
    float lsum[2] = {0.f, 0.f};
    float oa[8][4];
    #pragma unroll
    for (int i=0;i<8;i++)
        #pragma unroll
        for (int j=0;j<4;j++) oa[i][j]=0.f;

    for (int kt=0; kt<=qt; kt++){
        const int st = kt & 1;
        if (kt+1 <= qt){ issueKV(kt+1, st^1); cp_wait<1>(); }
        else           { cp_wait<0>(); }
        __syncthreads();

        float s[8][4];
        #pragma unroll
        for (int nt=0;nt<8;nt++)
            #pragma unroll
            for (int j=0;j<4;j++) s[nt][j]=0.f;

        #pragma unroll
        for (int ks=0; ks<4; ks++){
            u32 kbh[8][2];
            #pragma unroll
            for (int pr=0; pr<4; pr++){
                u32 r0,r1,r2,r3;
                u32 a = cvt_smem(sKh + st*4608 + (pr*16 + (q2&1)*8 + (lane&7))*72 + (q2>>1)*8) + ks*32;
                ldsm4(r0,r1,r2,r3, a);
                kbh[2*pr][0]=r0; kbh[2*pr][1]=r2; kbh[2*pr+1][0]=r1; kbh[2*pr+1][1]=r3;
            }
            #pragma unroll
            for (int nt=0; nt<8; nt++) mma16816h(s[nt], qfh[ks], kbh[nt]);
            #pragma unroll
            for (int nt=0; nt<8; nt++) mma16816h(s[nt], qfl[ks], kbh[nt]);
        }

        const bool diag = (kt == qt);
        #pragma unroll
        for (int nt=0;nt<8;nt++)
            #pragma unroll
            for (int j=0;j<4;j++){
                float v = s[nt][j]*0.125f;
                if (diag){
                    int col  = nt*8 + n2 + (j&1);
                    int rowl = w*16 + g + (j>>1)*8;
                    if (col > rowl) v = -1e30f;
                }
                s[nt][j] = v;
            }

        float mx0=-1e30f, mx1=-1e30f;
        #pragma unroll
        for (int nt=0;nt<8;nt++){
            mx0 = fmaxf(mx0, fmaxf(s[nt][0], s[nt][1]));
            mx1 = fmaxf(mx1, fmaxf(s[nt][2], s[nt][3]));
        }
        mx0 = fmaxf(mx0, __shfl_xor_sync(0xffffffffu, mx0, 1));
        mx0 = fmaxf(mx0, __shfl_xor_sync(0xffffffffu, mx0, 2));
        mx1 = fmaxf(mx1, __shfl_xor_sync(0xffffffffu, mx1, 1));
        mx1 = fmaxf(mx1, __shfl_xor_sync(0xffffffffu, mx1, 2));
        float mn0 = fmaxf(m[0], mx0), mn1 = fmaxf(m[1], mx1);
        float c0 = __expf(m[0]-mn0), c1 = __expf(m[1]-mn1);
        float ps0=0.f, ps1=0.f;
        #pragma unroll
        for (int nt=0;nt<8;nt++){
            s[nt][0] = __expf(s[nt][0]-mn0); ps0 += s[nt][0];
            s[nt][1] = __expf(s[nt][1]-mn0); ps0 += s[nt][1];
            s[nt][2] = __expf(s[nt][2]-mn1); ps1 += s[nt][2];
            s[nt][3] = __expf(s[nt][3]-mn1); ps1 += s[nt][3];
        }
        ps0 += __shfl_xor_sync(0xffffffffu, ps0, 1);
        ps0 += __shfl_xor_sync(0xffffffffu, ps0, 2);
        ps1 += __shfl_xor_sync(0xffffffffu, ps1, 1);
        ps1 += __shfl_xor_sync(0xffffffffu, ps1, 2);
        lsum[0] = lsum[0]*c0 + ps0;
        lsum[1] = lsum[1]*c1 + ps1;
        m[0] = mn0; m[1] = mn1;
        #pragma unroll
        for (int dt=0;dt<8;dt++){
            oa[dt][0]*=c0; oa[dt][1]*=c0; oa[dt][2]*=c1; oa[dt][3]*=c1;
        }

        #pragma unroll
        for (int ks=0; ks<4; ks++){
            u32 pfh[4], pfl[4];
            split2h(s[2*ks  ][0], s[2*ks  ][1], pfh[0], pfl[0]);
            split2h(s[2*ks  ][2], s[2*ks  ][3], pfh[1], pfl[1]);
            split2h(s[2*ks+1][0], s[2*ks+1][1], pfh[2], pfl[2]);
            split2h(s[2*ks+1][2], s[2*ks+1][3], pfh[3], pfl[3]);

            u32 vbh[8][2];
            #pragma unroll
            for (int dp=0; dp<4; dp++){
                u32 r0,r1,r2,r3;
                u32 a = cvt_smem(sVh + st*4608 + (ks*16 + (q2&1)*8 + (lane&7))*72 + dp*16 + (q2>>1)*8);
                ldsm4t(r0,r1,r2,r3, a);
                vbh[2*dp][0]=r0; vbh[2*dp][1]=r1; vbh[2*dp+1][0]=r2; vbh[2*dp+1][1]=r3;
            }
            #pragma unroll
            for (int dt=0; dt<8; dt++) mma16816h(oa[dt], pfh, vbh[dt]);
            #pragma unroll
            for (int dt=0; dt<8; dt++) mma16816h(oa[dt], pfl, vbh[dt]);
        }
        __syncthreads();
    }

    float inv0 = 1.0f/lsum[0], inv1 = 1.0f/lsum[1];
    size_t r0 = qrow0 + w*16 + g;
    size_t r1 = r0 + 8;
    #pragma unroll
    for (int dt=0; dt<8; dt++){
        int col = col0 + dt*8 + n2;
        u32 h_,l_;
        split2h(oa[dt][0]*inv0, oa[dt][1]*inv0, h_, l_);
        *(u32*)(Oh + r0*D_ + col) = h_;
        *(u32*)(Ol + r0*D_ + col) = l_;
        split2h(oa[dt][2]*inv1, oa[dt][3]*inv1, h_, l_);
        *(u32*)(Oh + r1*D_ + col) = h_;
        *(u32*)(Ol + r1*D_ + col) = l_;
    }
}

extern "C" void kernel_launch(void* const* d_in, const int* in_sizes, int n_in,
                              void* d_out, int out_size)
{
    (void)in_sizes; (void)n_in; (void)out_size;
    const int*   ids  = (const int*)  d_in[0];
    const float* emb  = (const float*)d_in[1];
    const float* wq   = (const float*)d_in[2];
    const float* bq   = (const float*)d_in[3];
    const float* wk   = (const float*)d_in[4];
    const float* bk   = (const float*)d_in[5];
    const float* wv   = (const float*)d_in[6];
    const float* bv   = (const float*)d_in[7];
    const float* wo   = (const float*)d_in[8];
    const float* bo   = (const float*)d_in[9];
    const float* ln1g = (const float*)d_in[10];
    const float* ln1b = (const float*)d_in[11];
    const float* ln2g = (const float*)d_in[12];
    const float* ln2b = (const float*)d_in[13];
    const float* w1   = (const float*)d_in[14];
    const float* b1   = (const float*)d_in[15];
    const float* w2   = (const float*)d_in[16];
    const float* b2   = (const float*)d_in[17];
    const float* lnfg = (const float*)d_in[18];
    const float* lnfb = (const float*)d_in[19];
    float* out = (float*)d_out;

    cudaFuncSetAttribute((const void*)k_gemm<0,2>, cudaFuncAttributeMaxDynamicSharedMemorySize, GEMM_SMEM2);
    cudaFuncSetAttribute((const void*)k_gemm<2,2>, cudaFuncAttributeMaxDynamicSharedMemorySize, GEMM_SMEM2);
    cudaFuncSetAttribute((const void*)k_gemm<1,1>, cudaFuncAttributeMaxDynamicSharedMemorySize, GEMM_SMEM1);
    cudaFuncSetAttribute((const void*)k_gemm<2,1>, cudaFuncAttributeMaxDynamicSharedMemorySize, GEMM_SMEM1);
    cudaFuncSetAttribute((const void*)k_gemm<3,1>, cudaFuncAttributeMaxDynamicSharedMemorySize, GEMM_SMEM1);
    cudaFuncSetAttribute((const void*)k_attn,      cudaFuncAttributeMaxDynamicSharedMemorySize, ATTN_SMEM);

    float* px;  cudaGetSymbolAddress((void**)&px,  g_x);
    bf16 *hh,*hl,*qh,*ql,*kh,*kl,*vh,*vl,*ah,*al,*fh,*fl;
    cudaGetSymbolAddress((void**)&hh, g_h_h); cudaGetSymbolAddress((void**)&hl, g_h_l);
    cudaGetSymbolAddress((void**)&qh, g_q_h); cudaGetSymbolAddress((void**)&ql, g_q_l);
    cudaGetSymbolAddress((void**)&kh, g_k_h); cudaGetSymbolAddress((void**)&kl, g_k_l);
    cudaGetSymbolAddress((void**)&vh, g_v_h); cudaGetSymbolAddress((void**)&vl, g_v_l);
    cudaGetSymbolAddress((void**)&ah, g_a_h); cudaGetSymbolAddress((void**)&al, g_a_l);
    cudaGetSymbolAddress((void**)&fh, g_f_h); cudaGetSymbolAddress((void**)&fl, g_f_l);
    bf16 *wqh,*wkh,*wvh,*woh,*w1h,*w2h,*eth;
    cudaGetSymbolAddress((void**)&wqh, g_wq_h);
    cudaGetSymbolAddress((void**)&wkh, g_wk_h);
    cudaGetSymbolAddress((void**)&wvh, g_wv_h);
    cudaGetSymbolAddress((void**)&woh, g_wo_h);
    cudaGetSymbolAddress((void**)&w1h, g_w1_h);
    cudaGetSymbolAddress((void**)&w2h, g_w2_h);
    cudaGetSymbolAddress((void**)&eth, g_et_h);

    {
        int nA = L_*D_*D_/4;
        k_cvt_h<<<(nA+255)/256,256>>>((const float4*)wq, (uint2*)wqh, nA);
        k_cvt_h<<<(nA+255)/256,256>>>((const float4*)wk, (uint2*)wkh, nA);
        k_cvt_h<<<(nA+255)/256,256>>>((const float4*)wv, (uint2*)wvh, nA);
        k_cvt_h<<<(nA+255)/256,256>>>((const float4*)wo, (uint2*)woh, nA);
        int nF = L_*D_*F_/4;
        k_cvt_h<<<(nF+255)/256,256>>>((const float4*)w1, (uint2*)w1h, nF);
        k_cvt_h<<<(nF+255)/256,256>>>((const float4*)w2, (uint2*)w2h, nF);
        k_cvt_t_h<<<dim3(V_/32, D_/32), dim3(32,8)>>>(emb, (__half*)eth);
    }

    k_embed<<<(M_*D_+255)/256, 256>>>(ids, emb, px);

    for (int l=0; l<L_; l++){
        size_t odd = (size_t)l*D_*D_;
        size_t off = (size_t)l*D_*F_;
        k_ln<<<M_,256>>>(px, ln1g+l*D_, ln1b+l*D_, hh, hl);
        k_gemm<0,2><<<dim3(D_/BN, M_/BM, 3),256,GEMM_SMEM2>>>(D_, D_, hh, hl,
            wqh+odd, wkh+odd, wvh+odd,
            bq+l*D_, bk+l*D_, bv+l*D_,
            nullptr, qh, ql, kh, kl, vh, vl);
        k_attn<<<dim3(S_/64, B_*H_),128,ATTN_SMEM>>>(qh, ql, kh, vh, ah, al);
        k_gemm<2,2><<<dim3(D_/BN, M_/BM, 1),256,GEMM_SMEM2>>>(D_, D_, ah, al,
            woh+odd, woh+odd, woh+odd,
            bo+l*D_, bo+l*D_, bo+l*D_,
            px, px, nullptr, px, nullptr, px, nullptr);
        k_ln<<<M_,256>>>(px, ln2g+l*D_, ln2b+l*D_, hh, hl);
        // FFN1: 1-pass fp16 (hi activation only)
        k_gemm<1,1><<<dim3(F_/BN, M_/BM, 1),256,GEMM_SMEM1>>>(F_, D_, hh, nullptr,
            w1h+off, w1h+off, w1h+off,
            b1+l*F_, b1+l*F_, b1+l*F_,
            nullptr, fh, fl, fh, fl, fh, fl);
        // FFN2: 1-pass fp16
        k_gemm<2,1><<<dim3(D_/BN, M_/BM, 1),256,GEMM_SMEM1>>>(D_, F_, fh, nullptr,
            w2h+off, w2h+off, w2h+off,
            b2+l*D_, b2+l*D_, b2+l*D_,
            px, px, nullptr, px, nullptr, px, nullptr);
    }
    k_ln<<<M_,256>>>(px, lnfg, lnfb, hh, hl);
    // lm_head: 1-pass fp16
    k_gemm<3,1><<<dim3(V_/BN, M_/BM, 1),256,GEMM_SMEM1>>>(V_, D_, hh, nullptr,
        eth, eth, eth,
        nullptr, nullptr, nullptr,
        nullptr, out, nullptr, out, nullptr, out, nullptr);
}